// round 2
// baseline (speedup 1.0000x reference)
#include <cuda_runtime.h>
#include <math.h>
#include <stdint.h>

// Problem constants: b=2, s=2048, d=2048, H=16, Dh=128, window=2048 (never binds -> causal)
#define GM 4096   // b*s
#define GD 2048   // model dim
#define SEQ 2048
#define NH 16
#define DH 128

// Scratch (device globals: allocation is forbidden, statics are allowed)
__device__ float g_Q[GM * GD];
__device__ float g_K[GM * GD];
__device__ float g_V[GM * GD];
__device__ float g_C[GM * GD];

// ---------------------------------------------------------------------------
// 3xTF32 tensor-core GEMM: C[M,N] = A[M,K] @ B[K,N], row-major fp32 in/out.
// Each fp32 x is split once (at smem fill) into hi = tf32(x), lo = tf32(x-hi).
// D += Ahi*Bhi + Ahi*Blo + Alo*Bhi   (missing Alo*Blo term ~2^-22 relative).
// Block tile 128x128x32, 256 threads (8 warps, 4x2), warp tile 32x64,
// mma.sync.m16n8k8.row.col.f32.tf32.tf32.f32.
// ---------------------------------------------------------------------------
#define BM 128
#define BN 128
#define BK 32
#define SA_STRIDE 36              // BK + 4 pad: frag LDS conflict-free
#define TILE_FLOATS (128 * SA_STRIDE)
#define GEMM_SMEM_BYTES (4 * TILE_FLOATS * 4)   // As_hi, As_lo, Bs_hi, Bs_lo = 72 KB

__device__ __forceinline__ float tf32_rnd(float x) {
    float r;
    asm("cvt.rna.tf32.f32 %0, %1;" : "=f"(r) : "f"(x));
    return r;
}

#define MMA_TF32(d, a, b0, b1)                                              \
    asm volatile(                                                           \
        "mma.sync.aligned.m16n8k8.row.col.f32.tf32.tf32.f32 "               \
        "{%0,%1,%2,%3}, {%4,%5,%6,%7}, {%8,%9}, {%0,%1,%2,%3};"             \
        : "+f"(d[0]), "+f"(d[1]), "+f"(d[2]), "+f"(d[3])                    \
        : "r"(a[0]), "r"(a[1]), "r"(a[2]), "r"(a[3]), "r"(b0), "r"(b1))

__global__ __launch_bounds__(256, 1) void tf32_gemm(
    const float* __restrict__ A, const float* __restrict__ B,
    float* __restrict__ C, int M, int N, int K)
{
    extern __shared__ float sm[];
    float* As_hi = sm;
    float* As_lo = sm + TILE_FLOATS;
    float* Bs_hi = sm + 2 * TILE_FLOATS;   // n-major: Bs[n][k]
    float* Bs_lo = sm + 3 * TILE_FLOATS;

    const int tid  = threadIdx.x;
    const int lane = tid & 31;
    const int warp = tid >> 5;
    const int wm = (warp & 3) * 32;   // warp m offset within block tile
    const int wn = (warp >> 2) * 64;  // warp n offset
    const int m0 = blockIdx.y * BM;
    const int n0 = blockIdx.x * BN;
    const int gid = lane >> 2;        // groupID
    const int tig = lane & 3;         // threadID_in_group

    // ---- prefetch first k-tile into registers ----
    float4 pa[4], pb[4];
    {
        const float* Ag = A + (size_t)m0 * K;
#pragma unroll
        for (int i = 0; i < 4; i++) {
            int idx = tid + i * 256;              // 0..1023 float4 units (128x32)
            int m = idx >> 3, k4 = (idx & 7) << 2;
            pa[i] = *reinterpret_cast<const float4*>(&Ag[(size_t)m * K + k4]);
        }
        const float* Bg = B + n0;
#pragma unroll
        for (int i = 0; i < 4; i++) {
            int idx = tid + i * 256;              // (32x128)
            int kk = idx >> 5, n4 = (idx & 31) << 2;
            pb[i] = *reinterpret_cast<const float4*>(&Bg[(size_t)kk * N + n4]);
        }
    }

    float acc[2][8][4];
#pragma unroll
    for (int mt = 0; mt < 2; mt++)
#pragma unroll
        for (int nt = 0; nt < 8; nt++)
#pragma unroll
            for (int r = 0; r < 4; r++) acc[mt][nt][r] = 0.0f;

    for (int k0 = 0; k0 < K; k0 += BK) {
        // ---- split + store prefetched tile to smem ----
#pragma unroll
        for (int i = 0; i < 4; i++) {
            int idx = tid + i * 256;
            int m = idx >> 3, k4 = (idx & 7) << 2;
            float v[4] = {pa[i].x, pa[i].y, pa[i].z, pa[i].w};
#pragma unroll
            for (int j = 0; j < 4; j++) {
                float hi = tf32_rnd(v[j]);
                As_hi[m * SA_STRIDE + k4 + j] = hi;
                As_lo[m * SA_STRIDE + k4 + j] = tf32_rnd(v[j] - hi);
            }
        }
#pragma unroll
        for (int i = 0; i < 4; i++) {
            int idx = tid + i * 256;
            int kk = idx >> 5, n4 = (idx & 31) << 2;
            float v[4] = {pb[i].x, pb[i].y, pb[i].z, pb[i].w};
#pragma unroll
            for (int j = 0; j < 4; j++) {
                float hi = tf32_rnd(v[j]);
                Bs_hi[(n4 + j) * SA_STRIDE + kk] = hi;      // transposed: [n][k]
                Bs_lo[(n4 + j) * SA_STRIDE + kk] = tf32_rnd(v[j] - hi);
            }
        }
        __syncthreads();

        // ---- prefetch next k-tile ----
        if (k0 + BK < K) {
            const float* Ag = A + (size_t)m0 * K + (k0 + BK);
#pragma unroll
            for (int i = 0; i < 4; i++) {
                int idx = tid + i * 256;
                int m = idx >> 3, k4 = (idx & 7) << 2;
                pa[i] = *reinterpret_cast<const float4*>(&Ag[(size_t)m * K + k4]);
            }
            const float* Bg = B + (size_t)(k0 + BK) * N + n0;
#pragma unroll
            for (int i = 0; i < 4; i++) {
                int idx = tid + i * 256;
                int kk = idx >> 5, n4 = (idx & 31) << 2;
                pb[i] = *reinterpret_cast<const float4*>(&Bg[(size_t)kk * N + n4]);
            }
        }

        // ---- compute: 4 k-steps of 8 ----
#pragma unroll
        for (int ks = 0; ks < BK; ks += 8) {
            uint32_t ah[2][4], al[2][4];
#pragma unroll
            for (int mt = 0; mt < 2; mt++) {
                int mb = wm + mt * 16;
                int r0 = (mb + gid) * SA_STRIDE + ks + tig;
                int r1 = (mb + gid + 8) * SA_STRIDE + ks + tig;
                ah[mt][0] = __float_as_uint(As_hi[r0]);
                ah[mt][1] = __float_as_uint(As_hi[r1]);
                ah[mt][2] = __float_as_uint(As_hi[r0 + 4]);
                ah[mt][3] = __float_as_uint(As_hi[r1 + 4]);
                al[mt][0] = __float_as_uint(As_lo[r0]);
                al[mt][1] = __float_as_uint(As_lo[r1]);
                al[mt][2] = __float_as_uint(As_lo[r0 + 4]);
                al[mt][3] = __float_as_uint(As_lo[r1 + 4]);
            }
#pragma unroll
            for (int nt = 0; nt < 8; nt++) {
                int nb = (wn + nt * 8 + gid) * SA_STRIDE + ks + tig;
                uint32_t bh0 = __float_as_uint(Bs_hi[nb]);
                uint32_t bh1 = __float_as_uint(Bs_hi[nb + 4]);
                uint32_t bl0 = __float_as_uint(Bs_lo[nb]);
                uint32_t bl1 = __float_as_uint(Bs_lo[nb + 4]);
#pragma unroll
                for (int mt = 0; mt < 2; mt++) {
                    MMA_TF32(acc[mt][nt], ah[mt], bh0, bh1);
                    MMA_TF32(acc[mt][nt], ah[mt], bl0, bl1);
                    MMA_TF32(acc[mt][nt], al[mt], bh0, bh1);
                }
            }
        }
        __syncthreads();
    }

    // ---- epilogue ----
#pragma unroll
    for (int mt = 0; mt < 2; mt++) {
#pragma unroll
        for (int nt = 0; nt < 8; nt++) {
            int row = m0 + wm + mt * 16 + gid;
            int col = n0 + wn + nt * 8 + tig * 2;
            float2 v0 = make_float2(acc[mt][nt][0], acc[mt][nt][1]);
            float2 v1 = make_float2(acc[mt][nt][2], acc[mt][nt][3]);
            *reinterpret_cast<float2*>(&C[(size_t)row * N + col]) = v0;
            *reinterpret_cast<float2*>(&C[(size_t)(row + 8) * N + col]) = v1;
        }
    }
}

// ---------------------------------------------------------------------------
// Causal flash attention (window never binds): unchanged from round 1 (fp32).
// ---------------------------------------------------------------------------
#define FA_STRIDE 132
#define FA_SMEM_BYTES (3 * 128 * FA_STRIDE * 4)
#define SM_SCALE 0.08838834764831845f  // 1/sqrt(128)

__global__ __launch_bounds__(256, 1) void flash_kernel(
    const float* __restrict__ Qg, const float* __restrict__ Kg,
    const float* __restrict__ Vg, float* __restrict__ Og)
{
    extern __shared__ float sm[];
    float* Qs = sm;                        // [128][132], Qs[d*132+q]
    float* Ks = sm + 128 * FA_STRIDE;      // [128][132], Ks[d*132+k]; later Ps[k*132+q]
    float* Vs = sm + 2 * 128 * FA_STRIDE;  // [128][132], Vs[k*132+d]

    const int tid = threadIdx.x;
    const int tx = tid & 15;   // k-cols / d-cols
    const int ty = tid >> 4;   // q-rows
    const int qt = blockIdx.x;
    const int h  = blockIdx.y;
    const int b  = blockIdx.z;
    const int q0 = qt * 128;
    const size_t base = ((size_t)b * SEQ) * GD + (size_t)h * DH;

#pragma unroll
    for (int i = 0; i < 16; i++) {
        int idx = tid + i * 256;
        int r  = idx >> 5;
        int d4 = (idx & 31) << 2;
        float4 v = *reinterpret_cast<const float4*>(&Qg[base + (size_t)(q0 + r) * GD + d4]);
        Qs[(d4 + 0) * FA_STRIDE + r] = v.x;
        Qs[(d4 + 1) * FA_STRIDE + r] = v.y;
        Qs[(d4 + 2) * FA_STRIDE + r] = v.z;
        Qs[(d4 + 3) * FA_STRIDE + r] = v.w;
    }

    float m_i[8], l_i[8], o[8][8];
#pragma unroll
    for (int i = 0; i < 8; i++) {
        m_i[i] = -1e30f; l_i[i] = 0.0f;
#pragma unroll
        for (int j = 0; j < 8; j++) o[i][j] = 0.0f;
    }

    for (int jt = 0; jt <= qt; jt++) {
        const int k0 = jt * 128;
        __syncthreads();
#pragma unroll
        for (int i = 0; i < 16; i++) {
            int idx = tid + i * 256;
            int r  = idx >> 5;
            int d4 = (idx & 31) << 2;
            float4 kv = *reinterpret_cast<const float4*>(&Kg[base + (size_t)(k0 + r) * GD + d4]);
            Ks[(d4 + 0) * FA_STRIDE + r] = kv.x;
            Ks[(d4 + 1) * FA_STRIDE + r] = kv.y;
            Ks[(d4 + 2) * FA_STRIDE + r] = kv.z;
            Ks[(d4 + 3) * FA_STRIDE + r] = kv.w;
            float4 vv = *reinterpret_cast<const float4*>(&Vg[base + (size_t)(k0 + r) * GD + d4]);
            *reinterpret_cast<float4*>(&Vs[r * FA_STRIDE + d4]) = vv;
        }
        __syncthreads();

        float s[8][8];
#pragma unroll
        for (int i = 0; i < 8; i++)
#pragma unroll
            for (int j = 0; j < 8; j++) s[i][j] = 0.0f;

        for (int d = 0; d < 128; d++) {
            float4 a0 = *reinterpret_cast<const float4*>(&Qs[d * FA_STRIDE + ty * 8]);
            float4 a1 = *reinterpret_cast<const float4*>(&Qs[d * FA_STRIDE + ty * 8 + 4]);
            float4 b0 = *reinterpret_cast<const float4*>(&Ks[d * FA_STRIDE + tx * 8]);
            float4 b1 = *reinterpret_cast<const float4*>(&Ks[d * FA_STRIDE + tx * 8 + 4]);
            float a[8] = {a0.x, a0.y, a0.z, a0.w, a1.x, a1.y, a1.z, a1.w};
            float bb[8] = {b0.x, b0.y, b0.z, b0.w, b1.x, b1.y, b1.z, b1.w};
#pragma unroll
            for (int i = 0; i < 8; i++)
#pragma unroll
                for (int j = 0; j < 8; j++)
                    s[i][j] = fmaf(a[i], bb[j], s[i][j]);
        }

        if (jt == qt) {
#pragma unroll
            for (int i = 0; i < 8; i++) {
                int qq = q0 + ty * 8 + i;
#pragma unroll
                for (int j = 0; j < 8; j++) {
                    int kk = k0 + tx * 8 + j;
                    s[i][j] = (kk > qq) ? -1e30f : s[i][j] * SM_SCALE;
                }
            }
        } else {
#pragma unroll
            for (int i = 0; i < 8; i++)
#pragma unroll
                for (int j = 0; j < 8; j++) s[i][j] *= SM_SCALE;
        }

#pragma unroll
        for (int i = 0; i < 8; i++) {
            float mloc = s[i][0];
#pragma unroll
            for (int j = 1; j < 8; j++) mloc = fmaxf(mloc, s[i][j]);
#pragma unroll
            for (int off = 8; off >= 1; off >>= 1)
                mloc = fmaxf(mloc, __shfl_xor_sync(0xffffffffu, mloc, off, 16));
            float mnew = fmaxf(m_i[i], mloc);
            float corr = __expf(m_i[i] - mnew);
            m_i[i] = mnew;
            float rs = 0.0f;
#pragma unroll
            for (int j = 0; j < 8; j++) {
                float p = __expf(s[i][j] - mnew);
                s[i][j] = p;
                rs += p;
            }
#pragma unroll
            for (int off = 8; off >= 1; off >>= 1)
                rs += __shfl_xor_sync(0xffffffffu, rs, off, 16);
            l_i[i] = l_i[i] * corr + rs;
#pragma unroll
            for (int j = 0; j < 8; j++) o[i][j] *= corr;
        }

        __syncthreads();
#pragma unroll
        for (int j = 0; j < 8; j++)
#pragma unroll
            for (int i = 0; i < 8; i++)
                Ks[(tx * 8 + j) * FA_STRIDE + ty * 8 + i] = s[i][j];
        __syncthreads();

        for (int k = 0; k < 128; k++) {
            float4 a0 = *reinterpret_cast<const float4*>(&Ks[k * FA_STRIDE + ty * 8]);
            float4 a1 = *reinterpret_cast<const float4*>(&Ks[k * FA_STRIDE + ty * 8 + 4]);
            float4 b0 = *reinterpret_cast<const float4*>(&Vs[k * FA_STRIDE + tx * 8]);
            float4 b1 = *reinterpret_cast<const float4*>(&Vs[k * FA_STRIDE + tx * 8 + 4]);
            float a[8] = {a0.x, a0.y, a0.z, a0.w, a1.x, a1.y, a1.z, a1.w};
            float bb[8] = {b0.x, b0.y, b0.z, b0.w, b1.x, b1.y, b1.z, b1.w};
#pragma unroll
            for (int i = 0; i < 8; i++)
#pragma unroll
                for (int j = 0; j < 8; j++)
                    o[i][j] = fmaf(a[i], bb[j], o[i][j]);
        }
    }

#pragma unroll
    for (int i = 0; i < 8; i++) {
        float inv = 1.0f / l_i[i];
        float* orow = &Og[base + (size_t)(q0 + ty * 8 + i) * GD + tx * 8];
        float4 c0 = make_float4(o[i][0] * inv, o[i][1] * inv, o[i][2] * inv, o[i][3] * inv);
        float4 c1 = make_float4(o[i][4] * inv, o[i][5] * inv, o[i][6] * inv, o[i][7] * inv);
        *reinterpret_cast<float4*>(orow) = c0;
        *reinterpret_cast<float4*>(orow + 4) = c1;
    }
}

// ---------------------------------------------------------------------------
extern "C" void kernel_launch(void* const* d_in, const int* in_sizes, int n_in,
                              void* d_out, int out_size)
{
    const float* x  = (const float*)d_in[0];
    const float* Wq = (const float*)d_in[1];
    const float* Wk = (const float*)d_in[2];
    const float* Wv = (const float*)d_in[3];
    const float* Wo = (const float*)d_in[4];

    float *Q, *K, *V, *C;
    cudaGetSymbolAddress((void**)&Q, g_Q);
    cudaGetSymbolAddress((void**)&K, g_K);
    cudaGetSymbolAddress((void**)&V, g_V);
    cudaGetSymbolAddress((void**)&C, g_C);

    cudaFuncSetAttribute(tf32_gemm,
                         cudaFuncAttributeMaxDynamicSharedMemorySize, GEMM_SMEM_BYTES);
    cudaFuncSetAttribute(flash_kernel,
                         cudaFuncAttributeMaxDynamicSharedMemorySize, FA_SMEM_BYTES);

    dim3 gemm_grid(GD / 128, GM / 128);  // (16, 32)

    tf32_gemm<<<gemm_grid, 256, GEMM_SMEM_BYTES>>>(x, Wq, Q, GM, GD, GD);
    tf32_gemm<<<gemm_grid, 256, GEMM_SMEM_BYTES>>>(x, Wk, K, GM, GD, GD);
    tf32_gemm<<<gemm_grid, 256, GEMM_SMEM_BYTES>>>(x, Wv, V, GM, GD, GD);

    flash_kernel<<<dim3(SEQ / 128, NH, 2), 256, FA_SMEM_BYTES>>>(Q, K, V, C);

    tf32_gemm<<<gemm_grid, 256, GEMM_SMEM_BYTES>>>(C, Wo, (float*)d_out, GM, GD, GD);
}

// round 4
// speedup vs baseline: 2.3276x; 2.3276x over previous
#include <cuda_runtime.h>
#include <cuda_fp16.h>
#include <math.h>
#include <stdint.h>

// Problem: b=2, s=2048, d=2048, H=16, Dh=128, window=2048 (never binds -> causal)
#define GM 4096
#define GD 2048
#define SEQ 2048
#define NH 16
#define DH 128

// ---------------- scratch (device globals; allocation forbidden) ----------------
__device__ float g_Q[GM * GD];
__device__ float g_K[GM * GD];
__device__ float g_V[GM * GD];
__device__ float g_C[GM * GD];
// 2-way fp16 splits of activations [M][K]
__device__ __half g_x1[GM * GD], g_x2[GM * GD];
__device__ __half g_c1[GM * GD], g_c2[GM * GD];
// transposed + 2-way-split weights: [N][K] (k-major)
__device__ __half g_wq1[GD * GD], g_wq2[GD * GD];
__device__ __half g_wk1[GD * GD], g_wk2[GD * GD];
__device__ __half g_wv1[GD * GD], g_wv2[GD * GD];
__device__ __half g_wo1[GD * GD], g_wo2[GD * GD];

// ---------------- PTX helpers (compute_103-safe: mma.sync / ldmatrix / cp.async) --
__device__ __forceinline__ uint32_t smem_u32(const void* p) {
    uint32_t a;
    asm("{ .reg .u64 t; cvta.to.shared.u64 t, %1; cvt.u32.u64 %0, t; }" : "=r"(a) : "l"(p));
    return a;
}

#define CP_ASYNC16(dst, src) \
    asm volatile("cp.async.cg.shared.global [%0], [%1], 16;" :: "r"(dst), "l"(src))
#define CP_COMMIT() asm volatile("cp.async.commit_group;" ::: "memory")
#define CP_WAIT(n)  asm volatile("cp.async.wait_group %0;" :: "n"(n) : "memory")

#define LDSM4(r0, r1, r2, r3, addr) \
    asm volatile("ldmatrix.sync.aligned.m8n8.x4.shared.b16 {%0,%1,%2,%3}, [%4];" \
                 : "=r"(r0), "=r"(r1), "=r"(r2), "=r"(r3) : "r"(addr))

#define MMA_F16(d, a, b0, b1)                                               \
    asm volatile(                                                           \
        "mma.sync.aligned.m16n8k16.row.col.f32.f16.f16.f32 "                \
        "{%0,%1,%2,%3}, {%4,%5,%6,%7}, {%8,%9}, {%0,%1,%2,%3};"             \
        : "+f"(d[0]), "+f"(d[1]), "+f"(d[2]), "+f"(d[3])                    \
        : "r"(a[0]), "r"(a[1]), "r"(a[2]), "r"(a[3]), "r"(b0), "r"(b1))

// ---------------------------------------------------------------------------
// Prep: elementwise 2-way fp16 split (same layout).
// ---------------------------------------------------------------------------
__global__ void split2(const float* __restrict__ in,
                       __half* __restrict__ o1, __half* __restrict__ o2)
{
    int i = blockIdx.x * blockDim.x + threadIdx.x;   // float4 index
    float4 v = reinterpret_cast<const float4*>(in)[i];
    float x[4] = {v.x, v.y, v.z, v.w};
    __half h[4], l[4];
#pragma unroll
    for (int j = 0; j < 4; j++) {
        h[j] = __float2half_rn(x[j]);
        l[j] = __float2half_rn(x[j] - __half2float(h[j]));
    }
    __half2* p1 = reinterpret_cast<__half2*>(o1) + 2 * i;
    __half2* p2 = reinterpret_cast<__half2*>(o2) + 2 * i;
    p1[0] = __halves2half2(h[0], h[1]); p1[1] = __halves2half2(h[2], h[3]);
    p2[0] = __halves2half2(l[0], l[1]); p2[1] = __halves2half2(l[2], l[3]);
}

// ---------------------------------------------------------------------------
// Prep: transpose + 2-way split: W fp32 [K][N] -> [N][K] fp16 x2.
// ---------------------------------------------------------------------------
__global__ void tsplit2(const float* __restrict__ W,
                        __half* __restrict__ o1, __half* __restrict__ o2)
{
    __shared__ float t[32][33];
    const int bx = blockIdx.x * 32;   // n
    const int by = blockIdx.y * 32;   // k
    const int tx = threadIdx.x, ty = threadIdx.y;
#pragma unroll
    for (int i = 0; i < 4; i++)
        t[ty + 8 * i][tx] = W[(size_t)(by + ty + 8 * i) * GD + bx + tx];
    __syncthreads();
#pragma unroll
    for (int i = 0; i < 4; i++) {
        float x = t[tx][ty + 8 * i];
        __half h = __float2half_rn(x);
        __half l = __float2half_rn(x - __half2float(h));
        size_t o = (size_t)(bx + ty + 8 * i) * GD + by + tx;
        o1[o] = h; o2[o] = l;
    }
}

// ---------------------------------------------------------------------------
// Split-fp16 tensor GEMM: C[M,N] = A @ Wt^T, fp32 out.
//   A given as 2 fp16 components [M][K]; Wt as 2 components [N][K].
//   CTA tile 128x128, KT=64, cp.async double-buffer, ldmatrix fragments,
//   mma.sync.m16n8k16: 3 MMAs per (frag, kstep): A1B1 + A1B2 + A2B1.
// 8 warps: warp m = (w&3)*32, n = (w>>2)*64.
// smem per stage: A1(16K) A2(16K) B1(16K) B2(16K) = 64KB; 2 stages = 128KB.
// Swizzle: 16B chunk c of row r stored at chunk (c ^ (r&7)).
// ---------------------------------------------------------------------------
#define KT 64
#define NCH (GD / KT)          // 32
#define TILE_B 16384           // 128 rows * 128 bytes
#define STAGE_B (4 * TILE_B)   // 64 KB
#define GEMM_SMEM (2 * STAGE_B)

__global__ __launch_bounds__(256, 1) void hgemm_split(
    const __half* __restrict__ A1, const __half* __restrict__ A2,
    const __half* __restrict__ B1, const __half* __restrict__ B2,
    float* __restrict__ C)
{
    extern __shared__ char smem[];
    const uint32_t sbase = smem_u32(smem);

    const int tid  = threadIdx.x;
    const int lane = tid & 31;
    const int warp = tid >> 5;
    const int wm = (warp & 3) * 32;
    const int wn = (warp >> 2) * 64;
    const int m0 = blockIdx.y * 128;
    const int n0 = blockIdx.x * 128;

    const __half* src[4] = {A1, A2, B1, B2};
    const int row0[4] = {m0, m0, n0, n0};

    // issue cp.async loads of chunk `ch` into stage `s`
    auto load_stage = [&](int ch, int s) {
        const int k0 = ch * KT;
        const uint32_t stage = sbase + s * STAGE_B;
#pragma unroll
        for (int t = 0; t < 4; t++) {
            const __half* g = src[t] + (size_t)row0[t] * GD + k0;
#pragma unroll
            for (int i = 0; i < 4; i++) {
                int idx = tid + i * 256;          // 0..1023 chunks
                int r = idx >> 3, c = idx & 7;
                uint32_t dst = stage + t * TILE_B + r * 128 + ((c ^ (r & 7)) << 4);
                CP_ASYNC16(dst, g + (size_t)r * GD + c * 8);
            }
        }
        CP_COMMIT();
    };

    float acc[2][8][4];
#pragma unroll
    for (int mt = 0; mt < 2; mt++)
#pragma unroll
        for (int nt = 0; nt < 8; nt++)
#pragma unroll
            for (int r = 0; r < 4; r++) acc[mt][nt][r] = 0.0f;

    load_stage(0, 0);

    for (int ch = 0; ch < NCH; ch++) {
        const int s = ch & 1;
        if (ch + 1 < NCH) { load_stage(ch + 1, s ^ 1); CP_WAIT(1); }
        else              { CP_WAIT(0); }
        __syncthreads();

        const uint32_t stage = sbase + s * STAGE_B;
#pragma unroll
        for (int ks = 0; ks < 4; ks++) {
            const int chunk = 2 * ks + (lane >> 4);
            // A fragments: [comp][mt][4]
            uint32_t a[2][2][4];
#pragma unroll
            for (int cc = 0; cc < 2; cc++)
#pragma unroll
                for (int mt = 0; mt < 2; mt++) {
                    int row = wm + mt * 16 + (lane & 15);
                    uint32_t ad = stage + cc * TILE_B + row * 128 + ((chunk ^ (row & 7)) << 4);
                    LDSM4(a[cc][mt][0], a[cc][mt][1], a[cc][mt][2], a[cc][mt][3], ad);
                }
            // B fragments: [comp][nt][2]
            uint32_t b[2][8][2];
#pragma unroll
            for (int cc = 0; cc < 2; cc++)
#pragma unroll
                for (int np = 0; np < 4; np++) {
                    int row = wn + np * 16 + (lane & 15);
                    uint32_t ad = stage + (2 + cc) * TILE_B + row * 128 + ((chunk ^ (row & 7)) << 4);
                    uint32_t r0, r1, r2, r3;
                    LDSM4(r0, r1, r2, r3, ad);
                    b[cc][2 * np][0] = r0; b[cc][2 * np][1] = r2;
                    b[cc][2 * np + 1][0] = r1; b[cc][2 * np + 1][1] = r3;
                }
#pragma unroll
            for (int mt = 0; mt < 2; mt++)
#pragma unroll
                for (int nt = 0; nt < 8; nt++) {
                    MMA_F16(acc[mt][nt], a[0][mt], b[0][nt][0], b[0][nt][1]);
                    MMA_F16(acc[mt][nt], a[0][mt], b[1][nt][0], b[1][nt][1]);
                    MMA_F16(acc[mt][nt], a[1][mt], b[0][nt][0], b[0][nt][1]);
                }
        }
        __syncthreads();
    }

    // epilogue
    const int gid = lane >> 2, tig = lane & 3;
#pragma unroll
    for (int mt = 0; mt < 2; mt++)
#pragma unroll
        for (int nt = 0; nt < 8; nt++) {
            int row = m0 + wm + mt * 16 + gid;
            int col = n0 + wn + nt * 8 + tig * 2;
            *reinterpret_cast<float2*>(&C[(size_t)row * GD + col]) =
                make_float2(acc[mt][nt][0], acc[mt][nt][1]);
            *reinterpret_cast<float2*>(&C[(size_t)(row + 8) * GD + col]) =
                make_float2(acc[mt][nt][2], acc[mt][nt][3]);
        }
}

// ---------------------------------------------------------------------------
// Causal flash attention (fp32, unchanged — known good).
// ---------------------------------------------------------------------------
#define FA_STRIDE 132
#define FA_SMEM_BYTES (3 * 128 * FA_STRIDE * 4)
#define SM_SCALE 0.08838834764831845f

__global__ __launch_bounds__(256, 1) void flash_kernel(
    const float* __restrict__ Qg, const float* __restrict__ Kg,
    const float* __restrict__ Vg, float* __restrict__ Og)
{
    extern __shared__ float sm[];
    float* Qs = sm;
    float* Ks = sm + 128 * FA_STRIDE;
    float* Vs = sm + 2 * 128 * FA_STRIDE;

    const int tid = threadIdx.x;
    const int tx = tid & 15;
    const int ty = tid >> 4;
    const int qt = blockIdx.x;
    const int h  = blockIdx.y;
    const int b  = blockIdx.z;
    const int q0 = qt * 128;
    const size_t base = ((size_t)b * SEQ) * GD + (size_t)h * DH;

#pragma unroll
    for (int i = 0; i < 16; i++) {
        int idx = tid + i * 256;
        int r  = idx >> 5;
        int d4 = (idx & 31) << 2;
        float4 v = *reinterpret_cast<const float4*>(&Qg[base + (size_t)(q0 + r) * GD + d4]);
        Qs[(d4 + 0) * FA_STRIDE + r] = v.x;
        Qs[(d4 + 1) * FA_STRIDE + r] = v.y;
        Qs[(d4 + 2) * FA_STRIDE + r] = v.z;
        Qs[(d4 + 3) * FA_STRIDE + r] = v.w;
    }

    float m_i[8], l_i[8], o[8][8];
#pragma unroll
    for (int i = 0; i < 8; i++) {
        m_i[i] = -1e30f; l_i[i] = 0.0f;
#pragma unroll
        for (int j = 0; j < 8; j++) o[i][j] = 0.0f;
    }

    for (int jt = 0; jt <= qt; jt++) {
        const int k0 = jt * 128;
        __syncthreads();
#pragma unroll
        for (int i = 0; i < 16; i++) {
            int idx = tid + i * 256;
            int r  = idx >> 5;
            int d4 = (idx & 31) << 2;
            float4 kv = *reinterpret_cast<const float4*>(&Kg[base + (size_t)(k0 + r) * GD + d4]);
            Ks[(d4 + 0) * FA_STRIDE + r] = kv.x;
            Ks[(d4 + 1) * FA_STRIDE + r] = kv.y;
            Ks[(d4 + 2) * FA_STRIDE + r] = kv.z;
            Ks[(d4 + 3) * FA_STRIDE + r] = kv.w;
            float4 vv = *reinterpret_cast<const float4*>(&Vg[base + (size_t)(k0 + r) * GD + d4]);
            *reinterpret_cast<float4*>(&Vs[r * FA_STRIDE + d4]) = vv;
        }
        __syncthreads();

        float s[8][8];
#pragma unroll
        for (int i = 0; i < 8; i++)
#pragma unroll
            for (int j = 0; j < 8; j++) s[i][j] = 0.0f;

        for (int d = 0; d < 128; d++) {
            float4 a0 = *reinterpret_cast<const float4*>(&Qs[d * FA_STRIDE + ty * 8]);
            float4 a1 = *reinterpret_cast<const float4*>(&Qs[d * FA_STRIDE + ty * 8 + 4]);
            float4 b0 = *reinterpret_cast<const float4*>(&Ks[d * FA_STRIDE + tx * 8]);
            float4 b1 = *reinterpret_cast<const float4*>(&Ks[d * FA_STRIDE + tx * 8 + 4]);
            float a[8] = {a0.x, a0.y, a0.z, a0.w, a1.x, a1.y, a1.z, a1.w};
            float bb[8] = {b0.x, b0.y, b0.z, b0.w, b1.x, b1.y, b1.z, b1.w};
#pragma unroll
            for (int i = 0; i < 8; i++)
#pragma unroll
                for (int j = 0; j < 8; j++)
                    s[i][j] = fmaf(a[i], bb[j], s[i][j]);
        }

        if (jt == qt) {
#pragma unroll
            for (int i = 0; i < 8; i++) {
                int qq = q0 + ty * 8 + i;
#pragma unroll
                for (int j = 0; j < 8; j++) {
                    int kk = k0 + tx * 8 + j;
                    s[i][j] = (kk > qq) ? -1e30f : s[i][j] * SM_SCALE;
                }
            }
        } else {
#pragma unroll
            for (int i = 0; i < 8; i++)
#pragma unroll
                for (int j = 0; j < 8; j++) s[i][j] *= SM_SCALE;
        }

#pragma unroll
        for (int i = 0; i < 8; i++) {
            float mloc = s[i][0];
#pragma unroll
            for (int j = 1; j < 8; j++) mloc = fmaxf(mloc, s[i][j]);
#pragma unroll
            for (int off = 8; off >= 1; off >>= 1)
                mloc = fmaxf(mloc, __shfl_xor_sync(0xffffffffu, mloc, off, 16));
            float mnew = fmaxf(m_i[i], mloc);
            float corr = __expf(m_i[i] - mnew);
            m_i[i] = mnew;
            float rs = 0.0f;
#pragma unroll
            for (int j = 0; j < 8; j++) {
                float p = __expf(s[i][j] - mnew);
                s[i][j] = p;
                rs += p;
            }
#pragma unroll
            for (int off = 8; off >= 1; off >>= 1)
                rs += __shfl_xor_sync(0xffffffffu, rs, off, 16);
            l_i[i] = l_i[i] * corr + rs;
#pragma unroll
            for (int j = 0; j < 8; j++) o[i][j] *= corr;
        }

        __syncthreads();
#pragma unroll
        for (int j = 0; j < 8; j++)
#pragma unroll
            for (int i = 0; i < 8; i++)
                Ks[(tx * 8 + j) * FA_STRIDE + ty * 8 + i] = s[i][j];
        __syncthreads();

        for (int k = 0; k < 128; k++) {
            float4 a0 = *reinterpret_cast<const float4*>(&Ks[k * FA_STRIDE + ty * 8]);
            float4 a1 = *reinterpret_cast<const float4*>(&Ks[k * FA_STRIDE + ty * 8 + 4]);
            float4 b0 = *reinterpret_cast<const float4*>(&Vs[k * FA_STRIDE + tx * 8]);
            float4 b1 = *reinterpret_cast<const float4*>(&Vs[k * FA_STRIDE + tx * 8 + 4]);
            float a[8] = {a0.x, a0.y, a0.z, a0.w, a1.x, a1.y, a1.z, a1.w};
            float bb[8] = {b0.x, b0.y, b0.z, b0.w, b1.x, b1.y, b1.z, b1.w};
#pragma unroll
            for (int i = 0; i < 8; i++)
#pragma unroll
                for (int j = 0; j < 8; j++)
                    o[i][j] = fmaf(a[i], bb[j], o[i][j]);
        }
    }

#pragma unroll
    for (int i = 0; i < 8; i++) {
        float inv = 1.0f / l_i[i];
        float* orow = &Og[base + (size_t)(q0 + ty * 8 + i) * GD + tx * 8];
        *reinterpret_cast<float4*>(orow) =
            make_float4(o[i][0] * inv, o[i][1] * inv, o[i][2] * inv, o[i][3] * inv);
        *reinterpret_cast<float4*>(orow + 4) =
            make_float4(o[i][4] * inv, o[i][5] * inv, o[i][6] * inv, o[i][7] * inv);
    }
}

// ---------------------------------------------------------------------------
extern "C" void kernel_launch(void* const* d_in, const int* in_sizes, int n_in,
                              void* d_out, int out_size)
{
    const float* x  = (const float*)d_in[0];
    const float* Wq = (const float*)d_in[1];
    const float* Wk = (const float*)d_in[2];
    const float* Wv = (const float*)d_in[3];
    const float* Wo = (const float*)d_in[4];

    float *Q, *K, *V, *C;
    cudaGetSymbolAddress((void**)&Q, g_Q);
    cudaGetSymbolAddress((void**)&K, g_K);
    cudaGetSymbolAddress((void**)&V, g_V);
    cudaGetSymbolAddress((void**)&C, g_C);

    __half *x1, *x2, *c1, *c2;
    cudaGetSymbolAddress((void**)&x1, g_x1); cudaGetSymbolAddress((void**)&x2, g_x2);
    cudaGetSymbolAddress((void**)&c1, g_c1); cudaGetSymbolAddress((void**)&c2, g_c2);

    __half *wq1, *wq2, *wk1, *wk2, *wv1, *wv2, *wo1, *wo2;
    cudaGetSymbolAddress((void**)&wq1, g_wq1); cudaGetSymbolAddress((void**)&wq2, g_wq2);
    cudaGetSymbolAddress((void**)&wk1, g_wk1); cudaGetSymbolAddress((void**)&wk2, g_wk2);
    cudaGetSymbolAddress((void**)&wv1, g_wv1); cudaGetSymbolAddress((void**)&wv2, g_wv2);
    cudaGetSymbolAddress((void**)&wo1, g_wo1); cudaGetSymbolAddress((void**)&wo2, g_wo2);

    cudaFuncSetAttribute(hgemm_split, cudaFuncAttributeMaxDynamicSharedMemorySize, GEMM_SMEM);
    cudaFuncSetAttribute(flash_kernel, cudaFuncAttributeMaxDynamicSharedMemorySize, FA_SMEM_BYTES);

    // prep
    split2<<<GM * GD / 1024, 256>>>(x, x1, x2);
    dim3 tgrid(GD / 32, GD / 32), tblk(32, 8);
    tsplit2<<<tgrid, tblk>>>(Wq, wq1, wq2);
    tsplit2<<<tgrid, tblk>>>(Wk, wk1, wk2);
    tsplit2<<<tgrid, tblk>>>(Wv, wv1, wv2);
    tsplit2<<<tgrid, tblk>>>(Wo, wo1, wo2);

    dim3 ggrid(GD / 128, GM / 128);   // (16, 32)
    hgemm_split<<<ggrid, 256, GEMM_SMEM>>>(x1, x2, wq1, wq2, Q);
    hgemm_split<<<ggrid, 256, GEMM_SMEM>>>(x1, x2, wk1, wk2, K);
    hgemm_split<<<ggrid, 256, GEMM_SMEM>>>(x1, x2, wv1, wv2, V);

    flash_kernel<<<dim3(SEQ / 128, NH, 2), 256, FA_SMEM_BYTES>>>(Q, K, V, C);

    split2<<<GM * GD / 1024, 256>>>(C, c1, c2);
    hgemm_split<<<ggrid, 256, GEMM_SMEM>>>(c1, c2, wo1, wo2, (float*)d_out);
}

// round 5
// speedup vs baseline: 3.5220x; 1.5132x over previous
#include <cuda_runtime.h>
#include <cuda_fp16.h>
#include <math.h>
#include <stdint.h>

// Problem: b=2, s=2048, d=2048, H=16, Dh=128, window=2048 (never binds -> causal)
#define GM 4096
#define GD 2048
#define SEQ 2048
#define NH 16
#define DH 128

// ---------------- scratch (device globals; allocation forbidden) ----------------
__device__ float g_C[GM * GD];
// fp16 2-way splits
__device__ __half g_x1[GM * GD], g_x2[GM * GD];
__device__ __half g_c1[GM * GD], g_c2[GM * GD];
__device__ __half g_qh[GM * GD], g_ql[GM * GD];
__device__ __half g_kh[GM * GD], g_kl[GM * GD];
__device__ __half g_vh[GM * GD], g_vl[GM * GD];
// transposed + split weights [N][K]
__device__ __half g_wq1[GD * GD], g_wq2[GD * GD];
__device__ __half g_wk1[GD * GD], g_wk2[GD * GD];
__device__ __half g_wv1[GD * GD], g_wv2[GD * GD];
__device__ __half g_wo1[GD * GD], g_wo2[GD * GD];

// ---------------- PTX helpers (compute_103-safe) ----------------
__device__ __forceinline__ uint32_t smem_u32(const void* p) {
    uint32_t a;
    asm("{ .reg .u64 t; cvta.to.shared.u64 t, %1; cvt.u32.u64 %0, t; }" : "=r"(a) : "l"(p));
    return a;
}
#define CP_ASYNC16(dst, src) \
    asm volatile("cp.async.cg.shared.global [%0], [%1], 16;" :: "r"(dst), "l"(src))
#define CP_COMMIT() asm volatile("cp.async.commit_group;" ::: "memory")
#define CP_WAIT(n)  asm volatile("cp.async.wait_group %0;" :: "n"(n) : "memory")

#define LDSM4(r0, r1, r2, r3, addr) \
    asm volatile("ldmatrix.sync.aligned.m8n8.x4.shared.b16 {%0,%1,%2,%3}, [%4];" \
                 : "=r"(r0), "=r"(r1), "=r"(r2), "=r"(r3) : "r"(addr))
#define LDSM4T(r0, r1, r2, r3, addr) \
    asm volatile("ldmatrix.sync.aligned.m8n8.x4.trans.shared.b16 {%0,%1,%2,%3}, [%4];" \
                 : "=r"(r0), "=r"(r1), "=r"(r2), "=r"(r3) : "r"(addr))

#define MMA_F16(d, a, b0, b1)                                               \
    asm volatile(                                                           \
        "mma.sync.aligned.m16n8k16.row.col.f32.f16.f16.f32 "                \
        "{%0,%1,%2,%3}, {%4,%5,%6,%7}, {%8,%9}, {%0,%1,%2,%3};"             \
        : "+f"(d[0]), "+f"(d[1]), "+f"(d[2]), "+f"(d[3])                    \
        : "r"(a[0]), "r"(a[1]), "r"(a[2]), "r"(a[3]), "r"(b0), "r"(b1))

__device__ __forceinline__ uint32_t pack_h2(__half a, __half b) {
    __half2 t = __halves2half2(a, b);
    return *reinterpret_cast<uint32_t*>(&t);
}
__device__ __forceinline__ void split_pack(float a, float b, uint32_t& hi, uint32_t& lo) {
    __half ha = __float2half_rn(a), hb = __float2half_rn(b);
    __half la = __float2half_rn(a - __half2float(ha));
    __half lb = __float2half_rn(b - __half2float(hb));
    hi = pack_h2(ha, hb); lo = pack_h2(la, lb);
}

// ---------------------------------------------------------------------------
// Prep kernels.
// ---------------------------------------------------------------------------
__global__ void split2(const float* __restrict__ in,
                       __half* __restrict__ o1, __half* __restrict__ o2)
{
    int i = blockIdx.x * blockDim.x + threadIdx.x;
    float4 v = reinterpret_cast<const float4*>(in)[i];
    float x[4] = {v.x, v.y, v.z, v.w};
    __half h[4], l[4];
#pragma unroll
    for (int j = 0; j < 4; j++) {
        h[j] = __float2half_rn(x[j]);
        l[j] = __float2half_rn(x[j] - __half2float(h[j]));
    }
    __half2* p1 = reinterpret_cast<__half2*>(o1) + 2 * i;
    __half2* p2 = reinterpret_cast<__half2*>(o2) + 2 * i;
    p1[0] = __halves2half2(h[0], h[1]); p1[1] = __halves2half2(h[2], h[3]);
    p2[0] = __halves2half2(l[0], l[1]); p2[1] = __halves2half2(l[2], l[3]);
}

__global__ void tsplit2(const float* __restrict__ W,
                        __half* __restrict__ o1, __half* __restrict__ o2)
{
    __shared__ float t[32][33];
    const int bx = blockIdx.x * 32;   // n
    const int by = blockIdx.y * 32;   // k
    const int tx = threadIdx.x, ty = threadIdx.y;
#pragma unroll
    for (int i = 0; i < 4; i++)
        t[ty + 8 * i][tx] = W[(size_t)(by + ty + 8 * i) * GD + bx + tx];
    __syncthreads();
#pragma unroll
    for (int i = 0; i < 4; i++) {
        float x = t[tx][ty + 8 * i];
        __half h = __float2half_rn(x);
        __half l = __float2half_rn(x - __half2float(h));
        size_t o = (size_t)(bx + ty + 8 * i) * GD + by + tx;
        o1[o] = h; o2[o] = l;
    }
}

// ---------------------------------------------------------------------------
// Split-fp16 tensor GEMM (round-4 proven). Output: fp32 Cf, or split (O1,O2).
// ---------------------------------------------------------------------------
#define KT 64
#define NCH (GD / KT)
#define TILE_B 16384
#define STAGE_B (4 * TILE_B)
#define GEMM_SMEM (2 * STAGE_B)

__global__ __launch_bounds__(256, 1) void hgemm_split(
    const __half* __restrict__ A1, const __half* __restrict__ A2,
    const __half* __restrict__ B1, const __half* __restrict__ B2,
    float* __restrict__ Cf, __half* __restrict__ O1, __half* __restrict__ O2)
{
    extern __shared__ char smem[];
    const uint32_t sbase = smem_u32(smem);

    const int tid  = threadIdx.x;
    const int lane = tid & 31;
    const int warp = tid >> 5;
    const int wm = (warp & 3) * 32;
    const int wn = (warp >> 2) * 64;
    const int m0 = blockIdx.y * 128;
    const int n0 = blockIdx.x * 128;

    const __half* src[4] = {A1, A2, B1, B2};
    const int row0[4] = {m0, m0, n0, n0};

    auto load_stage = [&](int ch, int s) {
        const int k0 = ch * KT;
        const uint32_t stage = sbase + s * STAGE_B;
#pragma unroll
        for (int t = 0; t < 4; t++) {
            const __half* g = src[t] + (size_t)row0[t] * GD + k0;
#pragma unroll
            for (int i = 0; i < 4; i++) {
                int idx = tid + i * 256;
                int r = idx >> 3, c = idx & 7;
                uint32_t dst = stage + t * TILE_B + r * 128 + ((c ^ (r & 7)) << 4);
                CP_ASYNC16(dst, g + (size_t)r * GD + c * 8);
            }
        }
        CP_COMMIT();
    };

    float acc[2][8][4];
#pragma unroll
    for (int mt = 0; mt < 2; mt++)
#pragma unroll
        for (int nt = 0; nt < 8; nt++)
#pragma unroll
            for (int r = 0; r < 4; r++) acc[mt][nt][r] = 0.0f;

    load_stage(0, 0);

    for (int ch = 0; ch < NCH; ch++) {
        const int s = ch & 1;
        if (ch + 1 < NCH) { load_stage(ch + 1, s ^ 1); CP_WAIT(1); }
        else              { CP_WAIT(0); }
        __syncthreads();

        const uint32_t stage = sbase + s * STAGE_B;
#pragma unroll
        for (int ks = 0; ks < 4; ks++) {
            const int chunk = 2 * ks + (lane >> 4);
            uint32_t a[2][2][4];
#pragma unroll
            for (int cc = 0; cc < 2; cc++)
#pragma unroll
                for (int mt = 0; mt < 2; mt++) {
                    int row = wm + mt * 16 + (lane & 15);
                    uint32_t ad = stage + cc * TILE_B + row * 128 + ((chunk ^ (row & 7)) << 4);
                    LDSM4(a[cc][mt][0], a[cc][mt][1], a[cc][mt][2], a[cc][mt][3], ad);
                }
            uint32_t b[2][8][2];
#pragma unroll
            for (int cc = 0; cc < 2; cc++)
#pragma unroll
                for (int np = 0; np < 4; np++) {
                    int row = wn + np * 16 + (lane & 15);
                    uint32_t ad = stage + (2 + cc) * TILE_B + row * 128 + ((chunk ^ (row & 7)) << 4);
                    uint32_t r0, r1, r2, r3;
                    LDSM4(r0, r1, r2, r3, ad);
                    b[cc][2 * np][0] = r0; b[cc][2 * np][1] = r2;
                    b[cc][2 * np + 1][0] = r1; b[cc][2 * np + 1][1] = r3;
                }
#pragma unroll
            for (int mt = 0; mt < 2; mt++)
#pragma unroll
                for (int nt = 0; nt < 8; nt++) {
                    MMA_F16(acc[mt][nt], a[0][mt], b[0][nt][0], b[0][nt][1]);
                    MMA_F16(acc[mt][nt], a[0][mt], b[1][nt][0], b[1][nt][1]);
                    MMA_F16(acc[mt][nt], a[1][mt], b[0][nt][0], b[0][nt][1]);
                }
        }
        __syncthreads();
    }

    const int gid = lane >> 2, tig = lane & 3;
#pragma unroll
    for (int mt = 0; mt < 2; mt++)
#pragma unroll
        for (int nt = 0; nt < 8; nt++) {
            int row = m0 + wm + mt * 16 + gid;
            int col = n0 + wn + nt * 8 + tig * 2;
            if (O1) {
                uint32_t h0, l0, h1, l1;
                split_pack(acc[mt][nt][0], acc[mt][nt][1], h0, l0);
                split_pack(acc[mt][nt][2], acc[mt][nt][3], h1, l1);
                *reinterpret_cast<uint32_t*>(&O1[(size_t)row * GD + col]) = h0;
                *reinterpret_cast<uint32_t*>(&O2[(size_t)row * GD + col]) = l0;
                *reinterpret_cast<uint32_t*>(&O1[(size_t)(row + 8) * GD + col]) = h1;
                *reinterpret_cast<uint32_t*>(&O2[(size_t)(row + 8) * GD + col]) = l1;
            } else {
                *reinterpret_cast<float2*>(&Cf[(size_t)row * GD + col]) =
                    make_float2(acc[mt][nt][0], acc[mt][nt][1]);
                *reinterpret_cast<float2*>(&Cf[(size_t)(row + 8) * GD + col]) =
                    make_float2(acc[mt][nt][2], acc[mt][nt][3]);
            }
        }
}

// ---------------------------------------------------------------------------
// Tensor-core causal flash attention.
// CTA = (qt, h, b): 128 q rows. 8 warps x 16 q rows. k-tiles of 128.
// smem tiles (32KB each): 0 Qh, 1 Ql, 2 Kh, 3 Kl, 4 Vh, 5 Vl; rows 256B,
// 16-byte chunk swizzle: slot = (c&8) | ((c ^ (r&7)) & 7).
// S: 3 split MMAs; P: in-register C->A frag conversion, split hi/lo;
// PV: 3 split MMAs with V via ldmatrix.trans.
// ---------------------------------------------------------------------------
#define FT_TILE 32768
#define FT_SMEM (6 * FT_TILE)
#define SM_SCALE 0.08838834764831845f

__device__ __forceinline__ uint32_t ft_addr(uint32_t sb, int tile, int r, int c) {
    return sb + tile * FT_TILE + r * 256 + (((c & 8) | ((c ^ (r & 7)) & 7)) << 4);
}

__global__ __launch_bounds__(256, 1) void flash_tc(
    const __half* __restrict__ Qh, const __half* __restrict__ Ql,
    const __half* __restrict__ Kh, const __half* __restrict__ Kl,
    const __half* __restrict__ Vh, const __half* __restrict__ Vl,
    float* __restrict__ Og)
{
    extern __shared__ char smem[];
    const uint32_t sb = smem_u32(smem);

    const int tid = threadIdx.x, lane = tid & 31, warp = tid >> 5;
    const int qt = blockIdx.x, h = blockIdx.y, b = blockIdx.z;
    const int q0 = qt * 128;
    const size_t base = ((size_t)b * SEQ) * GD + (size_t)h * DH;

    auto load_tile = [&](int t, const __half* src, int r0) {
        const __half* g = src + base + (size_t)r0 * GD;
#pragma unroll
        for (int i = 0; i < 8; i++) {
            int idx = tid + i * 256;
            int r = idx >> 4, c = idx & 15;
            CP_ASYNC16(ft_addr(sb, t, r, c), g + (size_t)r * GD + c * 8);
        }
    };

    load_tile(0, Qh, q0); load_tile(1, Ql, q0);
    load_tile(2, Kh, 0);  load_tile(3, Kl, 0);
    load_tile(4, Vh, 0);  load_tile(5, Vl, 0);
    CP_COMMIT(); CP_WAIT(0); __syncthreads();

    const int gid = lane >> 2, tig = lane & 3;
    const int qw = warp * 16;                 // warp q-offset within tile

    float o[16][4];
#pragma unroll
    for (int nt = 0; nt < 16; nt++)
#pragma unroll
        for (int c = 0; c < 4; c++) o[nt][c] = 0.0f;
    float m[2] = {-1e30f, -1e30f}, l[2] = {0.0f, 0.0f};

    for (int jt = 0; jt <= qt; jt++) {
        // ---- S = Q @ K^T ----
        float s[16][4];
#pragma unroll
        for (int nt = 0; nt < 16; nt++)
#pragma unroll
            for (int c = 0; c < 4; c++) s[nt][c] = 0.0f;

#pragma unroll
        for (int kf = 0; kf < 8; kf++) {
            const int ac = 2 * kf + (lane >> 4);
            uint32_t ah[4], al[4];
            {
                int r = qw + (lane & 15);
                LDSM4(ah[0], ah[1], ah[2], ah[3], ft_addr(sb, 0, r, ac));
                LDSM4(al[0], al[1], al[2], al[3], ft_addr(sb, 1, r, ac));
            }
#pragma unroll
            for (int nt2 = 0; nt2 < 8; nt2++) {
                int r = nt2 * 16 + (lane & 15);
                uint32_t h0, h1, h2, h3, l0, l1, l2, l3;
                LDSM4(h0, h1, h2, h3, ft_addr(sb, 2, r, ac));
                LDSM4(l0, l1, l2, l3, ft_addr(sb, 3, r, ac));
                MMA_F16(s[2 * nt2],     ah, h0, h2);
                MMA_F16(s[2 * nt2],     ah, l0, l2);
                MMA_F16(s[2 * nt2],     al, h0, h2);
                MMA_F16(s[2 * nt2 + 1], ah, h1, h3);
                MMA_F16(s[2 * nt2 + 1], ah, l1, l3);
                MMA_F16(s[2 * nt2 + 1], al, h1, h3);
            }
        }

        // ---- scale + causal mask ----
        if (jt == qt) {
#pragma unroll
            for (int nt = 0; nt < 16; nt++) {
                int colb = jt * 128 + nt * 8 + 2 * tig;
#pragma unroll
                for (int c = 0; c < 4; c++) {
                    int row = q0 + qw + gid + ((c >= 2) ? 8 : 0);
                    int col = colb + (c & 1);
                    s[nt][c] = (col > row) ? -1e30f : s[nt][c] * SM_SCALE;
                }
            }
        } else {
#pragma unroll
            for (int nt = 0; nt < 16; nt++)
#pragma unroll
                for (int c = 0; c < 4; c++) s[nt][c] *= SM_SCALE;
        }

        // ---- online softmax ----
        float mx0 = -1e30f, mx1 = -1e30f;
#pragma unroll
        for (int nt = 0; nt < 16; nt++) {
            mx0 = fmaxf(mx0, fmaxf(s[nt][0], s[nt][1]));
            mx1 = fmaxf(mx1, fmaxf(s[nt][2], s[nt][3]));
        }
#pragma unroll
        for (int off = 1; off <= 2; off <<= 1) {
            mx0 = fmaxf(mx0, __shfl_xor_sync(0xffffffffu, mx0, off, 4));
            mx1 = fmaxf(mx1, __shfl_xor_sync(0xffffffffu, mx1, off, 4));
        }
        float mn0 = fmaxf(m[0], mx0), mn1 = fmaxf(m[1], mx1);
        float cr0 = __expf(m[0] - mn0), cr1 = __expf(m[1] - mn1);
        m[0] = mn0; m[1] = mn1;
        float sum0 = 0.0f, sum1 = 0.0f;
#pragma unroll
        for (int nt = 0; nt < 16; nt++) {
            s[nt][0] = __expf(s[nt][0] - mn0); sum0 += s[nt][0];
            s[nt][1] = __expf(s[nt][1] - mn0); sum0 += s[nt][1];
            s[nt][2] = __expf(s[nt][2] - mn1); sum1 += s[nt][2];
            s[nt][3] = __expf(s[nt][3] - mn1); sum1 += s[nt][3];
        }
#pragma unroll
        for (int off = 1; off <= 2; off <<= 1) {
            sum0 += __shfl_xor_sync(0xffffffffu, sum0, off, 4);
            sum1 += __shfl_xor_sync(0xffffffffu, sum1, off, 4);
        }
        l[0] = l[0] * cr0 + sum0;
        l[1] = l[1] * cr1 + sum1;
#pragma unroll
        for (int nt = 0; nt < 16; nt++) {
            o[nt][0] *= cr0; o[nt][1] *= cr0;
            o[nt][2] *= cr1; o[nt][3] *= cr1;
        }

        __syncthreads();   // all warps done reading K smem
        if (jt < qt) {     // prefetch next K, overlapped with PV
            load_tile(2, Kh, (jt + 1) * 128);
            load_tile(3, Kl, (jt + 1) * 128);
            CP_COMMIT();
        }

        // ---- O += P @ V ----
#pragma unroll
        for (int kf = 0; kf < 8; kf++) {
            uint32_t ph[4], pl[4];
            split_pack(s[2 * kf][0],     s[2 * kf][1],     ph[0], pl[0]);
            split_pack(s[2 * kf][2],     s[2 * kf][3],     ph[1], pl[1]);
            split_pack(s[2 * kf + 1][0], s[2 * kf + 1][1], ph[2], pl[2]);
            split_pack(s[2 * kf + 1][2], s[2 * kf + 1][3], ph[3], pl[3]);
#pragma unroll
            for (int nt2 = 0; nt2 < 8; nt2++) {
                int r = kf * 16 + (lane & 15);
                int c = 2 * nt2 + (lane >> 4);
                uint32_t v0, v1, v2, v3, w0, w1, w2, w3;
                LDSM4T(v0, v1, v2, v3, ft_addr(sb, 4, r, c));
                LDSM4T(w0, w1, w2, w3, ft_addr(sb, 5, r, c));
                MMA_F16(o[2 * nt2],     ph, v0, v1);
                MMA_F16(o[2 * nt2],     ph, w0, w1);
                MMA_F16(o[2 * nt2],     pl, v0, v1);
                MMA_F16(o[2 * nt2 + 1], ph, v2, v3);
                MMA_F16(o[2 * nt2 + 1], ph, w2, w3);
                MMA_F16(o[2 * nt2 + 1], pl, v2, v3);
            }
        }

        __syncthreads();   // all warps done reading V smem
        if (jt < qt) {
            load_tile(4, Vh, (jt + 1) * 128);
            load_tile(5, Vl, (jt + 1) * 128);
            CP_COMMIT(); CP_WAIT(0); __syncthreads();
        }
    }

    // ---- epilogue ----
    float inv0 = 1.0f / l[0], inv1 = 1.0f / l[1];
    int row0 = q0 + qw + gid, row1 = row0 + 8;
#pragma unroll
    for (int nt = 0; nt < 16; nt++) {
        int col = nt * 8 + 2 * tig;
        *reinterpret_cast<float2*>(&Og[base + (size_t)row0 * GD + col]) =
            make_float2(o[nt][0] * inv0, o[nt][1] * inv0);
        *reinterpret_cast<float2*>(&Og[base + (size_t)row1 * GD + col]) =
            make_float2(o[nt][2] * inv1, o[nt][3] * inv1);
    }
}

// ---------------------------------------------------------------------------
extern "C" void kernel_launch(void* const* d_in, const int* in_sizes, int n_in,
                              void* d_out, int out_size)
{
    const float* x  = (const float*)d_in[0];
    const float* Wq = (const float*)d_in[1];
    const float* Wk = (const float*)d_in[2];
    const float* Wv = (const float*)d_in[3];
    const float* Wo = (const float*)d_in[4];

    float* C;
    cudaGetSymbolAddress((void**)&C, g_C);
    __half *x1, *x2, *c1, *c2, *qh, *ql, *kh, *kl, *vh, *vl;
    cudaGetSymbolAddress((void**)&x1, g_x1); cudaGetSymbolAddress((void**)&x2, g_x2);
    cudaGetSymbolAddress((void**)&c1, g_c1); cudaGetSymbolAddress((void**)&c2, g_c2);
    cudaGetSymbolAddress((void**)&qh, g_qh); cudaGetSymbolAddress((void**)&ql, g_ql);
    cudaGetSymbolAddress((void**)&kh, g_kh); cudaGetSymbolAddress((void**)&kl, g_kl);
    cudaGetSymbolAddress((void**)&vh, g_vh); cudaGetSymbolAddress((void**)&vl, g_vl);

    __half *wq1, *wq2, *wk1, *wk2, *wv1, *wv2, *wo1, *wo2;
    cudaGetSymbolAddress((void**)&wq1, g_wq1); cudaGetSymbolAddress((void**)&wq2, g_wq2);
    cudaGetSymbolAddress((void**)&wk1, g_wk1); cudaGetSymbolAddress((void**)&wk2, g_wk2);
    cudaGetSymbolAddress((void**)&wv1, g_wv1); cudaGetSymbolAddress((void**)&wv2, g_wv2);
    cudaGetSymbolAddress((void**)&wo1, g_wo1); cudaGetSymbolAddress((void**)&wo2, g_wo2);

    cudaFuncSetAttribute(hgemm_split, cudaFuncAttributeMaxDynamicSharedMemorySize, GEMM_SMEM);
    cudaFuncSetAttribute(flash_tc, cudaFuncAttributeMaxDynamicSharedMemorySize, FT_SMEM);

    split2<<<GM * GD / 1024, 256>>>(x, x1, x2);
    dim3 tgrid(GD / 32, GD / 32), tblk(32, 8);
    tsplit2<<<tgrid, tblk>>>(Wq, wq1, wq2);
    tsplit2<<<tgrid, tblk>>>(Wk, wk1, wk2);
    tsplit2<<<tgrid, tblk>>>(Wv, wv1, wv2);
    tsplit2<<<tgrid, tblk>>>(Wo, wo1, wo2);

    dim3 ggrid(GD / 128, GM / 128);
    hgemm_split<<<ggrid, 256, GEMM_SMEM>>>(x1, x2, wq1, wq2, nullptr, qh, ql);
    hgemm_split<<<ggrid, 256, GEMM_SMEM>>>(x1, x2, wk1, wk2, nullptr, kh, kl);
    hgemm_split<<<ggrid, 256, GEMM_SMEM>>>(x1, x2, wv1, wv2, nullptr, vh, vl);

    flash_tc<<<dim3(SEQ / 128, NH, 2), 256, FT_SMEM>>>(qh, ql, kh, kl, vh, vl, C);

    split2<<<GM * GD / 1024, 256>>>(C, c1, c2);
    hgemm_split<<<ggrid, 256, GEMM_SMEM>>>(c1, c2, wo1, wo2, (float*)d_out, nullptr, nullptr);
}

// round 6
// speedup vs baseline: 3.6413x; 1.0339x over previous
#include <cuda_runtime.h>
#include <cuda_fp16.h>
#include <math.h>
#include <stdint.h>

// Problem: b=2, s=2048, d=2048, H=16, Dh=128, window=2048 (never binds -> causal)
#define GM 4096
#define GD 2048
#define SEQ 2048
#define NH 16
#define DH 128

// ---------------- scratch (device globals; allocation forbidden) ----------------
__device__ __half g_x1[GM * GD], g_x2[GM * GD];
__device__ __half g_c1[GM * GD], g_c2[GM * GD];
__device__ __half g_qh[GM * GD], g_ql[GM * GD];
__device__ __half g_kh[GM * GD], g_kl[GM * GD];
__device__ __half g_vh[GM * GD], g_vl[GM * GD];
__device__ __half g_wq1[GD * GD], g_wq2[GD * GD];
__device__ __half g_wk1[GD * GD], g_wk2[GD * GD];
__device__ __half g_wv1[GD * GD], g_wv2[GD * GD];
__device__ __half g_wo1[GD * GD], g_wo2[GD * GD];

// ---------------- PTX helpers (compute_103-safe) ----------------
__device__ __forceinline__ uint32_t smem_u32(const void* p) {
    uint32_t a;
    asm("{ .reg .u64 t; cvta.to.shared.u64 t, %1; cvt.u32.u64 %0, t; }" : "=r"(a) : "l"(p));
    return a;
}
#define CP_ASYNC16(dst, src) \
    asm volatile("cp.async.cg.shared.global [%0], [%1], 16;" :: "r"(dst), "l"(src))
#define CP_COMMIT() asm volatile("cp.async.commit_group;" ::: "memory")
#define CP_WAIT(n)  asm volatile("cp.async.wait_group %0;" :: "n"(n) : "memory")

#define LDSM4(r0, r1, r2, r3, addr) \
    asm volatile("ldmatrix.sync.aligned.m8n8.x4.shared.b16 {%0,%1,%2,%3}, [%4];" \
                 : "=r"(r0), "=r"(r1), "=r"(r2), "=r"(r3) : "r"(addr))
#define LDSM4T(r0, r1, r2, r3, addr) \
    asm volatile("ldmatrix.sync.aligned.m8n8.x4.trans.shared.b16 {%0,%1,%2,%3}, [%4];" \
                 : "=r"(r0), "=r"(r1), "=r"(r2), "=r"(r3) : "r"(addr))

#define MMA_F16(d, a, b0, b1)                                               \
    asm volatile(                                                           \
        "mma.sync.aligned.m16n8k16.row.col.f32.f16.f16.f32 "                \
        "{%0,%1,%2,%3}, {%4,%5,%6,%7}, {%8,%9}, {%0,%1,%2,%3};"             \
        : "+f"(d[0]), "+f"(d[1]), "+f"(d[2]), "+f"(d[3])                    \
        : "r"(a[0]), "r"(a[1]), "r"(a[2]), "r"(a[3]), "r"(b0), "r"(b1))

__device__ __forceinline__ uint32_t pack_h2(__half a, __half b) {
    __half2 t = __halves2half2(a, b);
    return *reinterpret_cast<uint32_t*>(&t);
}
__device__ __forceinline__ void split_pack(float a, float b, uint32_t& hi, uint32_t& lo) {
    __half ha = __float2half_rn(a), hb = __float2half_rn(b);
    __half la = __float2half_rn(a - __half2float(ha));
    __half lb = __float2half_rn(b - __half2float(hb));
    hi = pack_h2(ha, hb); lo = pack_h2(la, lb);
}

// ---------------------------------------------------------------------------
// Prep kernels.
// ---------------------------------------------------------------------------
__global__ void split2(const float* __restrict__ in,
                       __half* __restrict__ o1, __half* __restrict__ o2)
{
    int i = blockIdx.x * blockDim.x + threadIdx.x;
    float4 v = reinterpret_cast<const float4*>(in)[i];
    float x[4] = {v.x, v.y, v.z, v.w};
    __half h[4], l[4];
#pragma unroll
    for (int j = 0; j < 4; j++) {
        h[j] = __float2half_rn(x[j]);
        l[j] = __float2half_rn(x[j] - __half2float(h[j]));
    }
    __half2* p1 = reinterpret_cast<__half2*>(o1) + 2 * i;
    __half2* p2 = reinterpret_cast<__half2*>(o2) + 2 * i;
    p1[0] = __halves2half2(h[0], h[1]); p1[1] = __halves2half2(h[2], h[3]);
    p2[0] = __halves2half2(l[0], l[1]); p2[1] = __halves2half2(l[2], l[3]);
}

// Batched: all 4 weight transposes+splits in one launch (z = weight index).
__global__ void tsplit4(const float* __restrict__ W0, const float* __restrict__ W1,
                        const float* __restrict__ W2, const float* __restrict__ W3,
                        __half* __restrict__ a0, __half* __restrict__ b0,
                        __half* __restrict__ a1, __half* __restrict__ b1,
                        __half* __restrict__ a2, __half* __restrict__ b2,
                        __half* __restrict__ a3, __half* __restrict__ b3)
{
    const float* W = (blockIdx.z == 0) ? W0 : (blockIdx.z == 1) ? W1
                   : (blockIdx.z == 2) ? W2 : W3;
    __half* o1 = (blockIdx.z == 0) ? a0 : (blockIdx.z == 1) ? a1
               : (blockIdx.z == 2) ? a2 : a3;
    __half* o2 = (blockIdx.z == 0) ? b0 : (blockIdx.z == 1) ? b1
               : (blockIdx.z == 2) ? b2 : b3;

    __shared__ float t[32][33];
    const int bx = blockIdx.x * 32;   // n
    const int by = blockIdx.y * 32;   // k
    const int tx = threadIdx.x, ty = threadIdx.y;
#pragma unroll
    for (int i = 0; i < 4; i++)
        t[ty + 8 * i][tx] = W[(size_t)(by + ty + 8 * i) * GD + bx + tx];
    __syncthreads();
#pragma unroll
    for (int i = 0; i < 4; i++) {
        float x = t[tx][ty + 8 * i];
        __half h = __float2half_rn(x);
        __half l = __float2half_rn(x - __half2float(h));
        size_t o = (size_t)(bx + ty + 8 * i) * GD + by + tx;
        o1[o] = h; o2[o] = l;
    }
}

// ---------------------------------------------------------------------------
// Split-fp16 tensor GEMM. MMAs issued term-major (reuse distance 16).
// ---------------------------------------------------------------------------
#define KT 64
#define NCH (GD / KT)
#define TILE_B 16384
#define STAGE_B (4 * TILE_B)
#define GEMM_SMEM (2 * STAGE_B)

__global__ __launch_bounds__(256, 1) void hgemm_split(
    const __half* __restrict__ A1, const __half* __restrict__ A2,
    const __half* __restrict__ B1, const __half* __restrict__ B2,
    float* __restrict__ Cf, __half* __restrict__ O1, __half* __restrict__ O2)
{
    extern __shared__ char smem[];
    const uint32_t sbase = smem_u32(smem);

    const int tid  = threadIdx.x;
    const int lane = tid & 31;
    const int warp = tid >> 5;
    const int wm = (warp & 3) * 32;
    const int wn = (warp >> 2) * 64;
    const int m0 = blockIdx.y * 128;
    const int n0 = blockIdx.x * 128;

    const __half* src[4] = {A1, A2, B1, B2};
    const int row0[4] = {m0, m0, n0, n0};

    auto load_stage = [&](int ch, int s) {
        const int k0 = ch * KT;
        const uint32_t stage = sbase + s * STAGE_B;
#pragma unroll
        for (int t = 0; t < 4; t++) {
            const __half* g = src[t] + (size_t)row0[t] * GD + k0;
#pragma unroll
            for (int i = 0; i < 4; i++) {
                int idx = tid + i * 256;
                int r = idx >> 3, c = idx & 7;
                uint32_t dst = stage + t * TILE_B + r * 128 + ((c ^ (r & 7)) << 4);
                CP_ASYNC16(dst, g + (size_t)r * GD + c * 8);
            }
        }
        CP_COMMIT();
    };

    float acc[2][8][4];
#pragma unroll
    for (int mt = 0; mt < 2; mt++)
#pragma unroll
        for (int nt = 0; nt < 8; nt++)
#pragma unroll
            for (int r = 0; r < 4; r++) acc[mt][nt][r] = 0.0f;

    load_stage(0, 0);

    for (int ch = 0; ch < NCH; ch++) {
        const int s = ch & 1;
        if (ch + 1 < NCH) { load_stage(ch + 1, s ^ 1); CP_WAIT(1); }
        else              { CP_WAIT(0); }
        __syncthreads();

        const uint32_t stage = sbase + s * STAGE_B;
#pragma unroll
        for (int ks = 0; ks < 4; ks++) {
            const int chunk = 2 * ks + (lane >> 4);
            uint32_t a[2][2][4];
#pragma unroll
            for (int cc = 0; cc < 2; cc++)
#pragma unroll
                for (int mt = 0; mt < 2; mt++) {
                    int row = wm + mt * 16 + (lane & 15);
                    uint32_t ad = stage + cc * TILE_B + row * 128 + ((chunk ^ (row & 7)) << 4);
                    LDSM4(a[cc][mt][0], a[cc][mt][1], a[cc][mt][2], a[cc][mt][3], ad);
                }
            uint32_t b[2][8][2];
#pragma unroll
            for (int cc = 0; cc < 2; cc++)
#pragma unroll
                for (int np = 0; np < 4; np++) {
                    int row = wn + np * 16 + (lane & 15);
                    uint32_t ad = stage + (2 + cc) * TILE_B + row * 128 + ((chunk ^ (row & 7)) << 4);
                    uint32_t r0, r1, r2, r3;
                    LDSM4(r0, r1, r2, r3, ad);
                    b[cc][2 * np][0] = r0; b[cc][2 * np][1] = r2;
                    b[cc][2 * np + 1][0] = r1; b[cc][2 * np + 1][1] = r3;
                }
            // term-major: same-accumulator reuse distance = 16 MMAs
#pragma unroll
            for (int mt = 0; mt < 2; mt++)
#pragma unroll
                for (int nt = 0; nt < 8; nt++)
                    MMA_F16(acc[mt][nt], a[0][mt], b[0][nt][0], b[0][nt][1]);
#pragma unroll
            for (int mt = 0; mt < 2; mt++)
#pragma unroll
                for (int nt = 0; nt < 8; nt++)
                    MMA_F16(acc[mt][nt], a[0][mt], b[1][nt][0], b[1][nt][1]);
#pragma unroll
            for (int mt = 0; mt < 2; mt++)
#pragma unroll
                for (int nt = 0; nt < 8; nt++)
                    MMA_F16(acc[mt][nt], a[1][mt], b[0][nt][0], b[0][nt][1]);
        }
        __syncthreads();
    }

    const int gid = lane >> 2, tig = lane & 3;
#pragma unroll
    for (int mt = 0; mt < 2; mt++)
#pragma unroll
        for (int nt = 0; nt < 8; nt++) {
            int row = m0 + wm + mt * 16 + gid;
            int col = n0 + wn + nt * 8 + tig * 2;
            if (O1) {
                uint32_t h0, l0, h1, l1;
                split_pack(acc[mt][nt][0], acc[mt][nt][1], h0, l0);
                split_pack(acc[mt][nt][2], acc[mt][nt][3], h1, l1);
                *reinterpret_cast<uint32_t*>(&O1[(size_t)row * GD + col]) = h0;
                *reinterpret_cast<uint32_t*>(&O2[(size_t)row * GD + col]) = l0;
                *reinterpret_cast<uint32_t*>(&O1[(size_t)(row + 8) * GD + col]) = h1;
                *reinterpret_cast<uint32_t*>(&O2[(size_t)(row + 8) * GD + col]) = l1;
            } else {
                *reinterpret_cast<float2*>(&Cf[(size_t)row * GD + col]) =
                    make_float2(acc[mt][nt][0], acc[mt][nt][1]);
                *reinterpret_cast<float2*>(&Cf[(size_t)(row + 8) * GD + col]) =
                    make_float2(acc[mt][nt][2], acc[mt][nt][3]);
            }
        }
}

// ---------------------------------------------------------------------------
// Tensor-core causal flash attention (V unsplit; interleaved MMA issue).
// smem tiles: 0 Qh, 1 Ql, 2 Kh, 3 Kl, 4 Vh.  Output: split c1/c2 (fused).
// ---------------------------------------------------------------------------
#define FT_TILE 32768
#define FT_SMEM (5 * FT_TILE)
#define SM_SCALE 0.08838834764831845f

__device__ __forceinline__ uint32_t ft_addr(uint32_t sb, int tile, int r, int c) {
    return sb + tile * FT_TILE + r * 256 + (((c & 8) | ((c ^ (r & 7)) & 7)) << 4);
}

__global__ __launch_bounds__(256, 1) void flash_tc(
    const __half* __restrict__ Qh, const __half* __restrict__ Ql,
    const __half* __restrict__ Kh, const __half* __restrict__ Kl,
    const __half* __restrict__ Vh,
    __half* __restrict__ C1, __half* __restrict__ C2)
{
    extern __shared__ char smem[];
    const uint32_t sb = smem_u32(smem);

    const int tid = threadIdx.x, lane = tid & 31, warp = tid >> 5;
    const int qt = blockIdx.x, h = blockIdx.y, b = blockIdx.z;
    const int q0 = qt * 128;
    const size_t base = ((size_t)b * SEQ) * GD + (size_t)h * DH;

    auto load_tile = [&](int t, const __half* src, int r0) {
        const __half* g = src + base + (size_t)r0 * GD;
#pragma unroll
        for (int i = 0; i < 8; i++) {
            int idx = tid + i * 256;
            int r = idx >> 4, c = idx & 15;
            CP_ASYNC16(ft_addr(sb, t, r, c), g + (size_t)r * GD + c * 8);
        }
    };

    load_tile(0, Qh, q0); load_tile(1, Ql, q0);
    load_tile(2, Kh, 0);  load_tile(3, Kl, 0);
    load_tile(4, Vh, 0);
    CP_COMMIT(); CP_WAIT(0); __syncthreads();

    const int gid = lane >> 2, tig = lane & 3;
    const int qw = warp * 16;

    float o[16][4];
#pragma unroll
    for (int nt = 0; nt < 16; nt++)
#pragma unroll
        for (int c = 0; c < 4; c++) o[nt][c] = 0.0f;
    float m[2] = {-1e30f, -1e30f}, l[2] = {0.0f, 0.0f};

    for (int jt = 0; jt <= qt; jt++) {
        // ---- S = Q @ K^T (pairs of K-tile fragments; 12 MMAs over 4 accs) ----
        float s[16][4];
#pragma unroll
        for (int nt = 0; nt < 16; nt++)
#pragma unroll
            for (int c = 0; c < 4; c++) s[nt][c] = 0.0f;

#pragma unroll
        for (int kf = 0; kf < 8; kf++) {
            const int ac = 2 * kf + (lane >> 4);
            uint32_t ah[4], al[4];
            {
                int r = qw + (lane & 15);
                LDSM4(ah[0], ah[1], ah[2], ah[3], ft_addr(sb, 0, r, ac));
                LDSM4(al[0], al[1], al[2], al[3], ft_addr(sb, 1, r, ac));
            }
#pragma unroll
            for (int p = 0; p < 4; p++) {
                int r0 = (2 * p) * 16 + (lane & 15);
                int r1 = (2 * p + 1) * 16 + (lane & 15);
                uint32_t h0, h1, h2, h3, l0, l1, l2, l3;
                uint32_t i0, i1, i2, i3, m0r, m1r, m2r, m3r;
                LDSM4(h0, h1, h2, h3, ft_addr(sb, 2, r0, ac));
                LDSM4(l0, l1, l2, l3, ft_addr(sb, 3, r0, ac));
                LDSM4(i0, i1, i2, i3, ft_addr(sb, 2, r1, ac));
                LDSM4(m0r, m1r, m2r, m3r, ft_addr(sb, 3, r1, ac));
                float* s0 = s[4 * p];     float* s1 = s[4 * p + 1];
                float* s2 = s[4 * p + 2]; float* s3 = s[4 * p + 3];
                MMA_F16(s0, ah, h0, h2);  MMA_F16(s1, ah, h1, h3);
                MMA_F16(s2, ah, i0, i2);  MMA_F16(s3, ah, i1, i3);
                MMA_F16(s0, ah, l0, l2);  MMA_F16(s1, ah, l1, l3);
                MMA_F16(s2, ah, m0r, m2r); MMA_F16(s3, ah, m1r, m3r);
                MMA_F16(s0, al, h0, h2);  MMA_F16(s1, al, h1, h3);
                MMA_F16(s2, al, i0, i2);  MMA_F16(s3, al, i1, i3);
            }
        }

        // ---- scale + causal mask ----
        if (jt == qt) {
#pragma unroll
            for (int nt = 0; nt < 16; nt++) {
                int colb = jt * 128 + nt * 8 + 2 * tig;
#pragma unroll
                for (int c = 0; c < 4; c++) {
                    int row = q0 + qw + gid + ((c >= 2) ? 8 : 0);
                    int col = colb + (c & 1);
                    s[nt][c] = (col > row) ? -1e30f : s[nt][c] * SM_SCALE;
                }
            }
        } else {
#pragma unroll
            for (int nt = 0; nt < 16; nt++)
#pragma unroll
                for (int c = 0; c < 4; c++) s[nt][c] *= SM_SCALE;
        }

        // ---- online softmax ----
        float mx0 = -1e30f, mx1 = -1e30f;
#pragma unroll
        for (int nt = 0; nt < 16; nt++) {
            mx0 = fmaxf(mx0, fmaxf(s[nt][0], s[nt][1]));
            mx1 = fmaxf(mx1, fmaxf(s[nt][2], s[nt][3]));
        }
#pragma unroll
        for (int off = 1; off <= 2; off <<= 1) {
            mx0 = fmaxf(mx0, __shfl_xor_sync(0xffffffffu, mx0, off, 4));
            mx1 = fmaxf(mx1, __shfl_xor_sync(0xffffffffu, mx1, off, 4));
        }
        float mn0 = fmaxf(m[0], mx0), mn1 = fmaxf(m[1], mx1);
        float cr0 = __expf(m[0] - mn0), cr1 = __expf(m[1] - mn1);
        m[0] = mn0; m[1] = mn1;
        float sum0 = 0.0f, sum1 = 0.0f;
#pragma unroll
        for (int nt = 0; nt < 16; nt++) {
            s[nt][0] = __expf(s[nt][0] - mn0); sum0 += s[nt][0];
            s[nt][1] = __expf(s[nt][1] - mn0); sum0 += s[nt][1];
            s[nt][2] = __expf(s[nt][2] - mn1); sum1 += s[nt][2];
            s[nt][3] = __expf(s[nt][3] - mn1); sum1 += s[nt][3];
        }
#pragma unroll
        for (int off = 1; off <= 2; off <<= 1) {
            sum0 += __shfl_xor_sync(0xffffffffu, sum0, off, 4);
            sum1 += __shfl_xor_sync(0xffffffffu, sum1, off, 4);
        }
        l[0] = l[0] * cr0 + sum0;
        l[1] = l[1] * cr1 + sum1;
#pragma unroll
        for (int nt = 0; nt < 16; nt++) {
            o[nt][0] *= cr0; o[nt][1] *= cr0;
            o[nt][2] *= cr1; o[nt][3] *= cr1;
        }

        __syncthreads();   // all warps done reading K smem
        if (jt < qt) {     // prefetch next K during PV
            load_tile(2, Kh, (jt + 1) * 128);
            load_tile(3, Kl, (jt + 1) * 128);
            CP_COMMIT();
        }

        // ---- O += P @ V (P split, V fp16-hi; 8 MMAs over 4 accs per pair) ----
#pragma unroll
        for (int kf = 0; kf < 8; kf++) {
            uint32_t ph[4], pl[4];
            split_pack(s[2 * kf][0],     s[2 * kf][1],     ph[0], pl[0]);
            split_pack(s[2 * kf][2],     s[2 * kf][3],     ph[1], pl[1]);
            split_pack(s[2 * kf + 1][0], s[2 * kf + 1][1], ph[2], pl[2]);
            split_pack(s[2 * kf + 1][2], s[2 * kf + 1][3], ph[3], pl[3]);
            int r = kf * 16 + (lane & 15);
#pragma unroll
            for (int p = 0; p < 4; p++) {
                int c0 = 2 * (2 * p) + (lane >> 4);
                int c1 = 2 * (2 * p + 1) + (lane >> 4);
                uint32_t v0, v1, v2, v3, u0, u1, u2, u3;
                LDSM4T(v0, v1, v2, v3, ft_addr(sb, 4, r, c0));
                LDSM4T(u0, u1, u2, u3, ft_addr(sb, 4, r, c1));
                float* o0 = o[4 * p];     float* o1 = o[4 * p + 1];
                float* o2 = o[4 * p + 2]; float* o3 = o[4 * p + 3];
                MMA_F16(o0, ph, v0, v1);  MMA_F16(o1, ph, v2, v3);
                MMA_F16(o2, ph, u0, u1);  MMA_F16(o3, ph, u2, u3);
                MMA_F16(o0, pl, v0, v1);  MMA_F16(o1, pl, v2, v3);
                MMA_F16(o2, pl, u0, u1);  MMA_F16(o3, pl, u2, u3);
            }
        }

        __syncthreads();   // all warps done reading V smem
        if (jt < qt) {
            load_tile(4, Vh, (jt + 1) * 128);
            CP_COMMIT(); CP_WAIT(0); __syncthreads();
        }
    }

    // ---- epilogue: normalize + fused hi/lo split store ----
    float inv0 = 1.0f / l[0], inv1 = 1.0f / l[1];
    int row0 = q0 + qw + gid, row1 = row0 + 8;
#pragma unroll
    for (int nt = 0; nt < 16; nt++) {
        int col = nt * 8 + 2 * tig;
        uint32_t h0, l0, h1, l1;
        split_pack(o[nt][0] * inv0, o[nt][1] * inv0, h0, l0);
        split_pack(o[nt][2] * inv1, o[nt][3] * inv1, h1, l1);
        *reinterpret_cast<uint32_t*>(&C1[base + (size_t)row0 * GD + col]) = h0;
        *reinterpret_cast<uint32_t*>(&C2[base + (size_t)row0 * GD + col]) = l0;
        *reinterpret_cast<uint32_t*>(&C1[base + (size_t)row1 * GD + col]) = h1;
        *reinterpret_cast<uint32_t*>(&C2[base + (size_t)row1 * GD + col]) = l1;
    }
}

// ---------------------------------------------------------------------------
extern "C" void kernel_launch(void* const* d_in, const int* in_sizes, int n_in,
                              void* d_out, int out_size)
{
    const float* x  = (const float*)d_in[0];
    const float* Wq = (const float*)d_in[1];
    const float* Wk = (const float*)d_in[2];
    const float* Wv = (const float*)d_in[3];
    const float* Wo = (const float*)d_in[4];

    __half *x1, *x2, *c1, *c2, *qh, *ql, *kh, *kl, *vh, *vl;
    cudaGetSymbolAddress((void**)&x1, g_x1); cudaGetSymbolAddress((void**)&x2, g_x2);
    cudaGetSymbolAddress((void**)&c1, g_c1); cudaGetSymbolAddress((void**)&c2, g_c2);
    cudaGetSymbolAddress((void**)&qh, g_qh); cudaGetSymbolAddress((void**)&ql, g_ql);
    cudaGetSymbolAddress((void**)&kh, g_kh); cudaGetSymbolAddress((void**)&kl, g_kl);
    cudaGetSymbolAddress((void**)&vh, g_vh); cudaGetSymbolAddress((void**)&vl, g_vl);

    __half *wq1, *wq2, *wk1, *wk2, *wv1, *wv2, *wo1, *wo2;
    cudaGetSymbolAddress((void**)&wq1, g_wq1); cudaGetSymbolAddress((void**)&wq2, g_wq2);
    cudaGetSymbolAddress((void**)&wk1, g_wk1); cudaGetSymbolAddress((void**)&wk2, g_wk2);
    cudaGetSymbolAddress((void**)&wv1, g_wv1); cudaGetSymbolAddress((void**)&wv2, g_wv2);
    cudaGetSymbolAddress((void**)&wo1, g_wo1); cudaGetSymbolAddress((void**)&wo2, g_wo2);

    cudaFuncSetAttribute(hgemm_split, cudaFuncAttributeMaxDynamicSharedMemorySize, GEMM_SMEM);
    cudaFuncSetAttribute(flash_tc, cudaFuncAttributeMaxDynamicSharedMemorySize, FT_SMEM);

    split2<<<GM * GD / 1024, 256>>>(x, x1, x2);
    dim3 tgrid(GD / 32, GD / 32, 4), tblk(32, 8);
    tsplit4<<<tgrid, tblk>>>(Wq, Wk, Wv, Wo,
                             wq1, wq2, wk1, wk2, wv1, wv2, wo1, wo2);

    dim3 ggrid(GD / 128, GM / 128);
    hgemm_split<<<ggrid, 256, GEMM_SMEM>>>(x1, x2, wq1, wq2, nullptr, qh, ql);
    hgemm_split<<<ggrid, 256, GEMM_SMEM>>>(x1, x2, wk1, wk2, nullptr, kh, kl);
    hgemm_split<<<ggrid, 256, GEMM_SMEM>>>(x1, x2, wv1, wv2, nullptr, vh, vl);

    flash_tc<<<dim3(SEQ / 128, NH, 2), 256, FT_SMEM>>>(qh, ql, kh, kl, vh, c1, c2);

    hgemm_split<<<ggrid, 256, GEMM_SMEM>>>(c1, c2, wo1, wo2, (float*)d_out, nullptr, nullptr);
}

// round 7
// speedup vs baseline: 3.7848x; 1.0394x over previous
#include <cuda_runtime.h>
#include <cuda_fp16.h>
#include <math.h>
#include <stdint.h>

// Problem: b=2, s=2048, d=2048, H=16, Dh=128, window=2048 (never binds -> causal)
#define GM 4096
#define GD 2048
#define SEQ 2048
#define NH 16
#define DH 128

// ---------------- scratch (device globals; allocation forbidden) ----------------
__device__ __half g_x1[GM * GD], g_x2[GM * GD];
__device__ __half g_c1[GM * GD], g_c2[GM * GD];
__device__ __half g_qh[GM * GD], g_ql[GM * GD];
__device__ __half g_kh[GM * GD], g_kl[GM * GD];
__device__ __half g_vh[GM * GD], g_vl[GM * GD];
__device__ __half g_wq1[GD * GD], g_wq2[GD * GD];
__device__ __half g_wk1[GD * GD], g_wk2[GD * GD];
__device__ __half g_wv1[GD * GD], g_wv2[GD * GD];
__device__ __half g_wo1[GD * GD], g_wo2[GD * GD];

// ---------------- PTX helpers (compute_103-safe) ----------------
__device__ __forceinline__ uint32_t smem_u32(const void* p) {
    uint32_t a;
    asm("{ .reg .u64 t; cvta.to.shared.u64 t, %1; cvt.u32.u64 %0, t; }" : "=r"(a) : "l"(p));
    return a;
}
#define CP_ASYNC16(dst, src) \
    asm volatile("cp.async.cg.shared.global [%0], [%1], 16;" :: "r"(dst), "l"(src))
#define CP_COMMIT() asm volatile("cp.async.commit_group;" ::: "memory")
#define CP_WAIT(n)  asm volatile("cp.async.wait_group %0;" :: "n"(n) : "memory")

#define LDSM4(r0, r1, r2, r3, addr) \
    asm volatile("ldmatrix.sync.aligned.m8n8.x4.shared.b16 {%0,%1,%2,%3}, [%4];" \
                 : "=r"(r0), "=r"(r1), "=r"(r2), "=r"(r3) : "r"(addr))
#define LDSM4T(r0, r1, r2, r3, addr) \
    asm volatile("ldmatrix.sync.aligned.m8n8.x4.trans.shared.b16 {%0,%1,%2,%3}, [%4];" \
                 : "=r"(r0), "=r"(r1), "=r"(r2), "=r"(r3) : "r"(addr))

#define MMA_F16(d, a, b0, b1)                                               \
    asm volatile(                                                           \
        "mma.sync.aligned.m16n8k16.row.col.f32.f16.f16.f32 "                \
        "{%0,%1,%2,%3}, {%4,%5,%6,%7}, {%8,%9}, {%0,%1,%2,%3};"             \
        : "+f"(d[0]), "+f"(d[1]), "+f"(d[2]), "+f"(d[3])                    \
        : "r"(a[0]), "r"(a[1]), "r"(a[2]), "r"(a[3]), "r"(b0), "r"(b1))

__device__ __forceinline__ uint32_t pack_h2(__half a, __half b) {
    __half2 t = __halves2half2(a, b);
    return *reinterpret_cast<uint32_t*>(&t);
}
__device__ __forceinline__ void split_pack(float a, float b, uint32_t& hi, uint32_t& lo) {
    __half ha = __float2half_rn(a), hb = __float2half_rn(b);
    __half la = __float2half_rn(a - __half2float(ha));
    __half lb = __float2half_rn(b - __half2float(hb));
    hi = pack_h2(ha, hb); lo = pack_h2(la, lb);
}

// ---------------------------------------------------------------------------
// Prep kernels.
// ---------------------------------------------------------------------------
__global__ void split2(const float* __restrict__ in,
                       __half* __restrict__ o1, __half* __restrict__ o2)
{
    int i = blockIdx.x * blockDim.x + threadIdx.x;
    float4 v = reinterpret_cast<const float4*>(in)[i];
    float x[4] = {v.x, v.y, v.z, v.w};
    __half h[4], l[4];
#pragma unroll
    for (int j = 0; j < 4; j++) {
        h[j] = __float2half_rn(x[j]);
        l[j] = __float2half_rn(x[j] - __half2float(h[j]));
    }
    __half2* p1 = reinterpret_cast<__half2*>(o1) + 2 * i;
    __half2* p2 = reinterpret_cast<__half2*>(o2) + 2 * i;
    p1[0] = __halves2half2(h[0], h[1]); p1[1] = __halves2half2(h[2], h[3]);
    p2[0] = __halves2half2(l[0], l[1]); p2[1] = __halves2half2(l[2], l[3]);
}

__global__ void tsplit4(const float* __restrict__ W0, const float* __restrict__ W1,
                        const float* __restrict__ W2, const float* __restrict__ W3,
                        __half* __restrict__ a0, __half* __restrict__ b0,
                        __half* __restrict__ a1, __half* __restrict__ b1,
                        __half* __restrict__ a2, __half* __restrict__ b2,
                        __half* __restrict__ a3, __half* __restrict__ b3)
{
    const float* W = (blockIdx.z == 0) ? W0 : (blockIdx.z == 1) ? W1
                   : (blockIdx.z == 2) ? W2 : W3;
    __half* o1 = (blockIdx.z == 0) ? a0 : (blockIdx.z == 1) ? a1
               : (blockIdx.z == 2) ? a2 : a3;
    __half* o2 = (blockIdx.z == 0) ? b0 : (blockIdx.z == 1) ? b1
               : (blockIdx.z == 2) ? b2 : b3;

    __shared__ float t[32][33];
    const int bx = blockIdx.x * 32;   // n
    const int by = blockIdx.y * 32;   // k
    const int tx = threadIdx.x, ty = threadIdx.y;
#pragma unroll
    for (int i = 0; i < 4; i++)
        t[ty + 8 * i][tx] = W[(size_t)(by + ty + 8 * i) * GD + bx + tx];
    __syncthreads();
#pragma unroll
    for (int i = 0; i < 4; i++) {
        float x = t[tx][ty + 8 * i];
        __half h = __float2half_rn(x);
        __half l = __float2half_rn(x - __half2float(h));
        size_t o = (size_t)(bx + ty + 8 * i) * GD + by + tx;
        o1[o] = h; o2[o] = l;
    }
}

// ---------------------------------------------------------------------------
// Split-fp16 GEMM body. KT=32 per stage; hi/lo packed side-by-side in a
// 128-row x 128B tile (chunks 0-3 = comp1, 4-7 = comp2). 3-stage cp.async
// pipeline, 96KB smem -> 2 CTAs/SM.
// ---------------------------------------------------------------------------
#define KT 32
#define NCH (GD / KT)          // 64
#define TILE_B 16384           // 128 rows * 128 bytes (both components)
#define STAGE_B (2 * TILE_B)   // tileA + tileB = 32 KB
#define GEMM_SMEM (3 * STAGE_B)

__device__ __forceinline__ void gemm_body(
    const __half* __restrict__ A1, const __half* __restrict__ A2,
    const __half* __restrict__ B1, const __half* __restrict__ B2,
    float* __restrict__ Cf, __half* __restrict__ O1, __half* __restrict__ O2,
    uint32_t sbase, int m0, int n0)
{
    const int tid  = threadIdx.x;
    const int lane = tid & 31;
    const int warp = tid >> 5;
    const int wm = (warp & 3) * 32;
    const int wn = (warp >> 2) * 64;

    auto load_stage = [&](int ch, int s) {
        const int k0 = ch * KT;
        const uint32_t stage = sbase + s * STAGE_B;
#pragma unroll
        for (int i = 0; i < 8; i++) {
            int idx = tid + i * 256;          // 0..2047
            int t = idx >> 10;                // 0 = A tile, 1 = B tile
            int w = idx & 1023;
            int r = w >> 3, c = w & 7;
            const __half* g = (c < 4) ? (t ? B1 : A1) : (t ? B2 : A2);
            int row = (t ? n0 : m0) + r;
            int kc = c & 3;
            uint32_t dst = stage + t * TILE_B + r * 128 + ((c ^ (r & 7)) << 4);
            CP_ASYNC16(dst, g + (size_t)row * GD + k0 + kc * 8);
        }
        CP_COMMIT();
    };

    float acc[2][8][4];
#pragma unroll
    for (int mt = 0; mt < 2; mt++)
#pragma unroll
        for (int nt = 0; nt < 8; nt++)
#pragma unroll
            for (int r = 0; r < 4; r++) acc[mt][nt][r] = 0.0f;

    load_stage(0, 0);
    load_stage(1, 1);

    for (int ch = 0; ch < NCH; ch++) {
        const int s = ch % 3;
        if (ch + 2 < NCH) { load_stage(ch + 2, (ch + 2) % 3); CP_WAIT(2); }
        else if (ch + 1 < NCH) { CP_WAIT(1); }
        else { CP_WAIT(0); }
        __syncthreads();                   // data visible

        const uint32_t stage = sbase + s * STAGE_B;
        const uint32_t tA = stage, tB = stage + TILE_B;
#pragma unroll
        for (int ks = 0; ks < 2; ks++) {
            const int c1 = 2 * ks + (lane >> 4);       // comp1 chunk
            const int c2 = 4 + c1;                     // comp2 chunk
            uint32_t a1[2][4], a2[2][4];
#pragma unroll
            for (int mt = 0; mt < 2; mt++) {
                int row = wm + mt * 16 + (lane & 15);
                LDSM4(a1[mt][0], a1[mt][1], a1[mt][2], a1[mt][3],
                      tA + row * 128 + ((c1 ^ (row & 7)) << 4));
                LDSM4(a2[mt][0], a2[mt][1], a2[mt][2], a2[mt][3],
                      tA + row * 128 + ((c2 ^ (row & 7)) << 4));
            }
            uint32_t b[8][2];
#pragma unroll
            for (int np = 0; np < 4; np++) {
                int row = wn + np * 16 + (lane & 15);
                uint32_t r0, r1, r2, r3;
                LDSM4(r0, r1, r2, r3, tB + row * 128 + ((c1 ^ (row & 7)) << 4));
                b[2 * np][0] = r0; b[2 * np][1] = r2;
                b[2 * np + 1][0] = r1; b[2 * np + 1][1] = r3;
            }
            // terms using B-comp1: A1*B1 then A2*B1 (reuse distance 16)
#pragma unroll
            for (int mt = 0; mt < 2; mt++)
#pragma unroll
                for (int nt = 0; nt < 8; nt++)
                    MMA_F16(acc[mt][nt], a1[mt], b[nt][0], b[nt][1]);
#pragma unroll
            for (int mt = 0; mt < 2; mt++)
#pragma unroll
                for (int nt = 0; nt < 8; nt++)
                    MMA_F16(acc[mt][nt], a2[mt], b[nt][0], b[nt][1]);
            // load B-comp2 over b[], then A1*B2
#pragma unroll
            for (int np = 0; np < 4; np++) {
                int row = wn + np * 16 + (lane & 15);
                uint32_t r0, r1, r2, r3;
                LDSM4(r0, r1, r2, r3, tB + row * 128 + ((c2 ^ (row & 7)) << 4));
                b[2 * np][0] = r0; b[2 * np][1] = r2;
                b[2 * np + 1][0] = r1; b[2 * np + 1][1] = r3;
            }
#pragma unroll
            for (int mt = 0; mt < 2; mt++)
#pragma unroll
                for (int nt = 0; nt < 8; nt++)
                    MMA_F16(acc[mt][nt], a1[mt], b[nt][0], b[nt][1]);
        }
        __syncthreads();                   // stage free for reuse
    }

    const int gid = lane >> 2, tig = lane & 3;
#pragma unroll
    for (int mt = 0; mt < 2; mt++)
#pragma unroll
        for (int nt = 0; nt < 8; nt++) {
            int row = m0 + wm + mt * 16 + gid;
            int col = n0 + wn + nt * 8 + tig * 2;
            if (O1) {
                uint32_t h0, l0, h1, l1;
                split_pack(acc[mt][nt][0], acc[mt][nt][1], h0, l0);
                split_pack(acc[mt][nt][2], acc[mt][nt][3], h1, l1);
                *reinterpret_cast<uint32_t*>(&O1[(size_t)row * GD + col]) = h0;
                *reinterpret_cast<uint32_t*>(&O2[(size_t)row * GD + col]) = l0;
                *reinterpret_cast<uint32_t*>(&O1[(size_t)(row + 8) * GD + col]) = h1;
                *reinterpret_cast<uint32_t*>(&O2[(size_t)(row + 8) * GD + col]) = l1;
            } else {
                *reinterpret_cast<float2*>(&Cf[(size_t)row * GD + col]) =
                    make_float2(acc[mt][nt][0], acc[mt][nt][1]);
                *reinterpret_cast<float2*>(&Cf[(size_t)(row + 8) * GD + col]) =
                    make_float2(acc[mt][nt][2], acc[mt][nt][3]);
            }
        }
}

// Fused Q/K/V projection: blockIdx.z selects the weight + destination.
__global__ __launch_bounds__(256, 2) void hgemm_qkv(
    const __half* __restrict__ x1, const __half* __restrict__ x2,
    const __half* __restrict__ wq1, const __half* __restrict__ wq2,
    const __half* __restrict__ wk1, const __half* __restrict__ wk2,
    const __half* __restrict__ wv1, const __half* __restrict__ wv2,
    __half* __restrict__ qh, __half* __restrict__ ql,
    __half* __restrict__ kh, __half* __restrict__ kl,
    __half* __restrict__ vh, __half* __restrict__ vl)
{
    extern __shared__ char smem[];
    const int z = blockIdx.z;
    const __half* B1 = (z == 0) ? wq1 : (z == 1) ? wk1 : wv1;
    const __half* B2 = (z == 0) ? wq2 : (z == 1) ? wk2 : wv2;
    __half* O1 = (z == 0) ? qh : (z == 1) ? kh : vh;
    __half* O2 = (z == 0) ? ql : (z == 1) ? kl : vl;
    gemm_body(x1, x2, B1, B2, nullptr, O1, O2,
              smem_u32(smem), blockIdx.y * 128, blockIdx.x * 128);
}

// Output projection: fp32 result.
__global__ __launch_bounds__(256, 2) void hgemm_out(
    const __half* __restrict__ c1, const __half* __restrict__ c2,
    const __half* __restrict__ wo1, const __half* __restrict__ wo2,
    float* __restrict__ Cf)
{
    extern __shared__ char smem[];
    gemm_body(c1, c2, wo1, wo2, Cf, nullptr, nullptr,
              smem_u32(smem), blockIdx.y * 128, blockIdx.x * 128);
}

// ---------------------------------------------------------------------------
// Tensor-core causal flash attention (round-6 proven).
// ---------------------------------------------------------------------------
#define FT_TILE 32768
#define FT_SMEM (5 * FT_TILE)
#define SM_SCALE 0.08838834764831845f

__device__ __forceinline__ uint32_t ft_addr(uint32_t sb, int tile, int r, int c) {
    return sb + tile * FT_TILE + r * 256 + (((c & 8) | ((c ^ (r & 7)) & 7)) << 4);
}

__global__ __launch_bounds__(256, 1) void flash_tc(
    const __half* __restrict__ Qh, const __half* __restrict__ Ql,
    const __half* __restrict__ Kh, const __half* __restrict__ Kl,
    const __half* __restrict__ Vh,
    __half* __restrict__ C1, __half* __restrict__ C2)
{
    extern __shared__ char smem[];
    const uint32_t sb = smem_u32(smem);

    const int tid = threadIdx.x, lane = tid & 31, warp = tid >> 5;
    const int qt = blockIdx.x, h = blockIdx.y, b = blockIdx.z;
    const int q0 = qt * 128;
    const size_t base = ((size_t)b * SEQ) * GD + (size_t)h * DH;

    auto load_tile = [&](int t, const __half* src, int r0) {
        const __half* g = src + base + (size_t)r0 * GD;
#pragma unroll
        for (int i = 0; i < 8; i++) {
            int idx = tid + i * 256;
            int r = idx >> 4, c = idx & 15;
            CP_ASYNC16(ft_addr(sb, t, r, c), g + (size_t)r * GD + c * 8);
        }
    };

    load_tile(0, Qh, q0); load_tile(1, Ql, q0);
    load_tile(2, Kh, 0);  load_tile(3, Kl, 0);
    load_tile(4, Vh, 0);
    CP_COMMIT(); CP_WAIT(0); __syncthreads();

    const int gid = lane >> 2, tig = lane & 3;
    const int qw = warp * 16;

    float o[16][4];
#pragma unroll
    for (int nt = 0; nt < 16; nt++)
#pragma unroll
        for (int c = 0; c < 4; c++) o[nt][c] = 0.0f;
    float m[2] = {-1e30f, -1e30f}, l[2] = {0.0f, 0.0f};

    for (int jt = 0; jt <= qt; jt++) {
        float s[16][4];
#pragma unroll
        for (int nt = 0; nt < 16; nt++)
#pragma unroll
            for (int c = 0; c < 4; c++) s[nt][c] = 0.0f;

#pragma unroll
        for (int kf = 0; kf < 8; kf++) {
            const int ac = 2 * kf + (lane >> 4);
            uint32_t ah[4], al[4];
            {
                int r = qw + (lane & 15);
                LDSM4(ah[0], ah[1], ah[2], ah[3], ft_addr(sb, 0, r, ac));
                LDSM4(al[0], al[1], al[2], al[3], ft_addr(sb, 1, r, ac));
            }
#pragma unroll
            for (int p = 0; p < 4; p++) {
                int r0 = (2 * p) * 16 + (lane & 15);
                int r1 = (2 * p + 1) * 16 + (lane & 15);
                uint32_t h0, h1, h2, h3, l0, l1, l2, l3;
                uint32_t i0, i1, i2, i3, m0r, m1r, m2r, m3r;
                LDSM4(h0, h1, h2, h3, ft_addr(sb, 2, r0, ac));
                LDSM4(l0, l1, l2, l3, ft_addr(sb, 3, r0, ac));
                LDSM4(i0, i1, i2, i3, ft_addr(sb, 2, r1, ac));
                LDSM4(m0r, m1r, m2r, m3r, ft_addr(sb, 3, r1, ac));
                float* s0 = s[4 * p];     float* s1 = s[4 * p + 1];
                float* s2 = s[4 * p + 2]; float* s3 = s[4 * p + 3];
                MMA_F16(s0, ah, h0, h2);  MMA_F16(s1, ah, h1, h3);
                MMA_F16(s2, ah, i0, i2);  MMA_F16(s3, ah, i1, i3);
                MMA_F16(s0, ah, l0, l2);  MMA_F16(s1, ah, l1, l3);
                MMA_F16(s2, ah, m0r, m2r); MMA_F16(s3, ah, m1r, m3r);
                MMA_F16(s0, al, h0, h2);  MMA_F16(s1, al, h1, h3);
                MMA_F16(s2, al, i0, i2);  MMA_F16(s3, al, i1, i3);
            }
        }

        if (jt == qt) {
#pragma unroll
            for (int nt = 0; nt < 16; nt++) {
                int colb = jt * 128 + nt * 8 + 2 * tig;
#pragma unroll
                for (int c = 0; c < 4; c++) {
                    int row = q0 + qw + gid + ((c >= 2) ? 8 : 0);
                    int col = colb + (c & 1);
                    s[nt][c] = (col > row) ? -1e30f : s[nt][c] * SM_SCALE;
                }
            }
        } else {
#pragma unroll
            for (int nt = 0; nt < 16; nt++)
#pragma unroll
                for (int c = 0; c < 4; c++) s[nt][c] *= SM_SCALE;
        }

        float mx0 = -1e30f, mx1 = -1e30f;
#pragma unroll
        for (int nt = 0; nt < 16; nt++) {
            mx0 = fmaxf(mx0, fmaxf(s[nt][0], s[nt][1]));
            mx1 = fmaxf(mx1, fmaxf(s[nt][2], s[nt][3]));
        }
#pragma unroll
        for (int off = 1; off <= 2; off <<= 1) {
            mx0 = fmaxf(mx0, __shfl_xor_sync(0xffffffffu, mx0, off, 4));
            mx1 = fmaxf(mx1, __shfl_xor_sync(0xffffffffu, mx1, off, 4));
        }
        float mn0 = fmaxf(m[0], mx0), mn1 = fmaxf(m[1], mx1);
        float cr0 = __expf(m[0] - mn0), cr1 = __expf(m[1] - mn1);
        m[0] = mn0; m[1] = mn1;
        float sum0 = 0.0f, sum1 = 0.0f;
#pragma unroll
        for (int nt = 0; nt < 16; nt++) {
            s[nt][0] = __expf(s[nt][0] - mn0); sum0 += s[nt][0];
            s[nt][1] = __expf(s[nt][1] - mn0); sum0 += s[nt][1];
            s[nt][2] = __expf(s[nt][2] - mn1); sum1 += s[nt][2];
            s[nt][3] = __expf(s[nt][3] - mn1); sum1 += s[nt][3];
        }
#pragma unroll
        for (int off = 1; off <= 2; off <<= 1) {
            sum0 += __shfl_xor_sync(0xffffffffu, sum0, off, 4);
            sum1 += __shfl_xor_sync(0xffffffffu, sum1, off, 4);
        }
        l[0] = l[0] * cr0 + sum0;
        l[1] = l[1] * cr1 + sum1;
#pragma unroll
        for (int nt = 0; nt < 16; nt++) {
            o[nt][0] *= cr0; o[nt][1] *= cr0;
            o[nt][2] *= cr1; o[nt][3] *= cr1;
        }

        __syncthreads();
        if (jt < qt) {
            load_tile(2, Kh, (jt + 1) * 128);
            load_tile(3, Kl, (jt + 1) * 128);
            CP_COMMIT();
        }

#pragma unroll
        for (int kf = 0; kf < 8; kf++) {
            uint32_t ph[4], pl[4];
            split_pack(s[2 * kf][0],     s[2 * kf][1],     ph[0], pl[0]);
            split_pack(s[2 * kf][2],     s[2 * kf][3],     ph[1], pl[1]);
            split_pack(s[2 * kf + 1][0], s[2 * kf + 1][1], ph[2], pl[2]);
            split_pack(s[2 * kf + 1][2], s[2 * kf + 1][3], ph[3], pl[3]);
            int r = kf * 16 + (lane & 15);
#pragma unroll
            for (int p = 0; p < 4; p++) {
                int c0 = 2 * (2 * p) + (lane >> 4);
                int c1 = 2 * (2 * p + 1) + (lane >> 4);
                uint32_t v0, v1, v2, v3, u0, u1, u2, u3;
                LDSM4T(v0, v1, v2, v3, ft_addr(sb, 4, r, c0));
                LDSM4T(u0, u1, u2, u3, ft_addr(sb, 4, r, c1));
                float* o0 = o[4 * p];     float* o1 = o[4 * p + 1];
                float* o2 = o[4 * p + 2]; float* o3 = o[4 * p + 3];
                MMA_F16(o0, ph, v0, v1);  MMA_F16(o1, ph, v2, v3);
                MMA_F16(o2, ph, u0, u1);  MMA_F16(o3, ph, u2, u3);
                MMA_F16(o0, pl, v0, v1);  MMA_F16(o1, pl, v2, v3);
                MMA_F16(o2, pl, u0, u1);  MMA_F16(o3, pl, u2, u3);
            }
        }

        __syncthreads();
        if (jt < qt) {
            load_tile(4, Vh, (jt + 1) * 128);
            CP_COMMIT(); CP_WAIT(0); __syncthreads();
        }
    }

    float inv0 = 1.0f / l[0], inv1 = 1.0f / l[1];
    int row0 = q0 + qw + gid, row1 = row0 + 8;
#pragma unroll
    for (int nt = 0; nt < 16; nt++) {
        int col = nt * 8 + 2 * tig;
        uint32_t h0, l0, h1, l1;
        split_pack(o[nt][0] * inv0, o[nt][1] * inv0, h0, l0);
        split_pack(o[nt][2] * inv1, o[nt][3] * inv1, h1, l1);
        *reinterpret_cast<uint32_t*>(&C1[base + (size_t)row0 * GD + col]) = h0;
        *reinterpret_cast<uint32_t*>(&C2[base + (size_t)row0 * GD + col]) = l0;
        *reinterpret_cast<uint32_t*>(&C1[base + (size_t)row1 * GD + col]) = h1;
        *reinterpret_cast<uint32_t*>(&C2[base + (size_t)row1 * GD + col]) = l1;
    }
}

// ---------------------------------------------------------------------------
extern "C" void kernel_launch(void* const* d_in, const int* in_sizes, int n_in,
                              void* d_out, int out_size)
{
    const float* x  = (const float*)d_in[0];
    const float* Wq = (const float*)d_in[1];
    const float* Wk = (const float*)d_in[2];
    const float* Wv = (const float*)d_in[3];
    const float* Wo = (const float*)d_in[4];

    __half *x1, *x2, *c1, *c2, *qh, *ql, *kh, *kl, *vh, *vl;
    cudaGetSymbolAddress((void**)&x1, g_x1); cudaGetSymbolAddress((void**)&x2, g_x2);
    cudaGetSymbolAddress((void**)&c1, g_c1); cudaGetSymbolAddress((void**)&c2, g_c2);
    cudaGetSymbolAddress((void**)&qh, g_qh); cudaGetSymbolAddress((void**)&ql, g_ql);
    cudaGetSymbolAddress((void**)&kh, g_kh); cudaGetSymbolAddress((void**)&kl, g_kl);
    cudaGetSymbolAddress((void**)&vh, g_vh); cudaGetSymbolAddress((void**)&vl, g_vl);

    __half *wq1, *wq2, *wk1, *wk2, *wv1, *wv2, *wo1, *wo2;
    cudaGetSymbolAddress((void**)&wq1, g_wq1); cudaGetSymbolAddress((void**)&wq2, g_wq2);
    cudaGetSymbolAddress((void**)&wk1, g_wk1); cudaGetSymbolAddress((void**)&wk2, g_wk2);
    cudaGetSymbolAddress((void**)&wv1, g_wv1); cudaGetSymbolAddress((void**)&wv2, g_wv2);
    cudaGetSymbolAddress((void**)&wo1, g_wo1); cudaGetSymbolAddress((void**)&wo2, g_wo2);

    cudaFuncSetAttribute(hgemm_qkv, cudaFuncAttributeMaxDynamicSharedMemorySize, GEMM_SMEM);
    cudaFuncSetAttribute(hgemm_out, cudaFuncAttributeMaxDynamicSharedMemorySize, GEMM_SMEM);
    cudaFuncSetAttribute(flash_tc, cudaFuncAttributeMaxDynamicSharedMemorySize, FT_SMEM);

    split2<<<GM * GD / 1024, 256>>>(x, x1, x2);
    dim3 tgrid(GD / 32, GD / 32, 4), tblk(32, 8);
    tsplit4<<<tgrid, tblk>>>(Wq, Wk, Wv, Wo,
                             wq1, wq2, wk1, wk2, wv1, wv2, wo1, wo2);

    dim3 qkv_grid(GD / 128, GM / 128, 3);   // (16, 32, 3)
    hgemm_qkv<<<qkv_grid, 256, GEMM_SMEM>>>(x1, x2, wq1, wq2, wk1, wk2, wv1, wv2,
                                            qh, ql, kh, kl, vh, vl);

    flash_tc<<<dim3(SEQ / 128, NH, 2), 256, FT_SMEM>>>(qh, ql, kh, kl, vh, c1, c2);

    dim3 ggrid(GD / 128, GM / 128);
    hgemm_out<<<ggrid, 256, GEMM_SMEM>>>(c1, c2, wo1, wo2, (float*)d_out);
}

// round 8
// speedup vs baseline: 5.3589x; 1.4159x over previous
#include <cuda_runtime.h>
#include <cuda_fp16.h>
#include <math.h>
#include <stdint.h>

// Problem: b=2, s=2048, d=2048, H=16, Dh=128, window=2048 (never binds -> causal)
#define GM 4096
#define GD 2048
#define SEQ 2048
#define NH 16
#define DH 128

// ---------------- scratch (device globals; allocation forbidden) ----------------
__device__ __half g_x1[GM * GD], g_x2[GM * GD];
__device__ __half g_c1[GM * GD], g_c2[GM * GD];
__device__ __half g_qh[GM * GD], g_ql[GM * GD];
__device__ __half g_kh[GM * GD], g_kl[GM * GD];
__device__ __half g_vh[GM * GD];
__device__ __half g_wq[GD * GD], g_wk[GD * GD], g_wv[GD * GD], g_wo[GD * GD];

// ---------------- PTX helpers (compute_103-safe) ----------------
__device__ __forceinline__ uint32_t smem_u32(const void* p) {
    uint32_t a;
    asm("{ .reg .u64 t; cvta.to.shared.u64 t, %1; cvt.u32.u64 %0, t; }" : "=r"(a) : "l"(p));
    return a;
}
#define CP_ASYNC16(dst, src) \
    asm volatile("cp.async.cg.shared.global [%0], [%1], 16;" :: "r"(dst), "l"(src))
#define CP_COMMIT() asm volatile("cp.async.commit_group;" ::: "memory")
#define CP_WAIT(n)  asm volatile("cp.async.wait_group %0;" :: "n"(n) : "memory")

#define LDSM4(r0, r1, r2, r3, addr) \
    asm volatile("ldmatrix.sync.aligned.m8n8.x4.shared.b16 {%0,%1,%2,%3}, [%4];" \
                 : "=r"(r0), "=r"(r1), "=r"(r2), "=r"(r3) : "r"(addr))
#define LDSM4T(r0, r1, r2, r3, addr) \
    asm volatile("ldmatrix.sync.aligned.m8n8.x4.trans.shared.b16 {%0,%1,%2,%3}, [%4];" \
                 : "=r"(r0), "=r"(r1), "=r"(r2), "=r"(r3) : "r"(addr))

#define MMA_F16(d, a, b0, b1)                                               \
    asm volatile(                                                           \
        "mma.sync.aligned.m16n8k16.row.col.f32.f16.f16.f32 "                \
        "{%0,%1,%2,%3}, {%4,%5,%6,%7}, {%8,%9}, {%0,%1,%2,%3};"             \
        : "+f"(d[0]), "+f"(d[1]), "+f"(d[2]), "+f"(d[3])                    \
        : "r"(a[0]), "r"(a[1]), "r"(a[2]), "r"(a[3]), "r"(b0), "r"(b1))

__device__ __forceinline__ uint32_t pack_h2(__half a, __half b) {
    __half2 t = __halves2half2(a, b);
    return *reinterpret_cast<uint32_t*>(&t);
}
__device__ __forceinline__ void split_pack(float a, float b, uint32_t& hi, uint32_t& lo) {
    __half ha = __float2half_rn(a), hb = __float2half_rn(b);
    __half la = __float2half_rn(a - __half2float(ha));
    __half lb = __float2half_rn(b - __half2float(hb));
    hi = pack_h2(ha, hb); lo = pack_h2(la, lb);
}

// ---------------------------------------------------------------------------
// Prep kernels.
// ---------------------------------------------------------------------------
__global__ void split2(const float* __restrict__ in,
                       __half* __restrict__ o1, __half* __restrict__ o2)
{
    int i = blockIdx.x * blockDim.x + threadIdx.x;
    float4 v = reinterpret_cast<const float4*>(in)[i];
    float x[4] = {v.x, v.y, v.z, v.w};
    __half h[4], l[4];
#pragma unroll
    for (int j = 0; j < 4; j++) {
        h[j] = __float2half_rn(x[j]);
        l[j] = __float2half_rn(x[j] - __half2float(h[j]));
    }
    __half2* p1 = reinterpret_cast<__half2*>(o1) + 2 * i;
    __half2* p2 = reinterpret_cast<__half2*>(o2) + 2 * i;
    p1[0] = __halves2half2(h[0], h[1]); p1[1] = __halves2half2(h[2], h[3]);
    p2[0] = __halves2half2(l[0], l[1]); p2[1] = __halves2half2(l[2], l[3]);
}

// transpose + fp16 convert (hi only), all 4 weights in one launch
__global__ void tconv4(const float* __restrict__ W0, const float* __restrict__ W1,
                       const float* __restrict__ W2, const float* __restrict__ W3,
                       __half* __restrict__ a0, __half* __restrict__ a1,
                       __half* __restrict__ a2, __half* __restrict__ a3)
{
    const float* W = (blockIdx.z == 0) ? W0 : (blockIdx.z == 1) ? W1
                   : (blockIdx.z == 2) ? W2 : W3;
    __half* o = (blockIdx.z == 0) ? a0 : (blockIdx.z == 1) ? a1
              : (blockIdx.z == 2) ? a2 : a3;

    __shared__ float t[32][33];
    const int bx = blockIdx.x * 32;   // n
    const int by = blockIdx.y * 32;   // k
    const int tx = threadIdx.x, ty = threadIdx.y;
#pragma unroll
    for (int i = 0; i < 4; i++)
        t[ty + 8 * i][tx] = W[(size_t)(by + ty + 8 * i) * GD + bx + tx];
    __syncthreads();
#pragma unroll
    for (int i = 0; i < 4; i++)
        o[(size_t)(bx + ty + 8 * i) * GD + by + tx] = __float2half_rn(t[tx][ty + 8 * i]);
}

// ---------------------------------------------------------------------------
// GEMM: C = A @ B^T, A split (A1 hi + A2 lo), B plain fp16.
// Terms: A1*B + A2*B (2 MMAs per fragment). KT=64, tiles A1/A2/B (16KB each),
// 2-stage cp.async pipeline, 96KB smem -> 2 CTAs/SM.
// ---------------------------------------------------------------------------
#define KT 64
#define NCH (GD / KT)          // 32
#define TILE_B 16384           // 128 rows * 128 bytes
#define STAGE_B (3 * TILE_B)   // A1 + A2 + B = 48 KB
#define GEMM_SMEM (2 * STAGE_B)

__device__ __forceinline__ void gemm_body(
    const __half* __restrict__ A1, const __half* __restrict__ A2,
    const __half* __restrict__ B1,
    float* __restrict__ Cf, __half* __restrict__ O1, __half* __restrict__ O2,
    uint32_t sbase, int m0, int n0)
{
    const int tid  = threadIdx.x;
    const int lane = tid & 31;
    const int warp = tid >> 5;
    const int wm = (warp & 3) * 32;
    const int wn = (warp >> 2) * 64;

    const __half* src[3] = {A1, A2, B1};
    const int row0[3] = {m0, m0, n0};

    auto load_stage = [&](int ch, int s) {
        const int k0 = ch * KT;
        const uint32_t stage = sbase + s * STAGE_B;
#pragma unroll
        for (int t = 0; t < 3; t++) {
            const __half* g = src[t] + (size_t)row0[t] * GD + k0;
#pragma unroll
            for (int i = 0; i < 4; i++) {
                int idx = tid + i * 256;
                int r = idx >> 3, c = idx & 7;
                uint32_t dst = stage + t * TILE_B + r * 128 + ((c ^ (r & 7)) << 4);
                CP_ASYNC16(dst, g + (size_t)r * GD + c * 8);
            }
        }
        CP_COMMIT();
    };

    float acc[2][8][4];
#pragma unroll
    for (int mt = 0; mt < 2; mt++)
#pragma unroll
        for (int nt = 0; nt < 8; nt++)
#pragma unroll
            for (int r = 0; r < 4; r++) acc[mt][nt][r] = 0.0f;

    load_stage(0, 0);

    for (int ch = 0; ch < NCH; ch++) {
        const int s = ch & 1;
        if (ch + 1 < NCH) { load_stage(ch + 1, s ^ 1); CP_WAIT(1); }
        else              { CP_WAIT(0); }
        __syncthreads();

        const uint32_t stage = sbase + s * STAGE_B;
#pragma unroll
        for (int ks = 0; ks < 4; ks++) {
            const int chunk = 2 * ks + (lane >> 4);
            uint32_t a1[2][4], a2[2][4];
#pragma unroll
            for (int mt = 0; mt < 2; mt++) {
                int row = wm + mt * 16 + (lane & 15);
                uint32_t sw = (chunk ^ (row & 7)) << 4;
                LDSM4(a1[mt][0], a1[mt][1], a1[mt][2], a1[mt][3],
                      stage + row * 128 + sw);
                LDSM4(a2[mt][0], a2[mt][1], a2[mt][2], a2[mt][3],
                      stage + TILE_B + row * 128 + sw);
            }
            uint32_t b[8][2];
#pragma unroll
            for (int np = 0; np < 4; np++) {
                int row = wn + np * 16 + (lane & 15);
                uint32_t r0, r1, r2, r3;
                LDSM4(r0, r1, r2, r3,
                      stage + 2 * TILE_B + row * 128 + ((chunk ^ (row & 7)) << 4));
                b[2 * np][0] = r0; b[2 * np][1] = r2;
                b[2 * np + 1][0] = r1; b[2 * np + 1][1] = r3;
            }
            // term-major: same-accumulator reuse distance = 16 MMAs
#pragma unroll
            for (int mt = 0; mt < 2; mt++)
#pragma unroll
                for (int nt = 0; nt < 8; nt++)
                    MMA_F16(acc[mt][nt], a1[mt], b[nt][0], b[nt][1]);
#pragma unroll
            for (int mt = 0; mt < 2; mt++)
#pragma unroll
                for (int nt = 0; nt < 8; nt++)
                    MMA_F16(acc[mt][nt], a2[mt], b[nt][0], b[nt][1]);
        }
        __syncthreads();
    }

    const int gid = lane >> 2, tig = lane & 3;
#pragma unroll
    for (int mt = 0; mt < 2; mt++)
#pragma unroll
        for (int nt = 0; nt < 8; nt++) {
            int row = m0 + wm + mt * 16 + gid;
            int col = n0 + wn + nt * 8 + tig * 2;
            if (O1) {
                uint32_t h0, l0, h1, l1;
                split_pack(acc[mt][nt][0], acc[mt][nt][1], h0, l0);
                split_pack(acc[mt][nt][2], acc[mt][nt][3], h1, l1);
                *reinterpret_cast<uint32_t*>(&O1[(size_t)row * GD + col]) = h0;
                if (O2) *reinterpret_cast<uint32_t*>(&O2[(size_t)row * GD + col]) = l0;
                *reinterpret_cast<uint32_t*>(&O1[(size_t)(row + 8) * GD + col]) = h1;
                if (O2) *reinterpret_cast<uint32_t*>(&O2[(size_t)(row + 8) * GD + col]) = l1;
            } else {
                *reinterpret_cast<float2*>(&Cf[(size_t)row * GD + col]) =
                    make_float2(acc[mt][nt][0], acc[mt][nt][1]);
                *reinterpret_cast<float2*>(&Cf[(size_t)(row + 8) * GD + col]) =
                    make_float2(acc[mt][nt][2], acc[mt][nt][3]);
            }
        }
}

// Fused Q/K/V projection (z selects weight/output). V gets hi-only output.
__global__ __launch_bounds__(256, 2) void hgemm_qkv(
    const __half* __restrict__ x1, const __half* __restrict__ x2,
    const __half* __restrict__ wq, const __half* __restrict__ wk,
    const __half* __restrict__ wv,
    __half* __restrict__ qh, __half* __restrict__ ql,
    __half* __restrict__ kh, __half* __restrict__ kl,
    __half* __restrict__ vh)
{
    extern __shared__ char smem[];
    const int z = blockIdx.z;
    const __half* B1 = (z == 0) ? wq : (z == 1) ? wk : wv;
    __half* O1 = (z == 0) ? qh : (z == 1) ? kh : vh;
    __half* O2 = (z == 0) ? ql : (z == 1) ? kl : nullptr;
    gemm_body(x1, x2, B1, nullptr, O1, O2,
              smem_u32(smem), blockIdx.y * 128, blockIdx.x * 128);
}

__global__ __launch_bounds__(256, 2) void hgemm_out(
    const __half* __restrict__ c1, const __half* __restrict__ c2,
    const __half* __restrict__ wo, float* __restrict__ Cf)
{
    extern __shared__ char smem[];
    gemm_body(c1, c2, wo, Cf, nullptr, nullptr,
              smem_u32(smem), blockIdx.y * 128, blockIdx.x * 128);
}

// ---------------------------------------------------------------------------
// Tensor-core causal flash attention (round-6/7 proven, unchanged).
// ---------------------------------------------------------------------------
#define FT_TILE 32768
#define FT_SMEM (5 * FT_TILE)
#define SM_SCALE 0.08838834764831845f

__device__ __forceinline__ uint32_t ft_addr(uint32_t sb, int tile, int r, int c) {
    return sb + tile * FT_TILE + r * 256 + (((c & 8) | ((c ^ (r & 7)) & 7)) << 4);
}

__global__ __launch_bounds__(256, 1) void flash_tc(
    const __half* __restrict__ Qh, const __half* __restrict__ Ql,
    const __half* __restrict__ Kh, const __half* __restrict__ Kl,
    const __half* __restrict__ Vh,
    __half* __restrict__ C1, __half* __restrict__ C2)
{
    extern __shared__ char smem[];
    const uint32_t sb = smem_u32(smem);

    const int tid = threadIdx.x, lane = tid & 31, warp = tid >> 5;
    const int qt = blockIdx.x, h = blockIdx.y, b = blockIdx.z;
    const int q0 = qt * 128;
    const size_t base = ((size_t)b * SEQ) * GD + (size_t)h * DH;

    auto load_tile = [&](int t, const __half* src, int r0) {
        const __half* g = src + base + (size_t)r0 * GD;
#pragma unroll
        for (int i = 0; i < 8; i++) {
            int idx = tid + i * 256;
            int r = idx >> 4, c = idx & 15;
            CP_ASYNC16(ft_addr(sb, t, r, c), g + (size_t)r * GD + c * 8);
        }
    };

    load_tile(0, Qh, q0); load_tile(1, Ql, q0);
    load_tile(2, Kh, 0);  load_tile(3, Kl, 0);
    load_tile(4, Vh, 0);
    CP_COMMIT(); CP_WAIT(0); __syncthreads();

    const int gid = lane >> 2, tig = lane & 3;
    const int qw = warp * 16;

    float o[16][4];
#pragma unroll
    for (int nt = 0; nt < 16; nt++)
#pragma unroll
        for (int c = 0; c < 4; c++) o[nt][c] = 0.0f;
    float m[2] = {-1e30f, -1e30f}, l[2] = {0.0f, 0.0f};

    for (int jt = 0; jt <= qt; jt++) {
        float s[16][4];
#pragma unroll
        for (int nt = 0; nt < 16; nt++)
#pragma unroll
            for (int c = 0; c < 4; c++) s[nt][c] = 0.0f;

#pragma unroll
        for (int kf = 0; kf < 8; kf++) {
            const int ac = 2 * kf + (lane >> 4);
            uint32_t ah[4], al[4];
            {
                int r = qw + (lane & 15);
                LDSM4(ah[0], ah[1], ah[2], ah[3], ft_addr(sb, 0, r, ac));
                LDSM4(al[0], al[1], al[2], al[3], ft_addr(sb, 1, r, ac));
            }
#pragma unroll
            for (int p = 0; p < 4; p++) {
                int r0 = (2 * p) * 16 + (lane & 15);
                int r1 = (2 * p + 1) * 16 + (lane & 15);
                uint32_t h0, h1, h2, h3, l0, l1, l2, l3;
                uint32_t i0, i1, i2, i3, m0r, m1r, m2r, m3r;
                LDSM4(h0, h1, h2, h3, ft_addr(sb, 2, r0, ac));
                LDSM4(l0, l1, l2, l3, ft_addr(sb, 3, r0, ac));
                LDSM4(i0, i1, i2, i3, ft_addr(sb, 2, r1, ac));
                LDSM4(m0r, m1r, m2r, m3r, ft_addr(sb, 3, r1, ac));
                float* s0 = s[4 * p];     float* s1 = s[4 * p + 1];
                float* s2 = s[4 * p + 2]; float* s3 = s[4 * p + 3];
                MMA_F16(s0, ah, h0, h2);  MMA_F16(s1, ah, h1, h3);
                MMA_F16(s2, ah, i0, i2);  MMA_F16(s3, ah, i1, i3);
                MMA_F16(s0, ah, l0, l2);  MMA_F16(s1, ah, l1, l3);
                MMA_F16(s2, ah, m0r, m2r); MMA_F16(s3, ah, m1r, m3r);
                MMA_F16(s0, al, h0, h2);  MMA_F16(s1, al, h1, h3);
                MMA_F16(s2, al, i0, i2);  MMA_F16(s3, al, i1, i3);
            }
        }

        if (jt == qt) {
#pragma unroll
            for (int nt = 0; nt < 16; nt++) {
                int colb = jt * 128 + nt * 8 + 2 * tig;
#pragma unroll
                for (int c = 0; c < 4; c++) {
                    int row = q0 + qw + gid + ((c >= 2) ? 8 : 0);
                    int col = colb + (c & 1);
                    s[nt][c] = (col > row) ? -1e30f : s[nt][c] * SM_SCALE;
                }
            }
        } else {
#pragma unroll
            for (int nt = 0; nt < 16; nt++)
#pragma unroll
                for (int c = 0; c < 4; c++) s[nt][c] *= SM_SCALE;
        }

        float mx0 = -1e30f, mx1 = -1e30f;
#pragma unroll
        for (int nt = 0; nt < 16; nt++) {
            mx0 = fmaxf(mx0, fmaxf(s[nt][0], s[nt][1]));
            mx1 = fmaxf(mx1, fmaxf(s[nt][2], s[nt][3]));
        }
#pragma unroll
        for (int off = 1; off <= 2; off <<= 1) {
            mx0 = fmaxf(mx0, __shfl_xor_sync(0xffffffffu, mx0, off, 4));
            mx1 = fmaxf(mx1, __shfl_xor_sync(0xffffffffu, mx1, off, 4));
        }
        float mn0 = fmaxf(m[0], mx0), mn1 = fmaxf(m[1], mx1);
        float cr0 = __expf(m[0] - mn0), cr1 = __expf(m[1] - mn1);
        m[0] = mn0; m[1] = mn1;
        float sum0 = 0.0f, sum1 = 0.0f;
#pragma unroll
        for (int nt = 0; nt < 16; nt++) {
            s[nt][0] = __expf(s[nt][0] - mn0); sum0 += s[nt][0];
            s[nt][1] = __expf(s[nt][1] - mn0); sum0 += s[nt][1];
            s[nt][2] = __expf(s[nt][2] - mn1); sum1 += s[nt][2];
            s[nt][3] = __expf(s[nt][3] - mn1); sum1 += s[nt][3];
        }
#pragma unroll
        for (int off = 1; off <= 2; off <<= 1) {
            sum0 += __shfl_xor_sync(0xffffffffu, sum0, off, 4);
            sum1 += __shfl_xor_sync(0xffffffffu, sum1, off, 4);
        }
        l[0] = l[0] * cr0 + sum0;
        l[1] = l[1] * cr1 + sum1;
#pragma unroll
        for (int nt = 0; nt < 16; nt++) {
            o[nt][0] *= cr0; o[nt][1] *= cr0;
            o[nt][2] *= cr1; o[nt][3] *= cr1;
        }

        __syncthreads();
        if (jt < qt) {
            load_tile(2, Kh, (jt + 1) * 128);
            load_tile(3, Kl, (jt + 1) * 128);
            CP_COMMIT();
        }

#pragma unroll
        for (int kf = 0; kf < 8; kf++) {
            uint32_t ph[4], pl[4];
            split_pack(s[2 * kf][0],     s[2 * kf][1],     ph[0], pl[0]);
            split_pack(s[2 * kf][2],     s[2 * kf][3],     ph[1], pl[1]);
            split_pack(s[2 * kf + 1][0], s[2 * kf + 1][1], ph[2], pl[2]);
            split_pack(s[2 * kf + 1][2], s[2 * kf + 1][3], ph[3], pl[3]);
            int r = kf * 16 + (lane & 15);
#pragma unroll
            for (int p = 0; p < 4; p++) {
                int c0 = 2 * (2 * p) + (lane >> 4);
                int c1 = 2 * (2 * p + 1) + (lane >> 4);
                uint32_t v0, v1, v2, v3, u0, u1, u2, u3;
                LDSM4T(v0, v1, v2, v3, ft_addr(sb, 4, r, c0));
                LDSM4T(u0, u1, u2, u3, ft_addr(sb, 4, r, c1));
                float* o0 = o[4 * p];     float* o1 = o[4 * p + 1];
                float* o2 = o[4 * p + 2]; float* o3 = o[4 * p + 3];
                MMA_F16(o0, ph, v0, v1);  MMA_F16(o1, ph, v2, v3);
                MMA_F16(o2, ph, u0, u1);  MMA_F16(o3, ph, u2, u3);
                MMA_F16(o0, pl, v0, v1);  MMA_F16(o1, pl, v2, v3);
                MMA_F16(o2, pl, u0, u1);  MMA_F16(o3, pl, u2, u3);
            }
        }

        __syncthreads();
        if (jt < qt) {
            load_tile(4, Vh, (jt + 1) * 128);
            CP_COMMIT(); CP_WAIT(0); __syncthreads();
        }
    }

    float inv0 = 1.0f / l[0], inv1 = 1.0f / l[1];
    int row0 = q0 + qw + gid, row1 = row0 + 8;
#pragma unroll
    for (int nt = 0; nt < 16; nt++) {
        int col = nt * 8 + 2 * tig;
        uint32_t h0, l0, h1, l1;
        split_pack(o[nt][0] * inv0, o[nt][1] * inv0, h0, l0);
        split_pack(o[nt][2] * inv1, o[nt][3] * inv1, h1, l1);
        *reinterpret_cast<uint32_t*>(&C1[base + (size_t)row0 * GD + col]) = h0;
        *reinterpret_cast<uint32_t*>(&C2[base + (size_t)row0 * GD + col]) = l0;
        *reinterpret_cast<uint32_t*>(&C1[base + (size_t)row1 * GD + col]) = h1;
        *reinterpret_cast<uint32_t*>(&C2[base + (size_t)row1 * GD + col]) = l1;
    }
}

// ---------------------------------------------------------------------------
extern "C" void kernel_launch(void* const* d_in, const int* in_sizes, int n_in,
                              void* d_out, int out_size)
{
    const float* x  = (const float*)d_in[0];
    const float* Wq = (const float*)d_in[1];
    const float* Wk = (const float*)d_in[2];
    const float* Wv = (const float*)d_in[3];
    const float* Wo = (const float*)d_in[4];

    __half *x1, *x2, *c1, *c2, *qh, *ql, *kh, *kl, *vh;
    cudaGetSymbolAddress((void**)&x1, g_x1); cudaGetSymbolAddress((void**)&x2, g_x2);
    cudaGetSymbolAddress((void**)&c1, g_c1); cudaGetSymbolAddress((void**)&c2, g_c2);
    cudaGetSymbolAddress((void**)&qh, g_qh); cudaGetSymbolAddress((void**)&ql, g_ql);
    cudaGetSymbolAddress((void**)&kh, g_kh); cudaGetSymbolAddress((void**)&kl, g_kl);
    cudaGetSymbolAddress((void**)&vh, g_vh);

    __half *wq, *wk, *wv, *wo;
    cudaGetSymbolAddress((void**)&wq, g_wq); cudaGetSymbolAddress((void**)&wk, g_wk);
    cudaGetSymbolAddress((void**)&wv, g_wv); cudaGetSymbolAddress((void**)&wo, g_wo);

    cudaFuncSetAttribute(hgemm_qkv, cudaFuncAttributeMaxDynamicSharedMemorySize, GEMM_SMEM);
    cudaFuncSetAttribute(hgemm_out, cudaFuncAttributeMaxDynamicSharedMemorySize, GEMM_SMEM);
    cudaFuncSetAttribute(flash_tc, cudaFuncAttributeMaxDynamicSharedMemorySize, FT_SMEM);

    split2<<<GM * GD / 1024, 256>>>(x, x1, x2);
    dim3 tgrid(GD / 32, GD / 32, 4), tblk(32, 8);
    tconv4<<<tgrid, tblk>>>(Wq, Wk, Wv, Wo, wq, wk, wv, wo);

    dim3 qkv_grid(GD / 128, GM / 128, 3);
    hgemm_qkv<<<qkv_grid, 256, GEMM_SMEM>>>(x1, x2, wq, wk, wv,
                                            qh, ql, kh, kl, vh);

    flash_tc<<<dim3(SEQ / 128, NH, 2), 256, FT_SMEM>>>(qh, ql, kh, kl, vh, c1, c2);

    dim3 ggrid(GD / 128, GM / 128);
    hgemm_out<<<ggrid, 256, GEMM_SMEM>>>(c1, c2, wo, (float*)d_out);
}

// round 9
// speedup vs baseline: 6.0684x; 1.1324x over previous
#include <cuda_runtime.h>
#include <cuda_fp16.h>
#include <math.h>
#include <stdint.h>

// Problem: b=2, s=2048, d=2048, H=16, Dh=128, window=2048 (never binds -> causal)
#define GM 4096
#define GD 2048
#define SEQ 2048
#define NH 16
#define DH 128

// Q is pre-scaled by SM_SCALE*log2(e); softmax runs in exp2 domain.
#define QSCALE (0.08838834764831845f * 1.4426950408889634f)

// ---------------- scratch (device globals; allocation forbidden) ----------------
__device__ __half g_x1[GM * GD], g_x2[GM * GD];
__device__ __half g_c1[GM * GD], g_c2[GM * GD];
__device__ __half g_qh[GM * GD], g_ql[GM * GD];
__device__ __half g_kh[GM * GD];
__device__ __half g_vh[GM * GD];
__device__ __half g_wq[GD * GD], g_wk[GD * GD], g_wv[GD * GD], g_wo[GD * GD];

// ---------------- PTX helpers (compute_103-safe) ----------------
__device__ __forceinline__ uint32_t smem_u32(const void* p) {
    uint32_t a;
    asm("{ .reg .u64 t; cvta.to.shared.u64 t, %1; cvt.u32.u64 %0, t; }" : "=r"(a) : "l"(p));
    return a;
}
#define CP_ASYNC16(dst, src) \
    asm volatile("cp.async.cg.shared.global [%0], [%1], 16;" :: "r"(dst), "l"(src))
#define CP_COMMIT() asm volatile("cp.async.commit_group;" ::: "memory")
#define CP_WAIT(n)  asm volatile("cp.async.wait_group %0;" :: "n"(n) : "memory")

#define LDSM4(r0, r1, r2, r3, addr) \
    asm volatile("ldmatrix.sync.aligned.m8n8.x4.shared.b16 {%0,%1,%2,%3}, [%4];" \
                 : "=r"(r0), "=r"(r1), "=r"(r2), "=r"(r3) : "r"(addr))
#define LDSM4T(r0, r1, r2, r3, addr) \
    asm volatile("ldmatrix.sync.aligned.m8n8.x4.trans.shared.b16 {%0,%1,%2,%3}, [%4];" \
                 : "=r"(r0), "=r"(r1), "=r"(r2), "=r"(r3) : "r"(addr))

#define MMA_F16(d, a, b0, b1)                                               \
    asm volatile(                                                           \
        "mma.sync.aligned.m16n8k16.row.col.f32.f16.f16.f32 "                \
        "{%0,%1,%2,%3}, {%4,%5,%6,%7}, {%8,%9}, {%0,%1,%2,%3};"             \
        : "+f"(d[0]), "+f"(d[1]), "+f"(d[2]), "+f"(d[3])                    \
        : "r"(a[0]), "r"(a[1]), "r"(a[2]), "r"(a[3]), "r"(b0), "r"(b1))

__device__ __forceinline__ uint32_t pack_h2(__half a, __half b) {
    __half2 t = __halves2half2(a, b);
    return *reinterpret_cast<uint32_t*>(&t);
}
__device__ __forceinline__ void split_pack(float a, float b, uint32_t& hi, uint32_t& lo) {
    __half ha = __float2half_rn(a), hb = __float2half_rn(b);
    __half la = __float2half_rn(a - __half2float(ha));
    __half lb = __float2half_rn(b - __half2float(hb));
    hi = pack_h2(ha, hb); lo = pack_h2(la, lb);
}

// ---------------------------------------------------------------------------
// Prep kernels.
// ---------------------------------------------------------------------------
__global__ void split2(const float* __restrict__ in,
                       __half* __restrict__ o1, __half* __restrict__ o2)
{
    int i = blockIdx.x * blockDim.x + threadIdx.x;
    float4 v = reinterpret_cast<const float4*>(in)[i];
    float x[4] = {v.x, v.y, v.z, v.w};
    __half h[4], l[4];
#pragma unroll
    for (int j = 0; j < 4; j++) {
        h[j] = __float2half_rn(x[j]);
        l[j] = __float2half_rn(x[j] - __half2float(h[j]));
    }
    __half2* p1 = reinterpret_cast<__half2*>(o1) + 2 * i;
    __half2* p2 = reinterpret_cast<__half2*>(o2) + 2 * i;
    p1[0] = __halves2half2(h[0], h[1]); p1[1] = __halves2half2(h[2], h[3]);
    p2[0] = __halves2half2(l[0], l[1]); p2[1] = __halves2half2(l[2], l[3]);
}

__global__ void tconv4(const float* __restrict__ W0, const float* __restrict__ W1,
                       const float* __restrict__ W2, const float* __restrict__ W3,
                       __half* __restrict__ a0, __half* __restrict__ a1,
                       __half* __restrict__ a2, __half* __restrict__ a3)
{
    const float* W = (blockIdx.z == 0) ? W0 : (blockIdx.z == 1) ? W1
                   : (blockIdx.z == 2) ? W2 : W3;
    __half* o = (blockIdx.z == 0) ? a0 : (blockIdx.z == 1) ? a1
              : (blockIdx.z == 2) ? a2 : a3;

    __shared__ float t[32][33];
    const int bx = blockIdx.x * 32;
    const int by = blockIdx.y * 32;
    const int tx = threadIdx.x, ty = threadIdx.y;
#pragma unroll
    for (int i = 0; i < 4; i++)
        t[ty + 8 * i][tx] = W[(size_t)(by + ty + 8 * i) * GD + bx + tx];
    __syncthreads();
#pragma unroll
    for (int i = 0; i < 4; i++)
        o[(size_t)(bx + ty + 8 * i) * GD + by + tx] = __float2half_rn(t[tx][ty + 8 * i]);
}

// ---------------------------------------------------------------------------
// GEMM: C = A @ B^T, A split (hi+lo), B plain fp16. 2 CTAs/SM.
// Split outputs are scaled by `oscale` (used to fold softmax scale into Q).
// ---------------------------------------------------------------------------
#define KT 64
#define NCH (GD / KT)
#define TILE_B 16384
#define STAGE_B (3 * TILE_B)
#define GEMM_SMEM (2 * STAGE_B)

__device__ __forceinline__ void gemm_body(
    const __half* __restrict__ A1, const __half* __restrict__ A2,
    const __half* __restrict__ B1,
    float* __restrict__ Cf, __half* __restrict__ O1, __half* __restrict__ O2,
    float oscale, uint32_t sbase, int m0, int n0)
{
    const int tid  = threadIdx.x;
    const int lane = tid & 31;
    const int warp = tid >> 5;
    const int wm = (warp & 3) * 32;
    const int wn = (warp >> 2) * 64;

    const __half* src[3] = {A1, A2, B1};
    const int row0[3] = {m0, m0, n0};

    auto load_stage = [&](int ch, int s) {
        const int k0 = ch * KT;
        const uint32_t stage = sbase + s * STAGE_B;
#pragma unroll
        for (int t = 0; t < 3; t++) {
            const __half* g = src[t] + (size_t)row0[t] * GD + k0;
#pragma unroll
            for (int i = 0; i < 4; i++) {
                int idx = tid + i * 256;
                int r = idx >> 3, c = idx & 7;
                uint32_t dst = stage + t * TILE_B + r * 128 + ((c ^ (r & 7)) << 4);
                CP_ASYNC16(dst, g + (size_t)r * GD + c * 8);
            }
        }
        CP_COMMIT();
    };

    float acc[2][8][4];
#pragma unroll
    for (int mt = 0; mt < 2; mt++)
#pragma unroll
        for (int nt = 0; nt < 8; nt++)
#pragma unroll
            for (int r = 0; r < 4; r++) acc[mt][nt][r] = 0.0f;

    load_stage(0, 0);

    for (int ch = 0; ch < NCH; ch++) {
        const int s = ch & 1;
        if (ch + 1 < NCH) { load_stage(ch + 1, s ^ 1); CP_WAIT(1); }
        else              { CP_WAIT(0); }
        __syncthreads();

        const uint32_t stage = sbase + s * STAGE_B;
#pragma unroll
        for (int ks = 0; ks < 4; ks++) {
            const int chunk = 2 * ks + (lane >> 4);
            uint32_t a1[2][4], a2[2][4];
#pragma unroll
            for (int mt = 0; mt < 2; mt++) {
                int row = wm + mt * 16 + (lane & 15);
                uint32_t sw = (chunk ^ (row & 7)) << 4;
                LDSM4(a1[mt][0], a1[mt][1], a1[mt][2], a1[mt][3],
                      stage + row * 128 + sw);
                LDSM4(a2[mt][0], a2[mt][1], a2[mt][2], a2[mt][3],
                      stage + TILE_B + row * 128 + sw);
            }
            uint32_t b[8][2];
#pragma unroll
            for (int np = 0; np < 4; np++) {
                int row = wn + np * 16 + (lane & 15);
                uint32_t r0, r1, r2, r3;
                LDSM4(r0, r1, r2, r3,
                      stage + 2 * TILE_B + row * 128 + ((chunk ^ (row & 7)) << 4));
                b[2 * np][0] = r0; b[2 * np][1] = r2;
                b[2 * np + 1][0] = r1; b[2 * np + 1][1] = r3;
            }
#pragma unroll
            for (int mt = 0; mt < 2; mt++)
#pragma unroll
                for (int nt = 0; nt < 8; nt++)
                    MMA_F16(acc[mt][nt], a1[mt], b[nt][0], b[nt][1]);
#pragma unroll
            for (int mt = 0; mt < 2; mt++)
#pragma unroll
                for (int nt = 0; nt < 8; nt++)
                    MMA_F16(acc[mt][nt], a2[mt], b[nt][0], b[nt][1]);
        }
        __syncthreads();
    }

    const int gid = lane >> 2, tig = lane & 3;
#pragma unroll
    for (int mt = 0; mt < 2; mt++)
#pragma unroll
        for (int nt = 0; nt < 8; nt++) {
            int row = m0 + wm + mt * 16 + gid;
            int col = n0 + wn + nt * 8 + tig * 2;
            if (O1) {
                uint32_t h0, l0, h1, l1;
                split_pack(acc[mt][nt][0] * oscale, acc[mt][nt][1] * oscale, h0, l0);
                split_pack(acc[mt][nt][2] * oscale, acc[mt][nt][3] * oscale, h1, l1);
                *reinterpret_cast<uint32_t*>(&O1[(size_t)row * GD + col]) = h0;
                if (O2) *reinterpret_cast<uint32_t*>(&O2[(size_t)row * GD + col]) = l0;
                *reinterpret_cast<uint32_t*>(&O1[(size_t)(row + 8) * GD + col]) = h1;
                if (O2) *reinterpret_cast<uint32_t*>(&O2[(size_t)(row + 8) * GD + col]) = l1;
            } else {
                *reinterpret_cast<float2*>(&Cf[(size_t)row * GD + col]) =
                    make_float2(acc[mt][nt][0], acc[mt][nt][1]);
                *reinterpret_cast<float2*>(&Cf[(size_t)(row + 8) * GD + col]) =
                    make_float2(acc[mt][nt][2], acc[mt][nt][3]);
            }
        }
}

// Fused Q/K/V projection. Q output pre-scaled by QSCALE; K/V hi-only.
__global__ __launch_bounds__(256, 2) void hgemm_qkv(
    const __half* __restrict__ x1, const __half* __restrict__ x2,
    const __half* __restrict__ wq, const __half* __restrict__ wk,
    const __half* __restrict__ wv,
    __half* __restrict__ qh, __half* __restrict__ ql,
    __half* __restrict__ kh, __half* __restrict__ vh)
{
    extern __shared__ char smem[];
    const int z = blockIdx.z;
    const __half* B1 = (z == 0) ? wq : (z == 1) ? wk : wv;
    __half* O1 = (z == 0) ? qh : (z == 1) ? kh : vh;
    __half* O2 = (z == 0) ? ql : nullptr;
    float oscale = (z == 0) ? QSCALE : 1.0f;
    gemm_body(x1, x2, B1, nullptr, O1, O2, oscale,
              smem_u32(smem), blockIdx.y * 128, blockIdx.x * 128);
}

__global__ __launch_bounds__(256, 2) void hgemm_out(
    const __half* __restrict__ c1, const __half* __restrict__ c2,
    const __half* __restrict__ wo, float* __restrict__ Cf)
{
    extern __shared__ char smem[];
    gemm_body(c1, c2, wo, Cf, nullptr, nullptr, 1.0f,
              smem_u32(smem), blockIdx.y * 128, blockIdx.x * 128);
}

// ---------------------------------------------------------------------------
// Flash attention v2: exp2-domain softmax (scale folded into Q), K/V/P fp16
// (hi only; Q keeps hi+lo), double-buffered K/V (one sync per k-tile),
// heavy q-tiles scheduled first.
// smem tiles (32KB): 0 Qh, 1 Ql, 2 Kh[0], 3 Kh[1], 4 Vh[0], 5 Vh[1] = 192KB.
// ---------------------------------------------------------------------------
#define FT_TILE 32768
#define FT_SMEM (6 * FT_TILE)

__device__ __forceinline__ uint32_t ft_addr(uint32_t sb, int tile, int r, int c) {
    return sb + tile * FT_TILE + r * 256 + (((c & 8) | ((c ^ (r & 7)) & 7)) << 4);
}

__global__ __launch_bounds__(256, 1) void flash_tc(
    const __half* __restrict__ Qh, const __half* __restrict__ Ql,
    const __half* __restrict__ Kh, const __half* __restrict__ Vh,
    __half* __restrict__ C1, __half* __restrict__ C2)
{
    extern __shared__ char smem[];
    const uint32_t sb = smem_u32(smem);

    const int tid = threadIdx.x, lane = tid & 31, warp = tid >> 5;
    const int qt = gridDim.x - 1 - blockIdx.x;   // heavy tiles first
    const int h = blockIdx.y, b = blockIdx.z;
    const int q0 = qt * 128;
    const size_t base = ((size_t)b * SEQ) * GD + (size_t)h * DH;

    auto load_tile = [&](int t, const __half* src, int r0) {
        const __half* g = src + base + (size_t)r0 * GD;
#pragma unroll
        for (int i = 0; i < 8; i++) {
            int idx = tid + i * 256;
            int r = idx >> 4, c = idx & 15;
            CP_ASYNC16(ft_addr(sb, t, r, c), g + (size_t)r * GD + c * 8);
        }
    };

    load_tile(0, Qh, q0); load_tile(1, Ql, q0);
    load_tile(2, Kh, 0);  load_tile(4, Vh, 0);
    CP_COMMIT(); CP_WAIT(0); __syncthreads();

    const int gid = lane >> 2, tig = lane & 3;
    const int qw = warp * 16;

    float o[16][4];
#pragma unroll
    for (int nt = 0; nt < 16; nt++)
#pragma unroll
        for (int c = 0; c < 4; c++) o[nt][c] = 0.0f;
    float m[2] = {-1e30f, -1e30f}, l[2] = {0.0f, 0.0f};

    for (int jt = 0; jt <= qt; jt++) {
        const int cur = jt & 1, nxt = cur ^ 1;

        // ---- S = Q @ K^T (2 terms: Q hi/lo x K hi) ----
        float s[16][4];
#pragma unroll
        for (int nt = 0; nt < 16; nt++)
#pragma unroll
            for (int c = 0; c < 4; c++) s[nt][c] = 0.0f;

#pragma unroll
        for (int kf = 0; kf < 8; kf++) {
            const int ac = 2 * kf + (lane >> 4);
            uint32_t ah[4], al[4];
            {
                int r = qw + (lane & 15);
                LDSM4(ah[0], ah[1], ah[2], ah[3], ft_addr(sb, 0, r, ac));
                LDSM4(al[0], al[1], al[2], al[3], ft_addr(sb, 1, r, ac));
            }
#pragma unroll
            for (int p = 0; p < 4; p++) {
                int r0 = (2 * p) * 16 + (lane & 15);
                int r1 = (2 * p + 1) * 16 + (lane & 15);
                uint32_t h0, h1, h2, h3, i0, i1, i2, i3;
                LDSM4(h0, h1, h2, h3, ft_addr(sb, 2 + cur, r0, ac));
                LDSM4(i0, i1, i2, i3, ft_addr(sb, 2 + cur, r1, ac));
                float* s0 = s[4 * p];     float* s1 = s[4 * p + 1];
                float* s2 = s[4 * p + 2]; float* s3 = s[4 * p + 3];
                MMA_F16(s0, ah, h0, h2);  MMA_F16(s1, ah, h1, h3);
                MMA_F16(s2, ah, i0, i2);  MMA_F16(s3, ah, i1, i3);
                MMA_F16(s0, al, h0, h2);  MMA_F16(s1, al, h1, h3);
                MMA_F16(s2, al, i0, i2);  MMA_F16(s3, al, i1, i3);
            }
        }

        // ---- causal mask (diag tile only; no scale mul — folded into Q) ----
        if (jt == qt) {
#pragma unroll
            for (int nt = 0; nt < 16; nt++) {
                int colb = jt * 128 + nt * 8 + 2 * tig;
#pragma unroll
                for (int c = 0; c < 4; c++) {
                    int row = q0 + qw + gid + ((c >= 2) ? 8 : 0);
                    int col = colb + (c & 1);
                    if (col > row) s[nt][c] = -1e30f;
                }
            }
        }

        // ---- online softmax in exp2 domain ----
        float mx0 = -1e30f, mx1 = -1e30f;
#pragma unroll
        for (int nt = 0; nt < 16; nt++) {
            mx0 = fmaxf(mx0, fmaxf(s[nt][0], s[nt][1]));
            mx1 = fmaxf(mx1, fmaxf(s[nt][2], s[nt][3]));
        }
#pragma unroll
        for (int off = 1; off <= 2; off <<= 1) {
            mx0 = fmaxf(mx0, __shfl_xor_sync(0xffffffffu, mx0, off, 4));
            mx1 = fmaxf(mx1, __shfl_xor_sync(0xffffffffu, mx1, off, 4));
        }
        float mn0 = fmaxf(m[0], mx0), mn1 = fmaxf(m[1], mx1);
        float cr0 = exp2f(m[0] - mn0), cr1 = exp2f(m[1] - mn1);
        m[0] = mn0; m[1] = mn1;
        float sum0 = 0.0f, sum1 = 0.0f;
#pragma unroll
        for (int nt = 0; nt < 16; nt++) {
            s[nt][0] = exp2f(s[nt][0] - mn0); sum0 += s[nt][0];
            s[nt][1] = exp2f(s[nt][1] - mn0); sum0 += s[nt][1];
            s[nt][2] = exp2f(s[nt][2] - mn1); sum1 += s[nt][2];
            s[nt][3] = exp2f(s[nt][3] - mn1); sum1 += s[nt][3];
        }
#pragma unroll
        for (int off = 1; off <= 2; off <<= 1) {
            sum0 += __shfl_xor_sync(0xffffffffu, sum0, off, 4);
            sum1 += __shfl_xor_sync(0xffffffffu, sum1, off, 4);
        }
        l[0] = l[0] * cr0 + sum0;
        l[1] = l[1] * cr1 + sum1;
#pragma unroll
        for (int nt = 0; nt < 16; nt++) {
            o[nt][0] *= cr0; o[nt][1] *= cr0;
            o[nt][2] *= cr1; o[nt][3] *= cr1;
        }

        // prefetch next K/V into the other buffer (no sync needed: disjoint)
        if (jt < qt) {
            load_tile(2 + nxt, Kh, (jt + 1) * 128);
            load_tile(4 + nxt, Vh, (jt + 1) * 128);
            CP_COMMIT();
        }

        // ---- O += P @ V (P hi only) ----
#pragma unroll
        for (int kf = 0; kf < 8; kf++) {
            uint32_t ph[4];
            ph[0] = pack_h2(__float2half_rn(s[2 * kf][0]),     __float2half_rn(s[2 * kf][1]));
            ph[1] = pack_h2(__float2half_rn(s[2 * kf][2]),     __float2half_rn(s[2 * kf][3]));
            ph[2] = pack_h2(__float2half_rn(s[2 * kf + 1][0]), __float2half_rn(s[2 * kf + 1][1]));
            ph[3] = pack_h2(__float2half_rn(s[2 * kf + 1][2]), __float2half_rn(s[2 * kf + 1][3]));
            int r = kf * 16 + (lane & 15);
#pragma unroll
            for (int p = 0; p < 4; p++) {
                int c0 = 4 * p + (lane >> 4);
                int c1 = 4 * p + 2 + (lane >> 4);
                uint32_t v0, v1, v2, v3, u0, u1, u2, u3;
                LDSM4T(v0, v1, v2, v3, ft_addr(sb, 4 + cur, r, c0));
                LDSM4T(u0, u1, u2, u3, ft_addr(sb, 4 + cur, r, c1));
                MMA_F16(o[4 * p],     ph, v0, v1);
                MMA_F16(o[4 * p + 1], ph, v2, v3);
                MMA_F16(o[4 * p + 2], ph, u0, u1);
                MMA_F16(o[4 * p + 3], ph, u2, u3);
            }
        }

        if (jt < qt) { CP_WAIT(0); __syncthreads(); }   // one sync per k-tile
    }

    // ---- epilogue: normalize + fused hi/lo split store ----
    float inv0 = 1.0f / l[0], inv1 = 1.0f / l[1];
    int row0 = q0 + qw + gid, row1 = row0 + 8;
#pragma unroll
    for (int nt = 0; nt < 16; nt++) {
        int col = nt * 8 + 2 * tig;
        uint32_t h0, l0, h1, l1;
        split_pack(o[nt][0] * inv0, o[nt][1] * inv0, h0, l0);
        split_pack(o[nt][2] * inv1, o[nt][3] * inv1, h1, l1);
        *reinterpret_cast<uint32_t*>(&C1[base + (size_t)row0 * GD + col]) = h0;
        *reinterpret_cast<uint32_t*>(&C2[base + (size_t)row0 * GD + col]) = l0;
        *reinterpret_cast<uint32_t*>(&C1[base + (size_t)row1 * GD + col]) = h1;
        *reinterpret_cast<uint32_t*>(&C2[base + (size_t)row1 * GD + col]) = l1;
    }
}

// ---------------------------------------------------------------------------
extern "C" void kernel_launch(void* const* d_in, const int* in_sizes, int n_in,
                              void* d_out, int out_size)
{
    const float* x  = (const float*)d_in[0];
    const float* Wq = (const float*)d_in[1];
    const float* Wk = (const float*)d_in[2];
    const float* Wv = (const float*)d_in[3];
    const float* Wo = (const float*)d_in[4];

    __half *x1, *x2, *c1, *c2, *qh, *ql, *kh, *vh;
    cudaGetSymbolAddress((void**)&x1, g_x1); cudaGetSymbolAddress((void**)&x2, g_x2);
    cudaGetSymbolAddress((void**)&c1, g_c1); cudaGetSymbolAddress((void**)&c2, g_c2);
    cudaGetSymbolAddress((void**)&qh, g_qh); cudaGetSymbolAddress((void**)&ql, g_ql);
    cudaGetSymbolAddress((void**)&kh, g_kh); cudaGetSymbolAddress((void**)&vh, g_vh);

    __half *wq, *wk, *wv, *wo;
    cudaGetSymbolAddress((void**)&wq, g_wq); cudaGetSymbolAddress((void**)&wk, g_wk);
    cudaGetSymbolAddress((void**)&wv, g_wv); cudaGetSymbolAddress((void**)&wo, g_wo);

    cudaFuncSetAttribute(hgemm_qkv, cudaFuncAttributeMaxDynamicSharedMemorySize, GEMM_SMEM);
    cudaFuncSetAttribute(hgemm_out, cudaFuncAttributeMaxDynamicSharedMemorySize, GEMM_SMEM);
    cudaFuncSetAttribute(flash_tc, cudaFuncAttributeMaxDynamicSharedMemorySize, FT_SMEM);

    split2<<<GM * GD / 1024, 256>>>(x, x1, x2);
    dim3 tgrid(GD / 32, GD / 32, 4), tblk(32, 8);
    tconv4<<<tgrid, tblk>>>(Wq, Wk, Wv, Wo, wq, wk, wv, wo);

    dim3 qkv_grid(GD / 128, GM / 128, 3);
    hgemm_qkv<<<qkv_grid, 256, GEMM_SMEM>>>(x1, x2, wq, wk, wv, qh, ql, kh, vh);

    flash_tc<<<dim3(SEQ / 128, NH, 2), 256, FT_SMEM>>>(qh, ql, kh, vh, c1, c2);

    dim3 ggrid(GD / 128, GM / 128);
    hgemm_out<<<ggrid, 256, GEMM_SMEM>>>(c1, c2, wo, (float*)d_out);
}

// round 10
// speedup vs baseline: 8.1559x; 1.3440x over previous
#include <cuda_runtime.h>
#include <cuda_fp16.h>
#include <math.h>
#include <stdint.h>

// Problem: b=2, s=2048, d=2048, H=16, Dh=128, window=2048 (never binds -> causal)
#define GM 4096
#define GD 2048
#define SEQ 2048
#define NH 16
#define DH 128

// Q is pre-scaled by SM_SCALE*log2(e); softmax runs in exp2 domain.
#define QSCALE (0.08838834764831845f * 1.4426950408889634f)

// ---------------- scratch (device globals; allocation forbidden) ----------------
__device__ __half g_xh[GM * GD];
__device__ __half g_c1[GM * GD], g_c2[GM * GD];
__device__ __half g_qh[GM * GD], g_ql[GM * GD];
__device__ __half g_kh[GM * GD];
__device__ __half g_vh[GM * GD];
__device__ __half g_wq[GD * GD], g_wk[GD * GD], g_wv[GD * GD], g_wo[GD * GD];

// ---------------- PTX helpers (compute_103-safe) ----------------
__device__ __forceinline__ uint32_t smem_u32(const void* p) {
    uint32_t a;
    asm("{ .reg .u64 t; cvta.to.shared.u64 t, %1; cvt.u32.u64 %0, t; }" : "=r"(a) : "l"(p));
    return a;
}
#define CP_ASYNC16(dst, src) \
    asm volatile("cp.async.cg.shared.global [%0], [%1], 16;" :: "r"(dst), "l"(src))
#define CP_COMMIT() asm volatile("cp.async.commit_group;" ::: "memory")
#define CP_WAIT(n)  asm volatile("cp.async.wait_group %0;" :: "n"(n) : "memory")

#define LDSM4(r0, r1, r2, r3, addr) \
    asm volatile("ldmatrix.sync.aligned.m8n8.x4.shared.b16 {%0,%1,%2,%3}, [%4];" \
                 : "=r"(r0), "=r"(r1), "=r"(r2), "=r"(r3) : "r"(addr))
#define LDSM4T(r0, r1, r2, r3, addr) \
    asm volatile("ldmatrix.sync.aligned.m8n8.x4.trans.shared.b16 {%0,%1,%2,%3}, [%4];" \
                 : "=r"(r0), "=r"(r1), "=r"(r2), "=r"(r3) : "r"(addr))

#define MMA_F16(d, a, b0, b1)                                               \
    asm volatile(                                                           \
        "mma.sync.aligned.m16n8k16.row.col.f32.f16.f16.f32 "                \
        "{%0,%1,%2,%3}, {%4,%5,%6,%7}, {%8,%9}, {%0,%1,%2,%3};"             \
        : "+f"(d[0]), "+f"(d[1]), "+f"(d[2]), "+f"(d[3])                    \
        : "r"(a[0]), "r"(a[1]), "r"(a[2]), "r"(a[3]), "r"(b0), "r"(b1))

__device__ __forceinline__ uint32_t pack_h2(__half a, __half b) {
    __half2 t = __halves2half2(a, b);
    return *reinterpret_cast<uint32_t*>(&t);
}
__device__ __forceinline__ void split_pack(float a, float b, uint32_t& hi, uint32_t& lo) {
    __half ha = __float2half_rn(a), hb = __float2half_rn(b);
    __half la = __float2half_rn(a - __half2float(ha));
    __half lb = __float2half_rn(b - __half2float(hb));
    hi = pack_h2(ha, hb); lo = pack_h2(la, lb);
}

// ---------------------------------------------------------------------------
// Prep kernels.
// ---------------------------------------------------------------------------
__global__ void xconv(const float* __restrict__ in, __half* __restrict__ o)
{
    int i = blockIdx.x * blockDim.x + threadIdx.x;   // float4 index
    float4 v = reinterpret_cast<const float4*>(in)[i];
    __half2* p = reinterpret_cast<__half2*>(o) + 2 * i;
    p[0] = __halves2half2(__float2half_rn(v.x), __float2half_rn(v.y));
    p[1] = __halves2half2(__float2half_rn(v.z), __float2half_rn(v.w));
}

__global__ void tconv4(const float* __restrict__ W0, const float* __restrict__ W1,
                       const float* __restrict__ W2, const float* __restrict__ W3,
                       __half* __restrict__ a0, __half* __restrict__ a1,
                       __half* __restrict__ a2, __half* __restrict__ a3)
{
    const float* W = (blockIdx.z == 0) ? W0 : (blockIdx.z == 1) ? W1
                   : (blockIdx.z == 2) ? W2 : W3;
    __half* o = (blockIdx.z == 0) ? a0 : (blockIdx.z == 1) ? a1
              : (blockIdx.z == 2) ? a2 : a3;

    __shared__ float t[32][33];
    const int bx = blockIdx.x * 32;
    const int by = blockIdx.y * 32;
    const int tx = threadIdx.x, ty = threadIdx.y;
#pragma unroll
    for (int i = 0; i < 4; i++)
        t[ty + 8 * i][tx] = W[(size_t)(by + ty + 8 * i) * GD + bx + tx];
    __syncthreads();
#pragma unroll
    for (int i = 0; i < 4; i++)
        o[(size_t)(bx + ty + 8 * i) * GD + by + tx] = __float2half_rn(t[tx][ty + 8 * i]);
}

// ---------------------------------------------------------------------------
// GEMM body, templated on A-split.
// SPLIT=true : 2 terms (A1 hi + A2 lo) x B, 2-stage pipeline, 48KB/stage.
// SPLIT=false: 1 term A1 x B, 3-stage pipeline, 32KB/stage.
// Both 96KB total -> 2 CTAs/SM.
// ---------------------------------------------------------------------------
#define KT 64
#define NCH (GD / KT)          // 32
#define TILE_B 16384           // 128 rows * 128 bytes
#define GEMM_SMEM (6 * TILE_B) // 96 KB

template <bool SPLIT>
__device__ __forceinline__ void gemm_body(
    const __half* __restrict__ A1, const __half* __restrict__ A2,
    const __half* __restrict__ B1,
    float* __restrict__ Cf, __half* __restrict__ O1, __half* __restrict__ O2,
    float oscale, uint32_t sbase, int m0, int n0)
{
    constexpr int NTILES = SPLIT ? 3 : 2;
    constexpr int NST    = SPLIT ? 2 : 3;
    constexpr int STAGE  = NTILES * TILE_B;
    constexpr int B_IDX  = NTILES - 1;

    const int tid  = threadIdx.x;
    const int lane = tid & 31;
    const int warp = tid >> 5;
    const int wm = (warp & 3) * 32;
    const int wn = (warp >> 2) * 64;

    auto load_stage = [&](int ch, int s) {
        const int k0 = ch * KT;
        const uint32_t stage = sbase + s * STAGE;
#pragma unroll
        for (int t = 0; t < NTILES; t++) {
            const __half* g = (t == B_IDX) ? B1 : (t == 0 ? A1 : A2);
            const int r0 = (t == B_IDX) ? n0 : m0;
            const __half* gp = g + (size_t)r0 * GD + k0;
#pragma unroll
            for (int i = 0; i < 4; i++) {
                int idx = tid + i * 256;
                int r = idx >> 3, c = idx & 7;
                uint32_t dst = stage + t * TILE_B + r * 128 + ((c ^ (r & 7)) << 4);
                CP_ASYNC16(dst, gp + (size_t)r * GD + c * 8);
            }
        }
        CP_COMMIT();
    };

    float acc[2][8][4];
#pragma unroll
    for (int mt = 0; mt < 2; mt++)
#pragma unroll
        for (int nt = 0; nt < 8; nt++)
#pragma unroll
            for (int r = 0; r < 4; r++) acc[mt][nt][r] = 0.0f;

#pragma unroll
    for (int s = 0; s < NST - 1; s++) load_stage(s, s);

    for (int ch = 0; ch < NCH; ch++) {
        const int s = ch % NST;
        if (ch + NST - 1 < NCH) {
            load_stage(ch + NST - 1, (ch + NST - 1) % NST);
            CP_WAIT(NST - 1);
        } else {
            CP_WAIT(0);
        }
        __syncthreads();

        const uint32_t stage = sbase + s * STAGE;
#pragma unroll
        for (int ks = 0; ks < 4; ks++) {
            const int chunk = 2 * ks + (lane >> 4);
            uint32_t a1[2][4], a2[2][4];
#pragma unroll
            for (int mt = 0; mt < 2; mt++) {
                int row = wm + mt * 16 + (lane & 15);
                uint32_t sw = (chunk ^ (row & 7)) << 4;
                LDSM4(a1[mt][0], a1[mt][1], a1[mt][2], a1[mt][3],
                      stage + row * 128 + sw);
                if (SPLIT)
                    LDSM4(a2[mt][0], a2[mt][1], a2[mt][2], a2[mt][3],
                          stage + TILE_B + row * 128 + sw);
            }
            uint32_t b[8][2];
#pragma unroll
            for (int np = 0; np < 4; np++) {
                int row = wn + np * 16 + (lane & 15);
                uint32_t r0, r1, r2, r3;
                LDSM4(r0, r1, r2, r3,
                      stage + B_IDX * TILE_B + row * 128 + ((chunk ^ (row & 7)) << 4));
                b[2 * np][0] = r0; b[2 * np][1] = r2;
                b[2 * np + 1][0] = r1; b[2 * np + 1][1] = r3;
            }
#pragma unroll
            for (int mt = 0; mt < 2; mt++)
#pragma unroll
                for (int nt = 0; nt < 8; nt++)
                    MMA_F16(acc[mt][nt], a1[mt], b[nt][0], b[nt][1]);
            if (SPLIT) {
#pragma unroll
                for (int mt = 0; mt < 2; mt++)
#pragma unroll
                    for (int nt = 0; nt < 8; nt++)
                        MMA_F16(acc[mt][nt], a2[mt], b[nt][0], b[nt][1]);
            }
        }
        __syncthreads();
    }

    const int gid = lane >> 2, tig = lane & 3;
#pragma unroll
    for (int mt = 0; mt < 2; mt++)
#pragma unroll
        for (int nt = 0; nt < 8; nt++) {
            int row = m0 + wm + mt * 16 + gid;
            int col = n0 + wn + nt * 8 + tig * 2;
            if (O1) {
                uint32_t h0, l0, h1, l1;
                split_pack(acc[mt][nt][0] * oscale, acc[mt][nt][1] * oscale, h0, l0);
                split_pack(acc[mt][nt][2] * oscale, acc[mt][nt][3] * oscale, h1, l1);
                *reinterpret_cast<uint32_t*>(&O1[(size_t)row * GD + col]) = h0;
                if (O2) *reinterpret_cast<uint32_t*>(&O2[(size_t)row * GD + col]) = l0;
                *reinterpret_cast<uint32_t*>(&O1[(size_t)(row + 8) * GD + col]) = h1;
                if (O2) *reinterpret_cast<uint32_t*>(&O2[(size_t)(row + 8) * GD + col]) = l1;
            } else {
                *reinterpret_cast<float2*>(&Cf[(size_t)row * GD + col]) =
                    make_float2(acc[mt][nt][0], acc[mt][nt][1]);
                *reinterpret_cast<float2*>(&Cf[(size_t)(row + 8) * GD + col]) =
                    make_float2(acc[mt][nt][2], acc[mt][nt][3]);
            }
        }
}

// Fused Q/K/V projection: single-term (x hi only). Q pre-scaled + split out.
__global__ __launch_bounds__(256, 2) void hgemm_qkv(
    const __half* __restrict__ xh,
    const __half* __restrict__ wq, const __half* __restrict__ wk,
    const __half* __restrict__ wv,
    __half* __restrict__ qh, __half* __restrict__ ql,
    __half* __restrict__ kh, __half* __restrict__ vh)
{
    extern __shared__ char smem[];
    const int z = blockIdx.z;
    const __half* B1 = (z == 0) ? wq : (z == 1) ? wk : wv;
    __half* O1 = (z == 0) ? qh : (z == 1) ? kh : vh;
    __half* O2 = (z == 0) ? ql : nullptr;
    float oscale = (z == 0) ? QSCALE : 1.0f;
    gemm_body<false>(xh, nullptr, B1, nullptr, O1, O2, oscale,
                     smem_u32(smem), blockIdx.y * 128, blockIdx.x * 128);
}

// Output projection: 2-term (c hi+lo), fp32 result.
__global__ __launch_bounds__(256, 2) void hgemm_out(
    const __half* __restrict__ c1, const __half* __restrict__ c2,
    const __half* __restrict__ wo, float* __restrict__ Cf)
{
    extern __shared__ char smem[];
    gemm_body<true>(c1, c2, wo, Cf, nullptr, nullptr, 1.0f,
                    smem_u32(smem), blockIdx.y * 128, blockIdx.x * 128);
}

// ---------------------------------------------------------------------------
// Flash attention (round-9 proven, unchanged): exp2 softmax, K/V/P hi-only,
// Q hi+lo, double-buffered K/V, heavy q-tiles first.
// ---------------------------------------------------------------------------
#define FT_TILE 32768
#define FT_SMEM (6 * FT_TILE)

__device__ __forceinline__ uint32_t ft_addr(uint32_t sb, int tile, int r, int c) {
    return sb + tile * FT_TILE + r * 256 + (((c & 8) | ((c ^ (r & 7)) & 7)) << 4);
}

__global__ __launch_bounds__(256, 1) void flash_tc(
    const __half* __restrict__ Qh, const __half* __restrict__ Ql,
    const __half* __restrict__ Kh, const __half* __restrict__ Vh,
    __half* __restrict__ C1, __half* __restrict__ C2)
{
    extern __shared__ char smem[];
    const uint32_t sb = smem_u32(smem);

    const int tid = threadIdx.x, lane = tid & 31, warp = tid >> 5;
    const int qt = gridDim.x - 1 - blockIdx.x;
    const int h = blockIdx.y, b = blockIdx.z;
    const int q0 = qt * 128;
    const size_t base = ((size_t)b * SEQ) * GD + (size_t)h * DH;

    auto load_tile = [&](int t, const __half* src, int r0) {
        const __half* g = src + base + (size_t)r0 * GD;
#pragma unroll
        for (int i = 0; i < 8; i++) {
            int idx = tid + i * 256;
            int r = idx >> 4, c = idx & 15;
            CP_ASYNC16(ft_addr(sb, t, r, c), g + (size_t)r * GD + c * 8);
        }
    };

    load_tile(0, Qh, q0); load_tile(1, Ql, q0);
    load_tile(2, Kh, 0);  load_tile(4, Vh, 0);
    CP_COMMIT(); CP_WAIT(0); __syncthreads();

    const int gid = lane >> 2, tig = lane & 3;
    const int qw = warp * 16;

    float o[16][4];
#pragma unroll
    for (int nt = 0; nt < 16; nt++)
#pragma unroll
        for (int c = 0; c < 4; c++) o[nt][c] = 0.0f;
    float m[2] = {-1e30f, -1e30f}, l[2] = {0.0f, 0.0f};

    for (int jt = 0; jt <= qt; jt++) {
        const int cur = jt & 1, nxt = cur ^ 1;

        float s[16][4];
#pragma unroll
        for (int nt = 0; nt < 16; nt++)
#pragma unroll
            for (int c = 0; c < 4; c++) s[nt][c] = 0.0f;

#pragma unroll
        for (int kf = 0; kf < 8; kf++) {
            const int ac = 2 * kf + (lane >> 4);
            uint32_t ah[4], al[4];
            {
                int r = qw + (lane & 15);
                LDSM4(ah[0], ah[1], ah[2], ah[3], ft_addr(sb, 0, r, ac));
                LDSM4(al[0], al[1], al[2], al[3], ft_addr(sb, 1, r, ac));
            }
#pragma unroll
            for (int p = 0; p < 4; p++) {
                int r0 = (2 * p) * 16 + (lane & 15);
                int r1 = (2 * p + 1) * 16 + (lane & 15);
                uint32_t h0, h1, h2, h3, i0, i1, i2, i3;
                LDSM4(h0, h1, h2, h3, ft_addr(sb, 2 + cur, r0, ac));
                LDSM4(i0, i1, i2, i3, ft_addr(sb, 2 + cur, r1, ac));
                float* s0 = s[4 * p];     float* s1 = s[4 * p + 1];
                float* s2 = s[4 * p + 2]; float* s3 = s[4 * p + 3];
                MMA_F16(s0, ah, h0, h2);  MMA_F16(s1, ah, h1, h3);
                MMA_F16(s2, ah, i0, i2);  MMA_F16(s3, ah, i1, i3);
                MMA_F16(s0, al, h0, h2);  MMA_F16(s1, al, h1, h3);
                MMA_F16(s2, al, i0, i2);  MMA_F16(s3, al, i1, i3);
            }
        }

        if (jt == qt) {
#pragma unroll
            for (int nt = 0; nt < 16; nt++) {
                int colb = jt * 128 + nt * 8 + 2 * tig;
#pragma unroll
                for (int c = 0; c < 4; c++) {
                    int row = q0 + qw + gid + ((c >= 2) ? 8 : 0);
                    int col = colb + (c & 1);
                    if (col > row) s[nt][c] = -1e30f;
                }
            }
        }

        float mx0 = -1e30f, mx1 = -1e30f;
#pragma unroll
        for (int nt = 0; nt < 16; nt++) {
            mx0 = fmaxf(mx0, fmaxf(s[nt][0], s[nt][1]));
            mx1 = fmaxf(mx1, fmaxf(s[nt][2], s[nt][3]));
        }
#pragma unroll
        for (int off = 1; off <= 2; off <<= 1) {
            mx0 = fmaxf(mx0, __shfl_xor_sync(0xffffffffu, mx0, off, 4));
            mx1 = fmaxf(mx1, __shfl_xor_sync(0xffffffffu, mx1, off, 4));
        }
        float mn0 = fmaxf(m[0], mx0), mn1 = fmaxf(m[1], mx1);
        float cr0 = exp2f(m[0] - mn0), cr1 = exp2f(m[1] - mn1);
        m[0] = mn0; m[1] = mn1;
        float sum0 = 0.0f, sum1 = 0.0f;
#pragma unroll
        for (int nt = 0; nt < 16; nt++) {
            s[nt][0] = exp2f(s[nt][0] - mn0); sum0 += s[nt][0];
            s[nt][1] = exp2f(s[nt][1] - mn0); sum0 += s[nt][1];
            s[nt][2] = exp2f(s[nt][2] - mn1); sum1 += s[nt][2];
            s[nt][3] = exp2f(s[nt][3] - mn1); sum1 += s[nt][3];
        }
#pragma unroll
        for (int off = 1; off <= 2; off <<= 1) {
            sum0 += __shfl_xor_sync(0xffffffffu, sum0, off, 4);
            sum1 += __shfl_xor_sync(0xffffffffu, sum1, off, 4);
        }
        l[0] = l[0] * cr0 + sum0;
        l[1] = l[1] * cr1 + sum1;
#pragma unroll
        for (int nt = 0; nt < 16; nt++) {
            o[nt][0] *= cr0; o[nt][1] *= cr0;
            o[nt][2] *= cr1; o[nt][3] *= cr1;
        }

        if (jt < qt) {
            load_tile(2 + nxt, Kh, (jt + 1) * 128);
            load_tile(4 + nxt, Vh, (jt + 1) * 128);
            CP_COMMIT();
        }

#pragma unroll
        for (int kf = 0; kf < 8; kf++) {
            uint32_t ph[4];
            ph[0] = pack_h2(__float2half_rn(s[2 * kf][0]),     __float2half_rn(s[2 * kf][1]));
            ph[1] = pack_h2(__float2half_rn(s[2 * kf][2]),     __float2half_rn(s[2 * kf][3]));
            ph[2] = pack_h2(__float2half_rn(s[2 * kf + 1][0]), __float2half_rn(s[2 * kf + 1][1]));
            ph[3] = pack_h2(__float2half_rn(s[2 * kf + 1][2]), __float2half_rn(s[2 * kf + 1][3]));
            int r = kf * 16 + (lane & 15);
#pragma unroll
            for (int p = 0; p < 4; p++) {
                int c0 = 4 * p + (lane >> 4);
                int c1 = 4 * p + 2 + (lane >> 4);
                uint32_t v0, v1, v2, v3, u0, u1, u2, u3;
                LDSM4T(v0, v1, v2, v3, ft_addr(sb, 4 + cur, r, c0));
                LDSM4T(u0, u1, u2, u3, ft_addr(sb, 4 + cur, r, c1));
                MMA_F16(o[4 * p],     ph, v0, v1);
                MMA_F16(o[4 * p + 1], ph, v2, v3);
                MMA_F16(o[4 * p + 2], ph, u0, u1);
                MMA_F16(o[4 * p + 3], ph, u2, u3);
            }
        }

        if (jt < qt) { CP_WAIT(0); __syncthreads(); }
    }

    float inv0 = 1.0f / l[0], inv1 = 1.0f / l[1];
    int row0 = q0 + qw + gid, row1 = row0 + 8;
#pragma unroll
    for (int nt = 0; nt < 16; nt++) {
        int col = nt * 8 + 2 * tig;
        uint32_t h0, l0, h1, l1;
        split_pack(o[nt][0] * inv0, o[nt][1] * inv0, h0, l0);
        split_pack(o[nt][2] * inv1, o[nt][3] * inv1, h1, l1);
        *reinterpret_cast<uint32_t*>(&C1[base + (size_t)row0 * GD + col]) = h0;
        *reinterpret_cast<uint32_t*>(&C2[base + (size_t)row0 * GD + col]) = l0;
        *reinterpret_cast<uint32_t*>(&C1[base + (size_t)row1 * GD + col]) = h1;
        *reinterpret_cast<uint32_t*>(&C2[base + (size_t)row1 * GD + col]) = l1;
    }
}

// ---------------------------------------------------------------------------
extern "C" void kernel_launch(void* const* d_in, const int* in_sizes, int n_in,
                              void* d_out, int out_size)
{
    const float* x  = (const float*)d_in[0];
    const float* Wq = (const float*)d_in[1];
    const float* Wk = (const float*)d_in[2];
    const float* Wv = (const float*)d_in[3];
    const float* Wo = (const float*)d_in[4];

    __half *xh, *c1, *c2, *qh, *ql, *kh, *vh;
    cudaGetSymbolAddress((void**)&xh, g_xh);
    cudaGetSymbolAddress((void**)&c1, g_c1); cudaGetSymbolAddress((void**)&c2, g_c2);
    cudaGetSymbolAddress((void**)&qh, g_qh); cudaGetSymbolAddress((void**)&ql, g_ql);
    cudaGetSymbolAddress((void**)&kh, g_kh); cudaGetSymbolAddress((void**)&vh, g_vh);

    __half *wq, *wk, *wv, *wo;
    cudaGetSymbolAddress((void**)&wq, g_wq); cudaGetSymbolAddress((void**)&wk, g_wk);
    cudaGetSymbolAddress((void**)&wv, g_wv); cudaGetSymbolAddress((void**)&wo, g_wo);

    cudaFuncSetAttribute(hgemm_qkv, cudaFuncAttributeMaxDynamicSharedMemorySize, GEMM_SMEM);
    cudaFuncSetAttribute(hgemm_out, cudaFuncAttributeMaxDynamicSharedMemorySize, GEMM_SMEM);
    cudaFuncSetAttribute(flash_tc, cudaFuncAttributeMaxDynamicSharedMemorySize, FT_SMEM);

    xconv<<<GM * GD / 1024, 256>>>(x, xh);
    dim3 tgrid(GD / 32, GD / 32, 4), tblk(32, 8);
    tconv4<<<tgrid, tblk>>>(Wq, Wk, Wv, Wo, wq, wk, wv, wo);

    dim3 qkv_grid(GD / 128, GM / 128, 3);
    hgemm_qkv<<<qkv_grid, 256, GEMM_SMEM>>>(xh, wq, wk, wv, qh, ql, kh, vh);

    flash_tc<<<dim3(SEQ / 128, NH, 2), 256, FT_SMEM>>>(qh, ql, kh, vh, c1, c2);

    dim3 ggrid(GD / 128, GM / 128);
    hgemm_out<<<ggrid, 256, GEMM_SMEM>>>(c1, c2, wo, (float*)d_out);
}

// round 11
// speedup vs baseline: 10.1228x; 1.2412x over previous
#include <cuda_runtime.h>
#include <cuda_fp16.h>
#include <math.h>
#include <stdint.h>

// Problem: b=2, s=2048, d=2048, H=16, Dh=128, window=2048 (never binds -> causal)
#define GM 4096
#define GD 2048
#define SEQ 2048
#define NH 16
#define DH 128

// Q is pre-scaled by SM_SCALE*log2(e); softmax runs in exp2 domain.
#define QSCALE (0.08838834764831845f * 1.4426950408889634f)

// ---------------- scratch (device globals; allocation forbidden) ----------------
__device__ __half g_xh[GM * GD];
__device__ __half g_ch[GM * GD];
__device__ __half g_qh[GM * GD];
__device__ __half g_kh[GM * GD];
__device__ __half g_vh[GM * GD];
__device__ __half g_wq[GD * GD], g_wk[GD * GD], g_wv[GD * GD], g_wo[GD * GD];

// ---------------- PTX helpers (compute_103-safe) ----------------
__device__ __forceinline__ uint32_t smem_u32(const void* p) {
    uint32_t a;
    asm("{ .reg .u64 t; cvta.to.shared.u64 t, %1; cvt.u32.u64 %0, t; }" : "=r"(a) : "l"(p));
    return a;
}
#define CP_ASYNC16(dst, src) \
    asm volatile("cp.async.cg.shared.global [%0], [%1], 16;" :: "r"(dst), "l"(src))
#define CP_COMMIT() asm volatile("cp.async.commit_group;" ::: "memory")
#define CP_WAIT(n)  asm volatile("cp.async.wait_group %0;" :: "n"(n) : "memory")

#define LDSM4(r0, r1, r2, r3, addr) \
    asm volatile("ldmatrix.sync.aligned.m8n8.x4.shared.b16 {%0,%1,%2,%3}, [%4];" \
                 : "=r"(r0), "=r"(r1), "=r"(r2), "=r"(r3) : "r"(addr))
#define LDSM4T(r0, r1, r2, r3, addr) \
    asm volatile("ldmatrix.sync.aligned.m8n8.x4.trans.shared.b16 {%0,%1,%2,%3}, [%4];" \
                 : "=r"(r0), "=r"(r1), "=r"(r2), "=r"(r3) : "r"(addr))

#define MMA_F16(d, a, b0, b1)                                               \
    asm volatile(                                                           \
        "mma.sync.aligned.m16n8k16.row.col.f32.f16.f16.f32 "                \
        "{%0,%1,%2,%3}, {%4,%5,%6,%7}, {%8,%9}, {%0,%1,%2,%3};"             \
        : "+f"(d[0]), "+f"(d[1]), "+f"(d[2]), "+f"(d[3])                    \
        : "r"(a[0]), "r"(a[1]), "r"(a[2]), "r"(a[3]), "r"(b0), "r"(b1))

__device__ __forceinline__ uint32_t pack_h2(__half a, __half b) {
    __half2 t = __halves2half2(a, b);
    return *reinterpret_cast<uint32_t*>(&t);
}

// ---------------------------------------------------------------------------
// Prep kernels.
// ---------------------------------------------------------------------------
__global__ void xconv(const float* __restrict__ in, __half* __restrict__ o)
{
    int i = blockIdx.x * blockDim.x + threadIdx.x;   // float4 index
    float4 v = reinterpret_cast<const float4*>(in)[i];
    __half2* p = reinterpret_cast<__half2*>(o) + 2 * i;
    p[0] = __halves2half2(__float2half_rn(v.x), __float2half_rn(v.y));
    p[1] = __halves2half2(__float2half_rn(v.z), __float2half_rn(v.w));
}

__global__ void tconv4(const float* __restrict__ W0, const float* __restrict__ W1,
                       const float* __restrict__ W2, const float* __restrict__ W3,
                       __half* __restrict__ a0, __half* __restrict__ a1,
                       __half* __restrict__ a2, __half* __restrict__ a3)
{
    const float* W = (blockIdx.z == 0) ? W0 : (blockIdx.z == 1) ? W1
                   : (blockIdx.z == 2) ? W2 : W3;
    __half* o = (blockIdx.z == 0) ? a0 : (blockIdx.z == 1) ? a1
              : (blockIdx.z == 2) ? a2 : a3;

    __shared__ float t[32][33];
    const int bx = blockIdx.x * 32;
    const int by = blockIdx.y * 32;
    const int tx = threadIdx.x, ty = threadIdx.y;
#pragma unroll
    for (int i = 0; i < 4; i++)
        t[ty + 8 * i][tx] = W[(size_t)(by + ty + 8 * i) * GD + bx + tx];
    __syncthreads();
#pragma unroll
    for (int i = 0; i < 4; i++)
        o[(size_t)(bx + ty + 8 * i) * GD + by + tx] = __float2half_rn(t[tx][ty + 8 * i]);
}

// ---------------------------------------------------------------------------
// Single-term fp16 GEMM: C = A @ B^T. KT=64, 3-stage cp.async pipeline,
// 32KB A + 32KB B per stage -> 96KB smem, 2 CTAs/SM.
// Output: fp16 O1 (scaled by oscale) or fp32 Cf.
// ---------------------------------------------------------------------------
#define KT 64
#define NCH (GD / KT)          // 32
#define TILE_B 16384           // 128 rows * 128 bytes
#define STAGE_B (2 * TILE_B)   // A + B = 32 KB
#define GEMM_SMEM (3 * STAGE_B)

__device__ __forceinline__ void gemm_body(
    const __half* __restrict__ A1, const __half* __restrict__ B1,
    float* __restrict__ Cf, __half* __restrict__ O1,
    float oscale, uint32_t sbase, int m0, int n0)
{
    const int tid  = threadIdx.x;
    const int lane = tid & 31;
    const int warp = tid >> 5;
    const int wm = (warp & 3) * 32;
    const int wn = (warp >> 2) * 64;

    auto load_stage = [&](int ch, int s) {
        const int k0 = ch * KT;
        const uint32_t stage = sbase + s * STAGE_B;
#pragma unroll
        for (int t = 0; t < 2; t++) {
            const __half* gp = (t ? B1 : A1) + (size_t)(t ? n0 : m0) * GD + k0;
#pragma unroll
            for (int i = 0; i < 4; i++) {
                int idx = tid + i * 256;
                int r = idx >> 3, c = idx & 7;
                uint32_t dst = stage + t * TILE_B + r * 128 + ((c ^ (r & 7)) << 4);
                CP_ASYNC16(dst, gp + (size_t)r * GD + c * 8);
            }
        }
        CP_COMMIT();
    };

    float acc[2][8][4];
#pragma unroll
    for (int mt = 0; mt < 2; mt++)
#pragma unroll
        for (int nt = 0; nt < 8; nt++)
#pragma unroll
            for (int r = 0; r < 4; r++) acc[mt][nt][r] = 0.0f;

    load_stage(0, 0);
    load_stage(1, 1);

    for (int ch = 0; ch < NCH; ch++) {
        const int s = ch % 3;
        if (ch + 2 < NCH) { load_stage(ch + 2, (ch + 2) % 3); CP_WAIT(2); }
        else if (ch + 1 < NCH) { CP_WAIT(1); }
        else { CP_WAIT(0); }
        __syncthreads();

        const uint32_t stage = sbase + s * STAGE_B;
#pragma unroll
        for (int ks = 0; ks < 4; ks++) {
            const int chunk = 2 * ks + (lane >> 4);
            uint32_t a1[2][4];
#pragma unroll
            for (int mt = 0; mt < 2; mt++) {
                int row = wm + mt * 16 + (lane & 15);
                LDSM4(a1[mt][0], a1[mt][1], a1[mt][2], a1[mt][3],
                      stage + row * 128 + ((chunk ^ (row & 7)) << 4));
            }
            uint32_t b[8][2];
#pragma unroll
            for (int np = 0; np < 4; np++) {
                int row = wn + np * 16 + (lane & 15);
                uint32_t r0, r1, r2, r3;
                LDSM4(r0, r1, r2, r3,
                      stage + TILE_B + row * 128 + ((chunk ^ (row & 7)) << 4));
                b[2 * np][0] = r0; b[2 * np][1] = r2;
                b[2 * np + 1][0] = r1; b[2 * np + 1][1] = r3;
            }
#pragma unroll
            for (int mt = 0; mt < 2; mt++)
#pragma unroll
                for (int nt = 0; nt < 8; nt++)
                    MMA_F16(acc[mt][nt], a1[mt], b[nt][0], b[nt][1]);
        }
        __syncthreads();
    }

    const int gid = lane >> 2, tig = lane & 3;
#pragma unroll
    for (int mt = 0; mt < 2; mt++)
#pragma unroll
        for (int nt = 0; nt < 8; nt++) {
            int row = m0 + wm + mt * 16 + gid;
            int col = n0 + wn + nt * 8 + tig * 2;
            if (O1) {
                uint32_t h0 = pack_h2(__float2half_rn(acc[mt][nt][0] * oscale),
                                      __float2half_rn(acc[mt][nt][1] * oscale));
                uint32_t h1 = pack_h2(__float2half_rn(acc[mt][nt][2] * oscale),
                                      __float2half_rn(acc[mt][nt][3] * oscale));
                *reinterpret_cast<uint32_t*>(&O1[(size_t)row * GD + col]) = h0;
                *reinterpret_cast<uint32_t*>(&O1[(size_t)(row + 8) * GD + col]) = h1;
            } else {
                *reinterpret_cast<float2*>(&Cf[(size_t)row * GD + col]) =
                    make_float2(acc[mt][nt][0], acc[mt][nt][1]);
                *reinterpret_cast<float2*>(&Cf[(size_t)(row + 8) * GD + col]) =
                    make_float2(acc[mt][nt][2], acc[mt][nt][3]);
            }
        }
}

// Fused Q/K/V projection: single-term. Q output pre-scaled by QSCALE.
__global__ __launch_bounds__(256, 2) void hgemm_qkv(
    const __half* __restrict__ xh,
    const __half* __restrict__ wq, const __half* __restrict__ wk,
    const __half* __restrict__ wv,
    __half* __restrict__ qh, __half* __restrict__ kh, __half* __restrict__ vh)
{
    extern __shared__ char smem[];
    const int z = blockIdx.z;
    const __half* B1 = (z == 0) ? wq : (z == 1) ? wk : wv;
    __half* O1 = (z == 0) ? qh : (z == 1) ? kh : vh;
    float oscale = (z == 0) ? QSCALE : 1.0f;
    gemm_body(xh, B1, nullptr, O1, oscale,
              smem_u32(smem), blockIdx.y * 128, blockIdx.x * 128);
}

// Output projection: single-term, fp32 result.
__global__ __launch_bounds__(256, 2) void hgemm_out(
    const __half* __restrict__ ch, const __half* __restrict__ wo,
    float* __restrict__ Cf)
{
    extern __shared__ char smem[];
    gemm_body(ch, wo, Cf, nullptr, 1.0f,
              smem_u32(smem), blockIdx.y * 128, blockIdx.x * 128);
}

// ---------------------------------------------------------------------------
// Flash attention v3: all-fp16 operands (Q/K/V/P hi-only), exp2 softmax,
// double-buffered K/V, heavy q-tiles first.
// smem tiles (32KB): 0 Qh, 1/2 Kh[buf], 3/4 Vh[buf] = 160KB.
// ---------------------------------------------------------------------------
#define FT_TILE 32768
#define FT_SMEM (5 * FT_TILE)

__device__ __forceinline__ uint32_t ft_addr(uint32_t sb, int tile, int r, int c) {
    return sb + tile * FT_TILE + r * 256 + (((c & 8) | ((c ^ (r & 7)) & 7)) << 4);
}

__global__ __launch_bounds__(256, 1) void flash_tc(
    const __half* __restrict__ Qh, const __half* __restrict__ Kh,
    const __half* __restrict__ Vh, __half* __restrict__ C1)
{
    extern __shared__ char smem[];
    const uint32_t sb = smem_u32(smem);

    const int tid = threadIdx.x, lane = tid & 31, warp = tid >> 5;
    const int qt = gridDim.x - 1 - blockIdx.x;   // heavy tiles first
    const int h = blockIdx.y, b = blockIdx.z;
    const int q0 = qt * 128;
    const size_t base = ((size_t)b * SEQ) * GD + (size_t)h * DH;

    auto load_tile = [&](int t, const __half* src, int r0) {
        const __half* g = src + base + (size_t)r0 * GD;
#pragma unroll
        for (int i = 0; i < 8; i++) {
            int idx = tid + i * 256;
            int r = idx >> 4, c = idx & 15;
            CP_ASYNC16(ft_addr(sb, t, r, c), g + (size_t)r * GD + c * 8);
        }
    };

    load_tile(0, Qh, q0);
    load_tile(1, Kh, 0);
    load_tile(3, Vh, 0);
    CP_COMMIT(); CP_WAIT(0); __syncthreads();

    const int gid = lane >> 2, tig = lane & 3;
    const int qw = warp * 16;

    float o[16][4];
#pragma unroll
    for (int nt = 0; nt < 16; nt++)
#pragma unroll
        for (int c = 0; c < 4; c++) o[nt][c] = 0.0f;
    float m[2] = {-1e30f, -1e30f}, l[2] = {0.0f, 0.0f};

    for (int jt = 0; jt <= qt; jt++) {
        const int cur = jt & 1, nxt = cur ^ 1;

        // ---- S = Q @ K^T (single term) ----
        float s[16][4];
#pragma unroll
        for (int nt = 0; nt < 16; nt++)
#pragma unroll
            for (int c = 0; c < 4; c++) s[nt][c] = 0.0f;

#pragma unroll
        for (int kf = 0; kf < 8; kf++) {
            const int ac = 2 * kf + (lane >> 4);
            uint32_t ah[4];
            {
                int r = qw + (lane & 15);
                LDSM4(ah[0], ah[1], ah[2], ah[3], ft_addr(sb, 0, r, ac));
            }
#pragma unroll
            for (int p = 0; p < 4; p++) {
                int r0 = (2 * p) * 16 + (lane & 15);
                int r1 = (2 * p + 1) * 16 + (lane & 15);
                uint32_t h0, h1, h2, h3, i0, i1, i2, i3;
                LDSM4(h0, h1, h2, h3, ft_addr(sb, 1 + cur, r0, ac));
                LDSM4(i0, i1, i2, i3, ft_addr(sb, 1 + cur, r1, ac));
                MMA_F16(s[4 * p],     ah, h0, h2);
                MMA_F16(s[4 * p + 1], ah, h1, h3);
                MMA_F16(s[4 * p + 2], ah, i0, i2);
                MMA_F16(s[4 * p + 3], ah, i1, i3);
            }
        }

        // ---- causal mask (diag tile only) ----
        if (jt == qt) {
#pragma unroll
            for (int nt = 0; nt < 16; nt++) {
                int colb = jt * 128 + nt * 8 + 2 * tig;
#pragma unroll
                for (int c = 0; c < 4; c++) {
                    int row = q0 + qw + gid + ((c >= 2) ? 8 : 0);
                    int col = colb + (c & 1);
                    if (col > row) s[nt][c] = -1e30f;
                }
            }
        }

        // ---- online softmax in exp2 domain ----
        float mx0 = -1e30f, mx1 = -1e30f;
#pragma unroll
        for (int nt = 0; nt < 16; nt++) {
            mx0 = fmaxf(mx0, fmaxf(s[nt][0], s[nt][1]));
            mx1 = fmaxf(mx1, fmaxf(s[nt][2], s[nt][3]));
        }
#pragma unroll
        for (int off = 1; off <= 2; off <<= 1) {
            mx0 = fmaxf(mx0, __shfl_xor_sync(0xffffffffu, mx0, off, 4));
            mx1 = fmaxf(mx1, __shfl_xor_sync(0xffffffffu, mx1, off, 4));
        }
        float mn0 = fmaxf(m[0], mx0), mn1 = fmaxf(m[1], mx1);
        float cr0 = exp2f(m[0] - mn0), cr1 = exp2f(m[1] - mn1);
        m[0] = mn0; m[1] = mn1;
        float sum0 = 0.0f, sum1 = 0.0f;
#pragma unroll
        for (int nt = 0; nt < 16; nt++) {
            s[nt][0] = exp2f(s[nt][0] - mn0); sum0 += s[nt][0];
            s[nt][1] = exp2f(s[nt][1] - mn0); sum0 += s[nt][1];
            s[nt][2] = exp2f(s[nt][2] - mn1); sum1 += s[nt][2];
            s[nt][3] = exp2f(s[nt][3] - mn1); sum1 += s[nt][3];
        }
#pragma unroll
        for (int off = 1; off <= 2; off <<= 1) {
            sum0 += __shfl_xor_sync(0xffffffffu, sum0, off, 4);
            sum1 += __shfl_xor_sync(0xffffffffu, sum1, off, 4);
        }
        l[0] = l[0] * cr0 + sum0;
        l[1] = l[1] * cr1 + sum1;
#pragma unroll
        for (int nt = 0; nt < 16; nt++) {
            o[nt][0] *= cr0; o[nt][1] *= cr0;
            o[nt][2] *= cr1; o[nt][3] *= cr1;
        }

        // prefetch next K/V into the other buffer
        if (jt < qt) {
            load_tile(1 + nxt, Kh, (jt + 1) * 128);
            load_tile(3 + nxt, Vh, (jt + 1) * 128);
            CP_COMMIT();
        }

        // ---- O += P @ V ----
#pragma unroll
        for (int kf = 0; kf < 8; kf++) {
            uint32_t ph[4];
            ph[0] = pack_h2(__float2half_rn(s[2 * kf][0]),     __float2half_rn(s[2 * kf][1]));
            ph[1] = pack_h2(__float2half_rn(s[2 * kf][2]),     __float2half_rn(s[2 * kf][3]));
            ph[2] = pack_h2(__float2half_rn(s[2 * kf + 1][0]), __float2half_rn(s[2 * kf + 1][1]));
            ph[3] = pack_h2(__float2half_rn(s[2 * kf + 1][2]), __float2half_rn(s[2 * kf + 1][3]));
            int r = kf * 16 + (lane & 15);
#pragma unroll
            for (int p = 0; p < 4; p++) {
                int c0 = 4 * p + (lane >> 4);
                int c1 = 4 * p + 2 + (lane >> 4);
                uint32_t v0, v1, v2, v3, u0, u1, u2, u3;
                LDSM4T(v0, v1, v2, v3, ft_addr(sb, 3 + cur, r, c0));
                LDSM4T(u0, u1, u2, u3, ft_addr(sb, 3 + cur, r, c1));
                MMA_F16(o[4 * p],     ph, v0, v1);
                MMA_F16(o[4 * p + 1], ph, v2, v3);
                MMA_F16(o[4 * p + 2], ph, u0, u1);
                MMA_F16(o[4 * p + 3], ph, u2, u3);
            }
        }

        if (jt < qt) { CP_WAIT(0); __syncthreads(); }   // one sync per k-tile
    }

    // ---- epilogue: normalize + fp16 store ----
    float inv0 = 1.0f / l[0], inv1 = 1.0f / l[1];
    int row0 = q0 + qw + gid, row1 = row0 + 8;
#pragma unroll
    for (int nt = 0; nt < 16; nt++) {
        int col = nt * 8 + 2 * tig;
        uint32_t h0 = pack_h2(__float2half_rn(o[nt][0] * inv0),
                              __float2half_rn(o[nt][1] * inv0));
        uint32_t h1 = pack_h2(__float2half_rn(o[nt][2] * inv1),
                              __float2half_rn(o[nt][3] * inv1));
        *reinterpret_cast<uint32_t*>(&C1[base + (size_t)row0 * GD + col]) = h0;
        *reinterpret_cast<uint32_t*>(&C1[base + (size_t)row1 * GD + col]) = h1;
    }
}

// ---------------------------------------------------------------------------
extern "C" void kernel_launch(void* const* d_in, const int* in_sizes, int n_in,
                              void* d_out, int out_size)
{
    const float* x  = (const float*)d_in[0];
    const float* Wq = (const float*)d_in[1];
    const float* Wk = (const float*)d_in[2];
    const float* Wv = (const float*)d_in[3];
    const float* Wo = (const float*)d_in[4];

    __half *xh, *ch, *qh, *kh, *vh;
    cudaGetSymbolAddress((void**)&xh, g_xh);
    cudaGetSymbolAddress((void**)&ch, g_ch);
    cudaGetSymbolAddress((void**)&qh, g_qh);
    cudaGetSymbolAddress((void**)&kh, g_kh);
    cudaGetSymbolAddress((void**)&vh, g_vh);

    __half *wq, *wk, *wv, *wo;
    cudaGetSymbolAddress((void**)&wq, g_wq); cudaGetSymbolAddress((void**)&wk, g_wk);
    cudaGetSymbolAddress((void**)&wv, g_wv); cudaGetSymbolAddress((void**)&wo, g_wo);

    cudaFuncSetAttribute(hgemm_qkv, cudaFuncAttributeMaxDynamicSharedMemorySize, GEMM_SMEM);
    cudaFuncSetAttribute(hgemm_out, cudaFuncAttributeMaxDynamicSharedMemorySize, GEMM_SMEM);
    cudaFuncSetAttribute(flash_tc, cudaFuncAttributeMaxDynamicSharedMemorySize, FT_SMEM);

    xconv<<<GM * GD / 1024, 256>>>(x, xh);
    dim3 tgrid(GD / 32, GD / 32, 4), tblk(32, 8);
    tconv4<<<tgrid, tblk>>>(Wq, Wk, Wv, Wo, wq, wk, wv, wo);

    dim3 qkv_grid(GD / 128, GM / 128, 3);
    hgemm_qkv<<<qkv_grid, 256, GEMM_SMEM>>>(xh, wq, wk, wv, qh, kh, vh);

    flash_tc<<<dim3(SEQ / 128, NH, 2), 256, FT_SMEM>>>(qh, kh, vh, ch);

    dim3 ggrid(GD / 128, GM / 128);
    hgemm_out<<<ggrid, 256, GEMM_SMEM>>>(ch, wo, (float*)d_out);
}